// round 2
// baseline (speedup 1.0000x reference)
#include <cuda_runtime.h>
#include <cuda_bf16.h>
#include <math.h>

// ---------------- problem constants ----------------
#define NN     40000      // nodes
#define EE     640000     // edges (before self loops)
#define ET     (EE + NN)  // edges incl self loops
#define GG     64         // graphs
#define HH     4          // heads
#define CC     64         // channels/head
#define HC     256        // H*C
#define NHID   1024
#define NOUT   768
#define NEG    0.2f

// ---------------- device scratch ----------------
__device__ __align__(16) float g_hw  [NN * HC];   // post-GEMM features (message source)
__device__ __align__(16) float g_hout[NN * HC];   // scatter accumulator
__device__ __align__(16) float g_hin [NN * HC];   // activated layer output / next input
__device__ __align__(16) float g_asrc[NN * HH];
__device__ __align__(16) float g_adst[NN * HH];
__device__ __align__(16) float g_denom[NN * HH];
__device__ __align__(16) float g_p   [(size_t)ET * HH];
__device__ __align__(16) float g_pool[GG * HC];
__device__ __align__(16) float g_hid [GG * NHID];
__device__ int g_gstart[GG + 1];
__device__ int g_str;      // 1 if indices are int32, 2 if int64 (low-word stride)

// ---------------- dtype detection ----------------
// int64 little-endian arrays of small non-negative ints have zero high words.
__global__ void detect_kernel(const int* __restrict__ ei) {
    if (threadIdx.x == 0 && blockIdx.x == 0) {
        int o = 0;
        #pragma unroll
        for (int k = 0; k < 16; k++) o |= ei[2 * k + 1];
        g_str = o ? 1 : 2;
    }
}

// ---------------- GEMM: C[M,256] = A[M,256] @ B[256,256] ----------------
__global__ void gemm_nn(const float* __restrict__ A, const float* __restrict__ B,
                        float* __restrict__ C, int M) {
    __shared__ float As[16][64];
    __shared__ float Bs[16][64];
    const int tid = threadIdx.x;          // 256 threads
    const int tx = tid & 15, ty = tid >> 4;
    const int row0 = blockIdx.x * 64;
    const int col0 = blockIdx.y * 64;

    const int lr = tid >> 2;              // A tile row 0..63
    const int lc = (tid & 3) * 4;         // A tile col 0,4,8,12
    const int br = tid >> 4;              // B tile row 0..15
    const int bc = (tid & 15) * 4;        // B tile col 0..60

    float acc[4][4];
    #pragma unroll
    for (int i = 0; i < 4; i++)
        #pragma unroll
        for (int j = 0; j < 4; j++) acc[i][j] = 0.f;

    for (int k0 = 0; k0 < HC; k0 += 16) {
        float4 av = make_float4(0.f, 0.f, 0.f, 0.f);
        if (row0 + lr < M)
            av = *(const float4*)(A + (size_t)(row0 + lr) * HC + k0 + lc);
        float4 bv = *(const float4*)(B + (size_t)(k0 + br) * HC + col0 + bc);
        As[lc + 0][lr] = av.x; As[lc + 1][lr] = av.y;
        As[lc + 2][lr] = av.z; As[lc + 3][lr] = av.w;
        *(float4*)&Bs[br][bc] = bv;
        __syncthreads();
        #pragma unroll
        for (int kk = 0; kk < 16; kk++) {
            float a[4], b[4];
            #pragma unroll
            for (int j = 0; j < 4; j++) { a[j] = As[kk][(ty << 2) + j]; b[j] = Bs[kk][(tx << 2) + j]; }
            #pragma unroll
            for (int i = 0; i < 4; i++)
                #pragma unroll
                for (int j = 0; j < 4; j++) acc[i][j] = fmaf(a[i], b[j], acc[i][j]);
        }
        __syncthreads();
    }
    #pragma unroll
    for (int i = 0; i < 4; i++) {
        int r = row0 + (ty << 2) + i;
        if (r < M) {
            float4 v = make_float4(acc[i][0], acc[i][1], acc[i][2], acc[i][3]);
            *(float4*)(C + (size_t)r * HC + col0 + (tx << 2)) = v;
        }
    }
}

// ---------------- per-node attention scalars ----------------
__global__ void node_prep(const float* __restrict__ hw,
                          const float* __restrict__ a_s, const float* __restrict__ a_d,
                          float* __restrict__ asrc, float* __restrict__ adst) {
    __shared__ float ss[HC], sd[HC];
    for (int i = threadIdx.x; i < HC; i += blockDim.x) { ss[i] = a_s[i]; sd[i] = a_d[i]; }
    __syncthreads();
    int t = blockIdx.x * blockDim.x + threadIdx.x;
    if (t >= NN * HH) return;
    int n = t >> 2, h = t & 3;
    const float4* hp = (const float4*)(hw + (size_t)n * HC + h * CC);
    const float4* sp = (const float4*)(ss + h * CC);
    const float4* dp = (const float4*)(sd + h * CC);
    float sa = 0.f, da = 0.f;
    #pragma unroll
    for (int i = 0; i < 16; i++) {
        float4 v = hp[i], w1 = sp[i], w2 = dp[i];
        sa += v.x * w1.x + v.y * w1.y + v.z * w1.z + v.w * w1.w;
        da += v.x * w2.x + v.y * w2.y + v.z * w2.z + v.w * w2.w;
    }
    asrc[t] = sa; adst[t] = da;
}

// ---------------- edge pass 1: p = exp(leakyrelu(es+ed)), denom += p --------
__global__ void edge_scalar(const int* __restrict__ ei,
                            const float* __restrict__ asrc, const float* __restrict__ adst,
                            float* __restrict__ p, float* __restrict__ denom) {
    int t = blockIdx.x * blockDim.x + threadIdx.x;
    if (t >= ET * HH) return;
    int e = t >> 2, h = t & 3;
    const int str = g_str;
    int s, d;
    if (e < EE) { s = ei[(size_t)e * str]; d = ei[((size_t)EE + e) * str]; }
    else        { s = d = e - EE; }
    float v = asrc[s * HH + h] + adst[d * HH + h];
    v = (v > 0.f) ? v : v * NEG;
    float pv = __expf(v);
    p[t] = pv;
    atomicAdd(&denom[d * HH + h], pv);
}

// ---------------- edge pass 2: out[dst] += alpha * h[src] -------------------
__global__ void edge_msg(const int* __restrict__ ei,
                         const float* __restrict__ p, const float* __restrict__ denom,
                         const float* __restrict__ hw, float* __restrict__ out) {
    int w = (blockIdx.x * blockDim.x + threadIdx.x) >> 5;
    int lane = threadIdx.x & 31;
    if (w >= ET) return;
    const int str = g_str;
    int s, d;
    if (w < EE) { s = ei[(size_t)w * str]; d = ei[((size_t)EE + w) * str]; }
    else        { s = d = w - EE; }
    float pv = 0.f;
    if (lane < 4) pv = p[(size_t)w * HH + lane] / denom[d * HH + lane];
    float a0 = __shfl_sync(0xffffffffu, pv, lane >> 4);          // head for chans lane*4
    float a1 = __shfl_sync(0xffffffffu, pv, 2 + (lane >> 4));    // head for chans 128+lane*4
    const float4* hs = (const float4*)(hw + (size_t)s * HC);
    float4 v0 = hs[lane];
    float4 v1 = hs[lane + 32];
    v0.x *= a0; v0.y *= a0; v0.z *= a0; v0.w *= a0;
    v1.x *= a1; v1.y *= a1; v1.z *= a1; v1.w *= a1;
    float* ob = out + (size_t)d * HC;
    asm volatile("red.global.add.v4.f32 [%0], {%1,%2,%3,%4};"
                 :: "l"(ob + lane * 4), "f"(v0.x), "f"(v0.y), "f"(v0.z), "f"(v0.w) : "memory");
    asm volatile("red.global.add.v4.f32 [%0], {%1,%2,%3,%4};"
                 :: "l"(ob + 128 + lane * 4), "f"(v1.x), "f"(v1.y), "f"(v1.z), "f"(v1.w) : "memory");
}

// ---------------- bias + optional relu ----------------
__global__ void bias_act(const float* __restrict__ acc, const float* __restrict__ b,
                         float* __restrict__ out, int relu) {
    size_t t = (size_t)blockIdx.x * blockDim.x + threadIdx.x;
    if (t >= (size_t)NN * HC) return;
    int c = (int)(t & (HC - 1));
    float v = acc[t] + b[c];
    if (relu) v = fmaxf(v, 0.f);
    out[t] = v;
}

// ---------------- graph boundaries via binary search (batch is sorted) ------
__global__ void bounds_kernel(const int* __restrict__ batch) {
    int g = blockIdx.x * blockDim.x + threadIdx.x;
    if (g > GG) return;
    const int str = g_str;
    int lo = 0, hi = NN;
    while (lo < hi) {
        int mid = (lo + hi) >> 1;
        if (batch[(size_t)mid * str] < g) lo = mid + 1; else hi = mid;
    }
    g_gstart[g] = lo;
}

// ---------------- mean pool ----------------
__global__ void pool_kernel(const float* __restrict__ h) {
    int g = blockIdx.x, c = threadIdx.x;
    int s = g_gstart[g], e = g_gstart[g + 1];
    float acc = 0.f;
    for (int n = s; n < e; n++) acc += h[(size_t)n * HC + c];
    float cnt = (float)max(e - s, 1);
    g_pool[g * HC + c] = acc / cnt;
}

// ---------------- MLP ----------------
__global__ void mlp1_kernel(const float* __restrict__ Wm1, const float* __restrict__ bm1) {
    __shared__ float row[HC];
    int g = blockIdx.x, t = threadIdx.x;
    for (int i = t; i < HC; i += blockDim.x) row[i] = g_pool[g * HC + i];
    __syncthreads();
    #pragma unroll
    for (int j = 0; j < NHID / 256; j++) {
        int o = t + j * 256;
        float acc = bm1[o];
        for (int k = 0; k < HC; k++) acc = fmaf(row[k], Wm1[(size_t)k * NHID + o], acc);
        g_hid[g * NHID + o] = fmaxf(acc, 0.f);
    }
}

__global__ void mlp2_kernel(const float* __restrict__ Wm2, const float* __restrict__ bm2,
                            float* __restrict__ out) {
    __shared__ float row[NHID];
    int g = blockIdx.x, t = threadIdx.x;
    for (int i = t; i < NHID; i += blockDim.x) row[i] = g_hid[g * NHID + i];
    __syncthreads();
    #pragma unroll
    for (int j = 0; j < NOUT / 256; j++) {
        int o = t + j * 256;
        float acc = bm2[o];
        for (int k = 0; k < NHID; k++) acc = fmaf(row[k], Wm2[(size_t)k * NOUT + o], acc);
        out[(size_t)g * NOUT + o] = acc;
    }
}

// ---------------- host orchestration ----------------
static void run_layer(const float* in, const float* W, const float* as_, const float* ad_,
                      const float* b, int relu, const int* ei,
                      float* hw, float* hout, float* hin_next,
                      float* asrc, float* adst, float* denom, float* p) {
    dim3 ggrid(NN / 64 + (NN % 64 ? 1 : 0), HC / 64);
    gemm_nn<<<ggrid, 256>>>(in, W, hw, NN);
    cudaMemsetAsync(hout, 0, (size_t)NN * HC * sizeof(float), 0);
    cudaMemsetAsync(denom, 0, (size_t)NN * HH * sizeof(float), 0);
    node_prep<<<(NN * HH + 255) / 256, 256>>>(hw, as_, ad_, asrc, adst);
    edge_scalar<<<((size_t)ET * HH + 255) / 256, 256>>>(ei, asrc, adst, p, denom);
    edge_msg<<<(ET + 7) / 8, 256>>>(ei, p, denom, hw, hout);
    bias_act<<<((size_t)NN * HC + 255) / 256, 256>>>(hout, b, hin_next, relu);
}

extern "C" void kernel_launch(void* const* d_in, const int* in_sizes, int n_in,
                              void* d_out, int out_size) {
    const float* x   = (const float*)d_in[0];
    const int*   ei  = (const int*)d_in[1];
    const int*   bat = (const int*)d_in[2];
    const float* W1  = (const float*)d_in[3];
    const float* as1 = (const float*)d_in[4];
    const float* ad1 = (const float*)d_in[5];
    const float* b1  = (const float*)d_in[6];
    const float* W2  = (const float*)d_in[7];
    const float* as2 = (const float*)d_in[8];
    const float* ad2 = (const float*)d_in[9];
    const float* b2  = (const float*)d_in[10];
    const float* W3  = (const float*)d_in[11];
    const float* as3 = (const float*)d_in[12];
    const float* ad3 = (const float*)d_in[13];
    const float* b3  = (const float*)d_in[14];
    const float* Wm1 = (const float*)d_in[15];
    const float* bm1 = (const float*)d_in[16];
    const float* Wm2 = (const float*)d_in[17];
    const float* bm2 = (const float*)d_in[18];
    float* out = (float*)d_out;

    float *hw, *hout, *hin, *asrc, *adst, *denom, *p;
    cudaGetSymbolAddress((void**)&hw,    g_hw);
    cudaGetSymbolAddress((void**)&hout,  g_hout);
    cudaGetSymbolAddress((void**)&hin,   g_hin);
    cudaGetSymbolAddress((void**)&asrc,  g_asrc);
    cudaGetSymbolAddress((void**)&adst,  g_adst);
    cudaGetSymbolAddress((void**)&denom, g_denom);
    cudaGetSymbolAddress((void**)&p,     g_p);

    detect_kernel<<<1, 32>>>(ei);

    run_layer(x,   W1, as1, ad1, b1, 1, ei, hw, hout, hin, asrc, adst, denom, p);
    run_layer(hin, W2, as2, ad2, b2, 1, ei, hw, hout, hin, asrc, adst, denom, p);
    run_layer(hin, W3, as3, ad3, b3, 0, ei, hw, hout, hin, asrc, adst, denom, p);

    bounds_kernel<<<1, 128>>>(bat);
    pool_kernel<<<GG, HC>>>(hin);
    mlp1_kernel<<<GG, 256>>>(Wm1, bm1);
    mlp2_kernel<<<GG, 256>>>(Wm2, bm2, out);
}

// round 4
// speedup vs baseline: 1.0572x; 1.0572x over previous
#include <cuda_runtime.h>
#include <cuda_bf16.h>
#include <math.h>
#include <stdint.h>

// ---------------- problem constants ----------------
#define NN     40000      // nodes
#define EE     640000     // edges (before self loops)
#define ET     (EE + NN)  // edges incl self loops
#define GG     64         // graphs
#define HH     4          // heads
#define CC     64         // channels/head
#define HC     256        // H*C
#define NHID   1024
#define NOUT   768
#define NEG    0.2f

// ---------------- device scratch ----------------
__device__ __align__(16) float g_hw  [NN * HC];   // post-GEMM features (message source)
__device__ __align__(16) float g_hout[NN * HC];   // scatter accumulator
__device__ __align__(16) float g_hin [NN * HC];   // activated layer output / next input
__device__ __align__(16) float g_asrc[NN * HH];
__device__ __align__(16) float g_adst[NN * HH];
__device__ __align__(16) float g_denom[NN * HH];
__device__ __align__(16) float g_p   [(size_t)ET * HH];
__device__ __align__(16) float g_pool[GG * HC];
__device__ __align__(16) float g_hid [GG * NHID];
__device__ int g_gstart[GG + 1];
__device__ int g_str;      // 1 if indices are int32, 2 if int64 (low-word stride)

// ---------------- dtype detection ----------------
__global__ void detect_kernel(const int* __restrict__ ei) {
    if (threadIdx.x == 0 && blockIdx.x == 0) {
        int o = 0;
        #pragma unroll
        for (int k = 0; k < 16; k++) o |= ei[2 * k + 1];
        g_str = o ? 1 : 2;
    }
}

// ---------------- tf32 helpers ----------------
__device__ __forceinline__ float tf32_rna(float x) {
    uint32_t r; asm("cvt.rna.tf32.f32 %0, %1;" : "=r"(r) : "f"(x));
    return __uint_as_float(r);
}
__device__ __forceinline__ void mma_tf32(float* c, const float* a, const float* b) {
    asm volatile(
        "mma.sync.aligned.m16n8k8.row.col.f32.tf32.tf32.f32 "
        "{%0,%1,%2,%3}, {%4,%5,%6,%7}, {%8,%9}, {%0,%1,%2,%3};"
        : "+f"(c[0]), "+f"(c[1]), "+f"(c[2]), "+f"(c[3])
        : "r"(__float_as_uint(a[0])), "r"(__float_as_uint(a[1])),
          "r"(__float_as_uint(a[2])), "r"(__float_as_uint(a[3])),
          "r"(__float_as_uint(b[0])), "r"(__float_as_uint(b[1])));
}

// ---------------- tensor-core GEMM: C[M,256] = A[M,256] @ B[256,256] --------
// Block tile 128x128, 8 warps (4x2) of 32x64 warp tiles, K-chunk 16.
// Split precision: acc += Ah*Bh + Al*Bh + Ah*Bl  (~fp32 accuracy).
#define AST 20    // As row stride (floats): conflict-free frag loads
#define BST 136   // Bs k-row stride (floats): conflict-free frag loads
__global__ __launch_bounds__(256) void gemm_tc(const float* __restrict__ A,
                                               const float* __restrict__ B,
                                               float* __restrict__ C, int M) {
    __shared__ float As_hi[128][AST], As_lo[128][AST];
    __shared__ float Bs_hi[16][BST],  Bs_lo[16][BST];

    const int tid = threadIdx.x;
    const int wid = tid >> 5, lane = tid & 31;
    const int wm = (wid & 3) * 32;          // warp m origin in tile
    const int wn = (wid >> 2) * 64;         // warp n origin in tile
    const int row0 = blockIdx.x * 128;
    const int col0 = blockIdx.y * 128;
    const int r = lane >> 2;                // groupID
    const int c = lane & 3;                 // threadID_in_group

    const int arow = tid >> 2;              // 0..63 (A load row, +64 second)
    const int acol = (tid & 3) * 4;         // 0,4,8,12
    const int bk   = tid >> 5;              // 0..7 (B load k-row, +8 second)
    const int bn4  = lane * 4;              // 0..124

    float acc[2][8][4];
    #pragma unroll
    for (int mt = 0; mt < 2; mt++)
        #pragma unroll
        for (int nt = 0; nt < 8; nt++)
            #pragma unroll
            for (int i = 0; i < 4; i++) acc[mt][nt][i] = 0.f;

    for (int k0 = 0; k0 < HC; k0 += 16) {
        // stage A chunk (rows of this block, k0..k0+15), split hi/lo
        #pragma unroll
        for (int i = 0; i < 2; i++) {
            int rr = arow + i * 64;
            float4 v = make_float4(0.f, 0.f, 0.f, 0.f);
            if (row0 + rr < M)
                v = *(const float4*)(A + (size_t)(row0 + rr) * HC + k0 + acol);
            float h0 = tf32_rna(v.x), h1 = tf32_rna(v.y);
            float h2 = tf32_rna(v.z), h3 = tf32_rna(v.w);
            As_hi[rr][acol + 0] = h0; As_lo[rr][acol + 0] = v.x - h0;
            As_hi[rr][acol + 1] = h1; As_lo[rr][acol + 1] = v.y - h1;
            As_hi[rr][acol + 2] = h2; As_lo[rr][acol + 2] = v.z - h2;
            As_hi[rr][acol + 3] = h3; As_lo[rr][acol + 3] = v.w - h3;
        }
        // stage B chunk (k0..k0+15, cols of this block), split hi/lo
        #pragma unroll
        for (int i = 0; i < 2; i++) {
            int kk = bk + i * 8;
            float4 v = *(const float4*)(B + (size_t)(k0 + kk) * HC + col0 + bn4);
            float h0 = tf32_rna(v.x), h1 = tf32_rna(v.y);
            float h2 = tf32_rna(v.z), h3 = tf32_rna(v.w);
            Bs_hi[kk][bn4 + 0] = h0; Bs_lo[kk][bn4 + 0] = v.x - h0;
            Bs_hi[kk][bn4 + 1] = h1; Bs_lo[kk][bn4 + 1] = v.y - h1;
            Bs_hi[kk][bn4 + 2] = h2; Bs_lo[kk][bn4 + 2] = v.z - h2;
            Bs_hi[kk][bn4 + 3] = h3; Bs_lo[kk][bn4 + 3] = v.w - h3;
        }
        __syncthreads();

        #pragma unroll
        for (int ks = 0; ks < 16; ks += 8) {
            float ah[2][4], al[2][4];
            #pragma unroll
            for (int mt = 0; mt < 2; mt++) {
                int mb = wm + mt * 16;
                ah[mt][0] = As_hi[mb + r    ][ks + c    ];
                ah[mt][1] = As_hi[mb + r + 8][ks + c    ];
                ah[mt][2] = As_hi[mb + r    ][ks + c + 4];
                ah[mt][3] = As_hi[mb + r + 8][ks + c + 4];
                al[mt][0] = As_lo[mb + r    ][ks + c    ];
                al[mt][1] = As_lo[mb + r + 8][ks + c    ];
                al[mt][2] = As_lo[mb + r    ][ks + c + 4];
                al[mt][3] = As_lo[mb + r + 8][ks + c + 4];
            }
            #pragma unroll
            for (int nt = 0; nt < 8; nt++) {
                int nb = wn + nt * 8 + r;
                float bh[2], bl[2];
                bh[0] = Bs_hi[ks + c    ][nb];
                bh[1] = Bs_hi[ks + c + 4][nb];
                bl[0] = Bs_lo[ks + c    ][nb];
                bl[1] = Bs_lo[ks + c + 4][nb];
                #pragma unroll
                for (int mt = 0; mt < 2; mt++) {
                    mma_tf32(acc[mt][nt], ah[mt], bh);
                    mma_tf32(acc[mt][nt], al[mt], bh);
                    mma_tf32(acc[mt][nt], ah[mt], bl);
                }
            }
        }
        __syncthreads();
    }

    // epilogue: C frag layout c0:(r,2c) c1:(r,2c+1) c2:(r+8,2c) c3:(r+8,2c+1)
    #pragma unroll
    for (int mt = 0; mt < 2; mt++) {
        #pragma unroll
        for (int nt = 0; nt < 8; nt++) {
            int rr = row0 + wm + mt * 16 + r;
            int cc = col0 + wn + nt * 8 + 2 * c;
            if (rr < M) {
                float2 v0 = make_float2(acc[mt][nt][0], acc[mt][nt][1]);
                *(float2*)(C + (size_t)rr * HC + cc) = v0;
            }
            if (rr + 8 < M) {
                float2 v1 = make_float2(acc[mt][nt][2], acc[mt][nt][3]);
                *(float2*)(C + (size_t)(rr + 8) * HC + cc) = v1;
            }
        }
    }
}

// ---------------- per-node attention scalars ----------------
__global__ void node_prep(const float* __restrict__ hw,
                          const float* __restrict__ a_s, const float* __restrict__ a_d,
                          float* __restrict__ asrc, float* __restrict__ adst) {
    __shared__ float ss[HC], sd[HC];
    for (int i = threadIdx.x; i < HC; i += blockDim.x) { ss[i] = a_s[i]; sd[i] = a_d[i]; }
    __syncthreads();
    int t = blockIdx.x * blockDim.x + threadIdx.x;
    if (t >= NN * HH) return;
    int n = t >> 2, h = t & 3;
    const float4* hp = (const float4*)(hw + (size_t)n * HC + h * CC);
    const float4* sp = (const float4*)(ss + h * CC);
    const float4* dp = (const float4*)(sd + h * CC);
    float sa = 0.f, da = 0.f;
    #pragma unroll
    for (int i = 0; i < 16; i++) {
        float4 v = hp[i], w1 = sp[i], w2 = dp[i];
        sa += v.x * w1.x + v.y * w1.y + v.z * w1.z + v.w * w1.w;
        da += v.x * w2.x + v.y * w2.y + v.z * w2.z + v.w * w2.w;
    }
    asrc[t] = sa; adst[t] = da;
}

// ---------------- edge pass 1: p = exp(leakyrelu(es+ed)), denom += p --------
__global__ void edge_scalar(const int* __restrict__ ei,
                            const float* __restrict__ asrc, const float* __restrict__ adst,
                            float* __restrict__ p, float* __restrict__ denom) {
    int t = blockIdx.x * blockDim.x + threadIdx.x;
    if (t >= ET * HH) return;
    int e = t >> 2, h = t & 3;
    const int str = g_str;
    int s, d;
    if (e < EE) { s = ei[(size_t)e * str]; d = ei[((size_t)EE + e) * str]; }
    else        { s = d = e - EE; }
    float v = asrc[s * HH + h] + adst[d * HH + h];
    v = (v > 0.f) ? v : v * NEG;
    float pv = __expf(v);
    p[t] = pv;
    atomicAdd(&denom[d * HH + h], pv);
}

// ---------------- edge pass 2: out[dst] += alpha * h[src] -------------------
__global__ void edge_msg(const int* __restrict__ ei,
                         const float* __restrict__ p, const float* __restrict__ denom,
                         const float* __restrict__ hw, float* __restrict__ out) {
    int w = (blockIdx.x * blockDim.x + threadIdx.x) >> 5;
    int lane = threadIdx.x & 31;
    if (w >= ET) return;
    const int str = g_str;
    int s, d;
    if (w < EE) { s = ei[(size_t)w * str]; d = ei[((size_t)EE + w) * str]; }
    else        { s = d = w - EE; }
    float pv = 0.f;
    if (lane < 4) pv = p[(size_t)w * HH + lane] / denom[d * HH + lane];
    float a0 = __shfl_sync(0xffffffffu, pv, lane >> 4);
    float a1 = __shfl_sync(0xffffffffu, pv, 2 + (lane >> 4));
    const float4* hs = (const float4*)(hw + (size_t)s * HC);
    float4 v0 = hs[lane];
    float4 v1 = hs[lane + 32];
    v0.x *= a0; v0.y *= a0; v0.z *= a0; v0.w *= a0;
    v1.x *= a1; v1.y *= a1; v1.z *= a1; v1.w *= a1;
    float* ob = out + (size_t)d * HC;
    asm volatile("red.global.add.v4.f32 [%0], {%1,%2,%3,%4};"
                 :: "l"(ob + lane * 4), "f"(v0.x), "f"(v0.y), "f"(v0.z), "f"(v0.w) : "memory");
    asm volatile("red.global.add.v4.f32 [%0], {%1,%2,%3,%4};"
                 :: "l"(ob + 128 + lane * 4), "f"(v1.x), "f"(v1.y), "f"(v1.z), "f"(v1.w) : "memory");
}

// ---------------- bias + optional relu ----------------
__global__ void bias_act(const float* __restrict__ acc, const float* __restrict__ b,
                         float* __restrict__ out, int relu) {
    size_t t = (size_t)blockIdx.x * blockDim.x + threadIdx.x;
    if (t >= (size_t)NN * HC) return;
    int c = (int)(t & (HC - 1));
    float v = acc[t] + b[c];
    if (relu) v = fmaxf(v, 0.f);
    out[t] = v;
}

// ---------------- graph boundaries ----------------
__global__ void bounds_kernel(const int* __restrict__ batch) {
    int g = blockIdx.x * blockDim.x + threadIdx.x;
    if (g > GG) return;
    const int str = g_str;
    int lo = 0, hi = NN;
    while (lo < hi) {
        int mid = (lo + hi) >> 1;
        if (batch[(size_t)mid * str] < g) lo = mid + 1; else hi = mid;
    }
    g_gstart[g] = lo;
}

// ---------------- mean pool ----------------
__global__ void pool_kernel(const float* __restrict__ h) {
    int g = blockIdx.x, c = threadIdx.x;
    int s = g_gstart[g], e = g_gstart[g + 1];
    float acc = 0.f;
    for (int n = s; n < e; n++) acc += h[(size_t)n * HC + c];
    float cnt = (float)max(e - s, 1);
    g_pool[g * HC + c] = acc / cnt;
}

// ---------------- MLP ----------------
__global__ void mlp1_kernel(const float* __restrict__ Wm1, const float* __restrict__ bm1) {
    __shared__ float row[HC];
    int g = blockIdx.x, t = threadIdx.x;
    for (int i = t; i < HC; i += blockDim.x) row[i] = g_pool[g * HC + i];
    __syncthreads();
    #pragma unroll
    for (int j = 0; j < NHID / 256; j++) {
        int o = t + j * 256;
        float acc = bm1[o];
        for (int k = 0; k < HC; k++) acc = fmaf(row[k], Wm1[(size_t)k * NHID + o], acc);
        g_hid[g * NHID + o] = fmaxf(acc, 0.f);
    }
}

__global__ void mlp2_kernel(const float* __restrict__ Wm2, const float* __restrict__ bm2,
                            float* __restrict__ out) {
    __shared__ float row[NHID];
    int g = blockIdx.x, t = threadIdx.x;
    for (int i = t; i < NHID; i += blockDim.x) row[i] = g_hid[g * NHID + i];
    __syncthreads();
    #pragma unroll
    for (int j = 0; j < NOUT / 256; j++) {
        int o = t + j * 256;
        float acc = bm2[o];
        for (int k = 0; k < NHID; k++) acc = fmaf(row[k], Wm2[(size_t)k * NOUT + o], acc);
        out[(size_t)g * NOUT + o] = acc;
    }
}

// ---------------- host orchestration ----------------
static void run_layer(const float* in, const float* W, const float* as_, const float* ad_,
                      const float* b, int relu, const int* ei,
                      float* hw, float* hout, float* hin_next,
                      float* asrc, float* adst, float* denom, float* p) {
    dim3 ggrid((NN + 127) / 128, HC / 128);
    gemm_tc<<<ggrid, 256>>>(in, W, hw, NN);
    cudaMemsetAsync(hout, 0, (size_t)NN * HC * sizeof(float), 0);
    cudaMemsetAsync(denom, 0, (size_t)NN * HH * sizeof(float), 0);
    node_prep<<<(NN * HH + 255) / 256, 256>>>(hw, as_, ad_, asrc, adst);
    edge_scalar<<<((size_t)ET * HH + 255) / 256, 256>>>(ei, asrc, adst, p, denom);
    edge_msg<<<(ET + 7) / 8, 256>>>(ei, p, denom, hw, hout);
    bias_act<<<((size_t)NN * HC + 255) / 256, 256>>>(hout, b, hin_next, relu);
}

extern "C" void kernel_launch(void* const* d_in, const int* in_sizes, int n_in,
                              void* d_out, int out_size) {
    const float* x   = (const float*)d_in[0];
    const int*   ei  = (const int*)d_in[1];
    const int*   bat = (const int*)d_in[2];
    const float* W1  = (const float*)d_in[3];
    const float* as1 = (const float*)d_in[4];
    const float* ad1 = (const float*)d_in[5];
    const float* b1  = (const float*)d_in[6];
    const float* W2  = (const float*)d_in[7];
    const float* as2 = (const float*)d_in[8];
    const float* ad2 = (const float*)d_in[9];
    const float* b2  = (const float*)d_in[10];
    const float* W3  = (const float*)d_in[11];
    const float* as3 = (const float*)d_in[12];
    const float* ad3 = (const float*)d_in[13];
    const float* b3  = (const float*)d_in[14];
    const float* Wm1 = (const float*)d_in[15];
    const float* bm1 = (const float*)d_in[16];
    const float* Wm2 = (const float*)d_in[17];
    const float* bm2 = (const float*)d_in[18];
    float* out = (float*)d_out;

    float *hw, *hout, *hin, *asrc, *adst, *denom, *p;
    cudaGetSymbolAddress((void**)&hw,    g_hw);
    cudaGetSymbolAddress((void**)&hout,  g_hout);
    cudaGetSymbolAddress((void**)&hin,   g_hin);
    cudaGetSymbolAddress((void**)&asrc,  g_asrc);
    cudaGetSymbolAddress((void**)&adst,  g_adst);
    cudaGetSymbolAddress((void**)&denom, g_denom);
    cudaGetSymbolAddress((void**)&p,     g_p);

    detect_kernel<<<1, 32>>>(ei);

    run_layer(x,   W1, as1, ad1, b1, 1, ei, hw, hout, hin, asrc, adst, denom, p);
    run_layer(hin, W2, as2, ad2, b2, 1, ei, hw, hout, hin, asrc, adst, denom, p);
    run_layer(hin, W3, as3, ad3, b3, 0, ei, hw, hout, hin, asrc, adst, denom, p);

    bounds_kernel<<<1, 128>>>(bat);
    pool_kernel<<<GG, HC>>>(hin);
    mlp1_kernel<<<GG, 256>>>(Wm1, bm1);
    mlp2_kernel<<<GG, 256>>>(Wm2, bm2, out);
}

// round 6
// speedup vs baseline: 1.3923x; 1.3170x over previous
#include <cuda_runtime.h>
#include <cuda_bf16.h>
#include <math.h>
#include <stdint.h>

// ---------------- problem constants ----------------
#define NN     40000      // nodes
#define EE     640000     // edges (before self loops)
#define ET     (EE + NN)  // edges incl self loops
#define GG     64         // graphs
#define HH     4          // heads
#define CC     64         // channels/head
#define HC     256        // H*C
#define NHID   1024
#define NOUT   768
#define NEG    0.2f

// ---------------- device scratch ----------------
__device__ __align__(16) float g_hw  [NN * HC];   // post-GEMM features
__device__ __align__(16) float g_hin [NN * HC];   // activated layer output / next input
__device__ __align__(16) float g_asrc[NN * HH];
__device__ __align__(16) float g_adst[NN * HH];
__device__ __align__(16) float g_pool[GG * HC];
__device__ __align__(16) float g_hid [GG * NHID];
__device__ int g_deg [NN];
__device__ int g_off [NN + 1];
__device__ int g_cur [NN];
__device__ int g_csrc[ET];       // src id per CSR slot (grouped by dst)
__device__ int g_gstart[GG + 1];
__device__ int g_str;            // 1 = int32 indices, 2 = int64 (low-word stride)

// ---------------- dtype detection ----------------
__global__ void detect_kernel(const int* __restrict__ ei) {
    if (threadIdx.x == 0 && blockIdx.x == 0) {
        int o = 0;
        #pragma unroll
        for (int k = 0; k < 16; k++) o |= ei[2 * k + 1];
        g_str = o ? 1 : 2;
    }
}

// ---------------- CSR build (once per launch; graph shared by all layers) ---
__global__ void hist_kernel(const int* __restrict__ ei) {
    int e = blockIdx.x * blockDim.x + threadIdx.x;
    if (e >= ET) return;
    const int str = g_str;
    int d = (e < EE) ? ei[((size_t)EE + e) * str] : e - EE;
    atomicAdd(&g_deg[d], 1);
}

__global__ void scan_kernel() {
    __shared__ int sums[1024];
    const int T = 1024, PER = (NN + T - 1) / T;   // 40
    int t = threadIdx.x;
    int base = t * PER;
    int s = 0;
    for (int i = 0; i < PER; i++) {
        int idx = base + i;
        if (idx < NN) s += g_deg[idx];
    }
    sums[t] = s;
    __syncthreads();
    for (int ofs = 1; ofs < T; ofs <<= 1) {
        int v = 0;
        if (t >= ofs) v = sums[t - ofs];
        __syncthreads();
        if (t >= ofs) sums[t] += v;
        __syncthreads();
    }
    int run = (t > 0) ? sums[t - 1] : 0;
    for (int i = 0; i < PER; i++) {
        int idx = base + i;
        if (idx < NN) {
            g_off[idx] = run;
            g_cur[idx] = run;
            run += g_deg[idx];
        }
    }
    if (t == T - 1) g_off[NN] = run;
}

__global__ void scatter_kernel(const int* __restrict__ ei) {
    int e = blockIdx.x * blockDim.x + threadIdx.x;
    if (e >= ET) return;
    const int str = g_str;
    int s, d;
    if (e < EE) { s = ei[(size_t)e * str]; d = ei[((size_t)EE + e) * str]; }
    else        { s = d = e - EE; }
    int pos = atomicAdd(&g_cur[d], 1);
    g_csrc[pos] = s;
}

// ---------------- tf32 helpers ----------------
__device__ __forceinline__ float tf32_rna(float x) {
    uint32_t r; asm("cvt.rna.tf32.f32 %0, %1;" : "=r"(r) : "f"(x));
    return __uint_as_float(r);
}
__device__ __forceinline__ void mma_tf32(float* c, const float* a, const float* b) {
    asm volatile(
        "mma.sync.aligned.m16n8k8.row.col.f32.tf32.tf32.f32 "
        "{%0,%1,%2,%3}, {%4,%5,%6,%7}, {%8,%9}, {%0,%1,%2,%3};"
        : "+f"(c[0]), "+f"(c[1]), "+f"(c[2]), "+f"(c[3])
        : "r"(__float_as_uint(a[0])), "r"(__float_as_uint(a[1])),
          "r"(__float_as_uint(a[2])), "r"(__float_as_uint(a[3])),
          "r"(__float_as_uint(b[0])), "r"(__float_as_uint(b[1])));
}

// ---------------- tensor-core GEMM: C[M,256] = A[M,256] @ B[256,256] --------
#define AST 20
#define BST 136
__global__ __launch_bounds__(256) void gemm_tc(const float* __restrict__ A,
                                               const float* __restrict__ B,
                                               float* __restrict__ C, int M) {
    __shared__ float As_hi[128][AST], As_lo[128][AST];
    __shared__ float Bs_hi[16][BST],  Bs_lo[16][BST];

    const int tid = threadIdx.x;
    const int wid = tid >> 5, lane = tid & 31;
    const int wm = (wid & 3) * 32;
    const int wn = (wid >> 2) * 64;
    const int row0 = blockIdx.x * 128;
    const int col0 = blockIdx.y * 128;
    const int r = lane >> 2;
    const int c = lane & 3;

    const int arow = tid >> 2;
    const int acol = (tid & 3) * 4;
    const int bk   = tid >> 5;
    const int bn4  = lane * 4;

    float acc[2][8][4];
    #pragma unroll
    for (int mt = 0; mt < 2; mt++)
        #pragma unroll
        for (int nt = 0; nt < 8; nt++)
            #pragma unroll
            for (int i = 0; i < 4; i++) acc[mt][nt][i] = 0.f;

    for (int k0 = 0; k0 < HC; k0 += 16) {
        #pragma unroll
        for (int i = 0; i < 2; i++) {
            int rr = arow + i * 64;
            float4 v = make_float4(0.f, 0.f, 0.f, 0.f);
            if (row0 + rr < M)
                v = *(const float4*)(A + (size_t)(row0 + rr) * HC + k0 + acol);
            float h0 = tf32_rna(v.x), h1 = tf32_rna(v.y);
            float h2 = tf32_rna(v.z), h3 = tf32_rna(v.w);
            As_hi[rr][acol + 0] = h0; As_lo[rr][acol + 0] = v.x - h0;
            As_hi[rr][acol + 1] = h1; As_lo[rr][acol + 1] = v.y - h1;
            As_hi[rr][acol + 2] = h2; As_lo[rr][acol + 2] = v.z - h2;
            As_hi[rr][acol + 3] = h3; As_lo[rr][acol + 3] = v.w - h3;
        }
        #pragma unroll
        for (int i = 0; i < 2; i++) {
            int kk = bk + i * 8;
            float4 v = *(const float4*)(B + (size_t)(k0 + kk) * HC + col0 + bn4);
            float h0 = tf32_rna(v.x), h1 = tf32_rna(v.y);
            float h2 = tf32_rna(v.z), h3 = tf32_rna(v.w);
            Bs_hi[kk][bn4 + 0] = h0; Bs_lo[kk][bn4 + 0] = v.x - h0;
            Bs_hi[kk][bn4 + 1] = h1; Bs_lo[kk][bn4 + 1] = v.y - h1;
            Bs_hi[kk][bn4 + 2] = h2; Bs_lo[kk][bn4 + 2] = v.z - h2;
            Bs_hi[kk][bn4 + 3] = h3; Bs_lo[kk][bn4 + 3] = v.w - h3;
        }
        __syncthreads();

        #pragma unroll
        for (int ks = 0; ks < 16; ks += 8) {
            float ah[2][4], al[2][4];
            #pragma unroll
            for (int mt = 0; mt < 2; mt++) {
                int mb = wm + mt * 16;
                ah[mt][0] = As_hi[mb + r    ][ks + c    ];
                ah[mt][1] = As_hi[mb + r + 8][ks + c    ];
                ah[mt][2] = As_hi[mb + r    ][ks + c + 4];
                ah[mt][3] = As_hi[mb + r + 8][ks + c + 4];
                al[mt][0] = As_lo[mb + r    ][ks + c    ];
                al[mt][1] = As_lo[mb + r + 8][ks + c    ];
                al[mt][2] = As_lo[mb + r    ][ks + c + 4];
                al[mt][3] = As_lo[mb + r + 8][ks + c + 4];
            }
            #pragma unroll
            for (int nt = 0; nt < 8; nt++) {
                int nb = wn + nt * 8 + r;
                float bh[2], bl[2];
                bh[0] = Bs_hi[ks + c    ][nb];
                bh[1] = Bs_hi[ks + c + 4][nb];
                bl[0] = Bs_lo[ks + c    ][nb];
                bl[1] = Bs_lo[ks + c + 4][nb];
                #pragma unroll
                for (int mt = 0; mt < 2; mt++) {
                    mma_tf32(acc[mt][nt], ah[mt], bh);
                    mma_tf32(acc[mt][nt], al[mt], bh);
                    mma_tf32(acc[mt][nt], ah[mt], bl);
                }
            }
        }
        __syncthreads();
    }

    #pragma unroll
    for (int mt = 0; mt < 2; mt++) {
        #pragma unroll
        for (int nt = 0; nt < 8; nt++) {
            int rr = row0 + wm + mt * 16 + r;
            int cc = col0 + wn + nt * 8 + 2 * c;
            if (rr < M) {
                float2 v0 = make_float2(acc[mt][nt][0], acc[mt][nt][1]);
                *(float2*)(C + (size_t)rr * HC + cc) = v0;
            }
            if (rr + 8 < M) {
                float2 v1 = make_float2(acc[mt][nt][2], acc[mt][nt][3]);
                *(float2*)(C + (size_t)(rr + 8) * HC + cc) = v1;
            }
        }
    }
}

// ---------------- per-node attention scalars ----------------
__global__ void node_prep(const float* __restrict__ hw,
                          const float* __restrict__ a_s, const float* __restrict__ a_d,
                          float* __restrict__ asrc, float* __restrict__ adst) {
    __shared__ float ss[HC], sd[HC];
    for (int i = threadIdx.x; i < HC; i += blockDim.x) { ss[i] = a_s[i]; sd[i] = a_d[i]; }
    __syncthreads();
    int t = blockIdx.x * blockDim.x + threadIdx.x;
    if (t >= NN * HH) return;
    int n = t >> 2, h = t & 3;
    const float4* hp = (const float4*)(hw + (size_t)n * HC + h * CC);
    const float4* sp = (const float4*)(ss + h * CC);
    const float4* dp = (const float4*)(sd + h * CC);
    float sa = 0.f, da = 0.f;
    #pragma unroll
    for (int i = 0; i < 16; i++) {
        float4 v = hp[i], w1 = sp[i], w2 = dp[i];
        sa += v.x * w1.x + v.y * w1.y + v.z * w1.z + v.w * w1.w;
        da += v.x * w2.x + v.y * w2.y + v.z * w2.z + v.w * w2.w;
    }
    asrc[t] = sa; adst[t] = da;
}

// ---------------- fused GAT aggregation: warp per dst node ------------------
// out[d] = (sum_e p_e * hw[src_e]) / (sum_e p_e) + bias  [, relu]
// lane owns channels [8*lane, 8*lane+8); head = lane>>3.
__global__ __launch_bounds__(256) void gat_agg(const float* __restrict__ hw,
                                               const float* __restrict__ asrc,
                                               const float* __restrict__ adst,
                                               const float* __restrict__ bias,
                                               float* __restrict__ outp, int relu) {
    int w = (blockIdx.x * blockDim.x + threadIdx.x) >> 5;
    int lane = threadIdx.x & 31;
    if (w >= NN) return;
    const int h  = lane >> 3;
    const int c0 = lane * 8;
    const int beg = g_off[w], end = g_off[w + 1];
    const float ad = adst[w * HH + h];

    float acc[8];
    #pragma unroll
    for (int i = 0; i < 8; i++) acc[i] = 0.f;
    float den = 0.f;

    int j = beg;
    for (; j + 1 < end; j += 2) {
        int s0 = g_csrc[j], s1 = g_csrc[j + 1];
        float v0 = asrc[s0 * HH + h] + ad;
        float v1 = asrc[s1 * HH + h] + ad;
        v0 = (v0 > 0.f) ? v0 : v0 * NEG;
        v1 = (v1 > 0.f) ? v1 : v1 * NEG;
        float p0 = __expf(v0), p1 = __expf(v1);
        den += p0 + p1;
        const float4* h0 = (const float4*)(hw + (size_t)s0 * HC + c0);
        const float4* h1 = (const float4*)(hw + (size_t)s1 * HC + c0);
        float4 a0 = h0[0], a1 = h0[1];
        float4 b0 = h1[0], b1 = h1[1];
        acc[0] = fmaf(p0, a0.x, acc[0]); acc[1] = fmaf(p0, a0.y, acc[1]);
        acc[2] = fmaf(p0, a0.z, acc[2]); acc[3] = fmaf(p0, a0.w, acc[3]);
        acc[4] = fmaf(p0, a1.x, acc[4]); acc[5] = fmaf(p0, a1.y, acc[5]);
        acc[6] = fmaf(p0, a1.z, acc[6]); acc[7] = fmaf(p0, a1.w, acc[7]);
        acc[0] = fmaf(p1, b0.x, acc[0]); acc[1] = fmaf(p1, b0.y, acc[1]);
        acc[2] = fmaf(p1, b0.z, acc[2]); acc[3] = fmaf(p1, b0.w, acc[3]);
        acc[4] = fmaf(p1, b1.x, acc[4]); acc[5] = fmaf(p1, b1.y, acc[5]);
        acc[6] = fmaf(p1, b1.z, acc[6]); acc[7] = fmaf(p1, b1.w, acc[7]);
    }
    if (j < end) {
        int s0 = g_csrc[j];
        float v0 = asrc[s0 * HH + h] + ad;
        v0 = (v0 > 0.f) ? v0 : v0 * NEG;
        float p0 = __expf(v0);
        den += p0;
        const float4* h0 = (const float4*)(hw + (size_t)s0 * HC + c0);
        float4 a0 = h0[0], a1 = h0[1];
        acc[0] = fmaf(p0, a0.x, acc[0]); acc[1] = fmaf(p0, a0.y, acc[1]);
        acc[2] = fmaf(p0, a0.z, acc[2]); acc[3] = fmaf(p0, a0.w, acc[3]);
        acc[4] = fmaf(p0, a1.x, acc[4]); acc[5] = fmaf(p0, a1.y, acc[5]);
        acc[6] = fmaf(p0, a1.z, acc[6]); acc[7] = fmaf(p0, a1.w, acc[7]);
    }

    float inv = 1.f / den;
    float4 bb0 = *(const float4*)(bias + c0);
    float4 bb1 = *(const float4*)(bias + c0 + 4);
    float4 o0, o1;
    o0.x = acc[0] * inv + bb0.x; o0.y = acc[1] * inv + bb0.y;
    o0.z = acc[2] * inv + bb0.z; o0.w = acc[3] * inv + bb0.w;
    o1.x = acc[4] * inv + bb1.x; o1.y = acc[5] * inv + bb1.y;
    o1.z = acc[6] * inv + bb1.z; o1.w = acc[7] * inv + bb1.w;
    if (relu) {
        o0.x = fmaxf(o0.x, 0.f); o0.y = fmaxf(o0.y, 0.f);
        o0.z = fmaxf(o0.z, 0.f); o0.w = fmaxf(o0.w, 0.f);
        o1.x = fmaxf(o1.x, 0.f); o1.y = fmaxf(o1.y, 0.f);
        o1.z = fmaxf(o1.z, 0.f); o1.w = fmaxf(o1.w, 0.f);
    }
    float* op = outp + (size_t)w * HC + c0;
    *(float4*)op = o0;
    *(float4*)(op + 4) = o1;
}

// ---------------- graph boundaries ----------------
__global__ void bounds_kernel(const int* __restrict__ batch) {
    int g = blockIdx.x * blockDim.x + threadIdx.x;
    if (g > GG) return;
    const int str = g_str;
    int lo = 0, hi = NN;
    while (lo < hi) {
        int mid = (lo + hi) >> 1;
        if (batch[(size_t)mid * str] < g) lo = mid + 1; else hi = mid;
    }
    g_gstart[g] = lo;
}

// ---------------- mean pool ----------------
__global__ void pool_kernel(const float* __restrict__ h) {
    int g = blockIdx.x, c = threadIdx.x;
    int s = g_gstart[g], e = g_gstart[g + 1];
    float acc = 0.f;
    for (int n = s; n < e; n++) acc += h[(size_t)n * HC + c];
    float cnt = (float)max(e - s, 1);
    g_pool[g * HC + c] = acc / cnt;
}

// ---------------- MLP ----------------
__global__ void mlp1_kernel(const float* __restrict__ Wm1, const float* __restrict__ bm1) {
    __shared__ float row[HC];
    int g = blockIdx.x, t = threadIdx.x;
    for (int i = t; i < HC; i += blockDim.x) row[i] = g_pool[g * HC + i];
    __syncthreads();
    #pragma unroll
    for (int j = 0; j < NHID / 256; j++) {
        int o = t + j * 256;
        float acc = bm1[o];
        for (int k = 0; k < HC; k++) acc = fmaf(row[k], Wm1[(size_t)k * NHID + o], acc);
        g_hid[g * NHID + o] = fmaxf(acc, 0.f);
    }
}

__global__ void mlp2_kernel(const float* __restrict__ Wm2, const float* __restrict__ bm2,
                            float* __restrict__ out) {
    __shared__ float row[NHID];
    int g = blockIdx.x, t = threadIdx.x;
    for (int i = t; i < NHID; i += blockDim.x) row[i] = g_hid[g * NHID + i];
    __syncthreads();
    #pragma unroll
    for (int j = 0; j < NOUT / 256; j++) {
        int o = t + j * 256;
        float acc = bm2[o];
        for (int k = 0; k < NHID; k++) acc = fmaf(row[k], Wm2[(size_t)k * NOUT + o], acc);
        out[(size_t)g * NOUT + o] = acc;
    }
}

// ---------------- host orchestration ----------------
static void run_layer(const float* in, const float* W, const float* as_, const float* ad_,
                      const float* b, int relu,
                      float* hw, float* hin_next, float* asrc, float* adst) {
    dim3 ggrid((NN + 127) / 128, HC / 128);
    gemm_tc<<<ggrid, 256>>>(in, W, hw, NN);
    node_prep<<<(NN * HH + 255) / 256, 256>>>(hw, as_, ad_, asrc, adst);
    gat_agg<<<(NN * 32 + 255) / 256, 256>>>(hw, asrc, adst, b, hin_next, relu);
}

extern "C" void kernel_launch(void* const* d_in, const int* in_sizes, int n_in,
                              void* d_out, int out_size) {
    const float* x   = (const float*)d_in[0];
    const int*   ei  = (const int*)d_in[1];
    const int*   bat = (const int*)d_in[2];
    const float* W1  = (const float*)d_in[3];
    const float* as1 = (const float*)d_in[4];
    const float* ad1 = (const float*)d_in[5];
    const float* b1  = (const float*)d_in[6];
    const float* W2  = (const float*)d_in[7];
    const float* as2 = (const float*)d_in[8];
    const float* ad2 = (const float*)d_in[9];
    const float* b2  = (const float*)d_in[10];
    const float* W3  = (const float*)d_in[11];
    const float* as3 = (const float*)d_in[12];
    const float* ad3 = (const float*)d_in[13];
    const float* b3  = (const float*)d_in[14];
    const float* Wm1 = (const float*)d_in[15];
    const float* bm1 = (const float*)d_in[16];
    const float* Wm2 = (const float*)d_in[17];
    const float* bm2 = (const float*)d_in[18];
    float* out = (float*)d_out;

    float *hw, *hin, *asrc, *adst;
    int* deg;
    cudaGetSymbolAddress((void**)&hw,   g_hw);
    cudaGetSymbolAddress((void**)&hin,  g_hin);
    cudaGetSymbolAddress((void**)&asrc, g_asrc);
    cudaGetSymbolAddress((void**)&adst, g_adst);
    cudaGetSymbolAddress((void**)&deg,  g_deg);

    detect_kernel<<<1, 32>>>(ei);

    // CSR build (graph identical across layers)
    cudaMemsetAsync(deg, 0, NN * sizeof(int), 0);
    hist_kernel<<<(ET + 255) / 256, 256>>>(ei);
    scan_kernel<<<1, 1024>>>();
    scatter_kernel<<<(ET + 255) / 256, 256>>>(ei);

    run_layer(x,   W1, as1, ad1, b1, 1, hw, hin, asrc, adst);
    run_layer(hin, W2, as2, ad2, b2, 1, hw, hin, asrc, adst);
    run_layer(hin, W3, as3, ad3, b3, 0, hw, hin, asrc, adst);

    bounds_kernel<<<1, 128>>>(bat);
    pool_kernel<<<GG, HC>>>(hin);
    mlp1_kernel<<<GG, 256>>>(Wm1, bm1);
    mlp2_kernel<<<GG, 256>>>(Wm2, bm2, out);
}

// round 7
// speedup vs baseline: 1.4786x; 1.0620x over previous
#include <cuda_runtime.h>
#include <cuda_bf16.h>
#include <math.h>
#include <stdint.h>

// ---------------- problem constants ----------------
#define NN     40000      // nodes
#define EE     640000     // edges (before self loops)
#define ET     (EE + NN)  // edges incl self loops
#define GG     64         // graphs
#define HH     4          // heads
#define CC     64         // channels/head
#define HC     256        // H*C
#define NHID   1024
#define NOUT   768
#define NEG    0.2f

// ---------------- device scratch ----------------
__device__ __align__(16) float g_hw  [NN * HC];            // post-GEMM features (fp32)
__device__ __align__(16) __nv_bfloat16 g_hwb[NN * HC];     // bf16 shadow for gather
__device__ __align__(16) float g_hin [NN * HC];            // activated layer output
__device__ __align__(16) float g_asrc[NN * HH];
__device__ __align__(16) float g_adst[NN * HH];
__device__ __align__(16) float g_pool[GG * HC];
__device__ __align__(16) float g_hid [GG * NHID];
__device__ int g_deg [NN];
__device__ int g_off [NN + 1];
__device__ int g_cur [NN];
__device__ int g_csrc[ET];       // src id per CSR slot (grouped by dst)
__device__ int g_gstart[GG + 1];
__device__ int g_str;            // 1 = int32 indices, 2 = int64 (low-word stride)

// ---------------- dtype detection ----------------
__global__ void detect_kernel(const int* __restrict__ ei) {
    if (threadIdx.x == 0 && blockIdx.x == 0) {
        int o = 0;
        #pragma unroll
        for (int k = 0; k < 16; k++) o |= ei[2 * k + 1];
        g_str = o ? 1 : 2;
    }
}

// ---------------- CSR build ----------------
__global__ void hist_kernel(const int* __restrict__ ei) {
    int e = blockIdx.x * blockDim.x + threadIdx.x;
    if (e >= ET) return;
    const int str = g_str;
    int d = (e < EE) ? ei[((size_t)EE + e) * str] : e - EE;
    atomicAdd(&g_deg[d], 1);
}

__global__ void scan_kernel() {
    __shared__ int sums[1024];
    const int T = 1024, PER = (NN + T - 1) / T;
    int t = threadIdx.x;
    int base = t * PER;
    int s = 0;
    for (int i = 0; i < PER; i++) {
        int idx = base + i;
        if (idx < NN) s += g_deg[idx];
    }
    sums[t] = s;
    __syncthreads();
    for (int ofs = 1; ofs < T; ofs <<= 1) {
        int v = 0;
        if (t >= ofs) v = sums[t - ofs];
        __syncthreads();
        if (t >= ofs) sums[t] += v;
        __syncthreads();
    }
    int run = (t > 0) ? sums[t - 1] : 0;
    for (int i = 0; i < PER; i++) {
        int idx = base + i;
        if (idx < NN) {
            g_off[idx] = run;
            g_cur[idx] = run;
            run += g_deg[idx];
        }
    }
    if (t == T - 1) g_off[NN] = run;
}

__global__ void scatter_kernel(const int* __restrict__ ei) {
    int e = blockIdx.x * blockDim.x + threadIdx.x;
    if (e >= ET) return;
    const int str = g_str;
    int s, d;
    if (e < EE) { s = ei[(size_t)e * str]; d = ei[((size_t)EE + e) * str]; }
    else        { s = d = e - EE; }
    int pos = atomicAdd(&g_cur[d], 1);
    g_csrc[pos] = s;
}

// ---------------- tf32 helpers ----------------
__device__ __forceinline__ float tf32_rna(float x) {
    uint32_t r; asm("cvt.rna.tf32.f32 %0, %1;" : "=r"(r) : "f"(x));
    return __uint_as_float(r);
}
__device__ __forceinline__ void mma_tf32(float* c, const float* a, const float* b) {
    asm volatile(
        "mma.sync.aligned.m16n8k8.row.col.f32.tf32.tf32.f32 "
        "{%0,%1,%2,%3}, {%4,%5,%6,%7}, {%8,%9}, {%0,%1,%2,%3};"
        : "+f"(c[0]), "+f"(c[1]), "+f"(c[2]), "+f"(c[3])
        : "r"(__float_as_uint(a[0])), "r"(__float_as_uint(a[1])),
          "r"(__float_as_uint(a[2])), "r"(__float_as_uint(a[3])),
          "r"(__float_as_uint(b[0])), "r"(__float_as_uint(b[1])));
}

// ---------------- tensor-core GEMM: C[M,256] = A[M,256] @ B[256,256] --------
// Also emits a bf16 shadow copy of C (HB) for the gather kernel.
#define AST 20
#define BST 136
__global__ __launch_bounds__(256) void gemm_tc(const float* __restrict__ A,
                                               const float* __restrict__ B,
                                               float* __restrict__ C,
                                               __nv_bfloat16* __restrict__ HB, int M) {
    __shared__ float As_hi[128][AST], As_lo[128][AST];
    __shared__ float Bs_hi[16][BST],  Bs_lo[16][BST];

    const int tid = threadIdx.x;
    const int wid = tid >> 5, lane = tid & 31;
    const int wm = (wid & 3) * 32;
    const int wn = (wid >> 2) * 64;
    const int row0 = blockIdx.x * 128;
    const int col0 = blockIdx.y * 128;
    const int r = lane >> 2;
    const int c = lane & 3;

    const int arow = tid >> 2;
    const int acol = (tid & 3) * 4;
    const int bk   = tid >> 5;
    const int bn4  = lane * 4;

    float acc[2][8][4];
    #pragma unroll
    for (int mt = 0; mt < 2; mt++)
        #pragma unroll
        for (int nt = 0; nt < 8; nt++)
            #pragma unroll
            for (int i = 0; i < 4; i++) acc[mt][nt][i] = 0.f;

    for (int k0 = 0; k0 < HC; k0 += 16) {
        #pragma unroll
        for (int i = 0; i < 2; i++) {
            int rr = arow + i * 64;
            float4 v = make_float4(0.f, 0.f, 0.f, 0.f);
            if (row0 + rr < M)
                v = *(const float4*)(A + (size_t)(row0 + rr) * HC + k0 + acol);
            float h0 = tf32_rna(v.x), h1 = tf32_rna(v.y);
            float h2 = tf32_rna(v.z), h3 = tf32_rna(v.w);
            As_hi[rr][acol + 0] = h0; As_lo[rr][acol + 0] = v.x - h0;
            As_hi[rr][acol + 1] = h1; As_lo[rr][acol + 1] = v.y - h1;
            As_hi[rr][acol + 2] = h2; As_lo[rr][acol + 2] = v.z - h2;
            As_hi[rr][acol + 3] = h3; As_lo[rr][acol + 3] = v.w - h3;
        }
        #pragma unroll
        for (int i = 0; i < 2; i++) {
            int kk = bk + i * 8;
            float4 v = *(const float4*)(B + (size_t)(k0 + kk) * HC + col0 + bn4);
            float h0 = tf32_rna(v.x), h1 = tf32_rna(v.y);
            float h2 = tf32_rna(v.z), h3 = tf32_rna(v.w);
            Bs_hi[kk][bn4 + 0] = h0; Bs_lo[kk][bn4 + 0] = v.x - h0;
            Bs_hi[kk][bn4 + 1] = h1; Bs_lo[kk][bn4 + 1] = v.y - h1;
            Bs_hi[kk][bn4 + 2] = h2; Bs_lo[kk][bn4 + 2] = v.z - h2;
            Bs_hi[kk][bn4 + 3] = h3; Bs_lo[kk][bn4 + 3] = v.w - h3;
        }
        __syncthreads();

        #pragma unroll
        for (int ks = 0; ks < 16; ks += 8) {
            float ah[2][4], al[2][4];
            #pragma unroll
            for (int mt = 0; mt < 2; mt++) {
                int mb = wm + mt * 16;
                ah[mt][0] = As_hi[mb + r    ][ks + c    ];
                ah[mt][1] = As_hi[mb + r + 8][ks + c    ];
                ah[mt][2] = As_hi[mb + r    ][ks + c + 4];
                ah[mt][3] = As_hi[mb + r + 8][ks + c + 4];
                al[mt][0] = As_lo[mb + r    ][ks + c    ];
                al[mt][1] = As_lo[mb + r + 8][ks + c    ];
                al[mt][2] = As_lo[mb + r    ][ks + c + 4];
                al[mt][3] = As_lo[mb + r + 8][ks + c + 4];
            }
            #pragma unroll
            for (int nt = 0; nt < 8; nt++) {
                int nb = wn + nt * 8 + r;
                float bh[2], bl[2];
                bh[0] = Bs_hi[ks + c    ][nb];
                bh[1] = Bs_hi[ks + c + 4][nb];
                bl[0] = Bs_lo[ks + c    ][nb];
                bl[1] = Bs_lo[ks + c + 4][nb];
                #pragma unroll
                for (int mt = 0; mt < 2; mt++) {
                    mma_tf32(acc[mt][nt], ah[mt], bh);
                    mma_tf32(acc[mt][nt], al[mt], bh);
                    mma_tf32(acc[mt][nt], ah[mt], bl);
                }
            }
        }
        __syncthreads();
    }

    #pragma unroll
    for (int mt = 0; mt < 2; mt++) {
        #pragma unroll
        for (int nt = 0; nt < 8; nt++) {
            int rr = row0 + wm + mt * 16 + r;
            int cc = col0 + wn + nt * 8 + 2 * c;
            if (rr < M) {
                float2 v0 = make_float2(acc[mt][nt][0], acc[mt][nt][1]);
                *(float2*)(C + (size_t)rr * HC + cc) = v0;
                *(__nv_bfloat162*)(HB + (size_t)rr * HC + cc) =
                    __floats2bfloat162_rn(v0.x, v0.y);
            }
            if (rr + 8 < M) {
                float2 v1 = make_float2(acc[mt][nt][2], acc[mt][nt][3]);
                *(float2*)(C + (size_t)(rr + 8) * HC + cc) = v1;
                *(__nv_bfloat162*)(HB + (size_t)(rr + 8) * HC + cc) =
                    __floats2bfloat162_rn(v1.x, v1.y);
            }
        }
    }
}

// ---------------- per-node attention scalars (fp32 input) -------------------
__global__ void node_prep(const float* __restrict__ hw,
                          const float* __restrict__ a_s, const float* __restrict__ a_d,
                          float* __restrict__ asrc, float* __restrict__ adst) {
    __shared__ float ss[HC], sd[HC];
    for (int i = threadIdx.x; i < HC; i += blockDim.x) { ss[i] = a_s[i]; sd[i] = a_d[i]; }
    __syncthreads();
    int t = blockIdx.x * blockDim.x + threadIdx.x;
    if (t >= NN * HH) return;
    int n = t >> 2, h = t & 3;
    const float4* hp = (const float4*)(hw + (size_t)n * HC + h * CC);
    const float4* sp = (const float4*)(ss + h * CC);
    const float4* dp = (const float4*)(sd + h * CC);
    float sa = 0.f, da = 0.f;
    #pragma unroll
    for (int i = 0; i < 16; i++) {
        float4 v = hp[i], w1 = sp[i], w2 = dp[i];
        sa += v.x * w1.x + v.y * w1.y + v.z * w1.z + v.w * w1.w;
        da += v.x * w2.x + v.y * w2.y + v.z * w2.z + v.w * w2.w;
    }
    asrc[t] = sa; adst[t] = da;
}

// ---------------- fused GAT aggregation: warp per dst node, bf16 gather -----
// out[d] = (sum_e p_e * hwb[src_e]) / (sum_e p_e) + bias  [, relu]
// lane owns channels [8*lane, 8*lane+8); head = lane>>3.
__global__ __launch_bounds__(256) void gat_agg(const __nv_bfloat16* __restrict__ hwb,
                                               const float* __restrict__ asrc,
                                               const float* __restrict__ adst,
                                               const float* __restrict__ bias,
                                               float* __restrict__ outp, int relu) {
    int w = (blockIdx.x * blockDim.x + threadIdx.x) >> 5;
    int lane = threadIdx.x & 31;
    if (w >= NN) return;
    const int h  = lane >> 3;
    const int c0 = lane * 8;
    const int beg = g_off[w], end = g_off[w + 1];
    const float ad = adst[w * HH + h];

    float acc[8];
    #pragma unroll
    for (int i = 0; i < 8; i++) acc[i] = 0.f;
    float den = 0.f;

    int j = beg;
    for (; j + 1 < end; j += 2) {
        int s0 = g_csrc[j], s1 = g_csrc[j + 1];
        float v0 = asrc[s0 * HH + h] + ad;
        float v1 = asrc[s1 * HH + h] + ad;
        v0 = (v0 > 0.f) ? v0 : v0 * NEG;
        v1 = (v1 > 0.f) ? v1 : v1 * NEG;
        float p0 = __expf(v0), p1 = __expf(v1);
        den += p0 + p1;
        uint4 u0 = *(const uint4*)(hwb + (size_t)s0 * HC + c0);
        uint4 u1 = *(const uint4*)(hwb + (size_t)s1 * HC + c0);
        float2 a0 = __bfloat1622float2(*(__nv_bfloat162*)&u0.x);
        float2 a1 = __bfloat1622float2(*(__nv_bfloat162*)&u0.y);
        float2 a2 = __bfloat1622float2(*(__nv_bfloat162*)&u0.z);
        float2 a3 = __bfloat1622float2(*(__nv_bfloat162*)&u0.w);
        float2 b0 = __bfloat1622float2(*(__nv_bfloat162*)&u1.x);
        float2 b1 = __bfloat1622float2(*(__nv_bfloat162*)&u1.y);
        float2 b2 = __bfloat1622float2(*(__nv_bfloat162*)&u1.z);
        float2 b3 = __bfloat1622float2(*(__nv_bfloat162*)&u1.w);
        acc[0] = fmaf(p0, a0.x, acc[0]); acc[1] = fmaf(p0, a0.y, acc[1]);
        acc[2] = fmaf(p0, a1.x, acc[2]); acc[3] = fmaf(p0, a1.y, acc[3]);
        acc[4] = fmaf(p0, a2.x, acc[4]); acc[5] = fmaf(p0, a2.y, acc[5]);
        acc[6] = fmaf(p0, a3.x, acc[6]); acc[7] = fmaf(p0, a3.y, acc[7]);
        acc[0] = fmaf(p1, b0.x, acc[0]); acc[1] = fmaf(p1, b0.y, acc[1]);
        acc[2] = fmaf(p1, b1.x, acc[2]); acc[3] = fmaf(p1, b1.y, acc[3]);
        acc[4] = fmaf(p1, b2.x, acc[4]); acc[5] = fmaf(p1, b2.y, acc[5]);
        acc[6] = fmaf(p1, b3.x, acc[6]); acc[7] = fmaf(p1, b3.y, acc[7]);
    }
    if (j < end) {
        int s0 = g_csrc[j];
        float v0 = asrc[s0 * HH + h] + ad;
        v0 = (v0 > 0.f) ? v0 : v0 * NEG;
        float p0 = __expf(v0);
        den += p0;
        uint4 u0 = *(const uint4*)(hwb + (size_t)s0 * HC + c0);
        float2 a0 = __bfloat1622float2(*(__nv_bfloat162*)&u0.x);
        float2 a1 = __bfloat1622float2(*(__nv_bfloat162*)&u0.y);
        float2 a2 = __bfloat1622float2(*(__nv_bfloat162*)&u0.z);
        float2 a3 = __bfloat1622float2(*(__nv_bfloat162*)&u0.w);
        acc[0] = fmaf(p0, a0.x, acc[0]); acc[1] = fmaf(p0, a0.y, acc[1]);
        acc[2] = fmaf(p0, a1.x, acc[2]); acc[3] = fmaf(p0, a1.y, acc[3]);
        acc[4] = fmaf(p0, a2.x, acc[4]); acc[5] = fmaf(p0, a2.y, acc[5]);
        acc[6] = fmaf(p0, a3.x, acc[6]); acc[7] = fmaf(p0, a3.y, acc[7]);
    }

    float inv = 1.f / den;
    float4 bb0 = *(const float4*)(bias + c0);
    float4 bb1 = *(const float4*)(bias + c0 + 4);
    float4 o0, o1;
    o0.x = acc[0] * inv + bb0.x; o0.y = acc[1] * inv + bb0.y;
    o0.z = acc[2] * inv + bb0.z; o0.w = acc[3] * inv + bb0.w;
    o1.x = acc[4] * inv + bb1.x; o1.y = acc[5] * inv + bb1.y;
    o1.z = acc[6] * inv + bb1.z; o1.w = acc[7] * inv + bb1.w;
    if (relu) {
        o0.x = fmaxf(o0.x, 0.f); o0.y = fmaxf(o0.y, 0.f);
        o0.z = fmaxf(o0.z, 0.f); o0.w = fmaxf(o0.w, 0.f);
        o1.x = fmaxf(o1.x, 0.f); o1.y = fmaxf(o1.y, 0.f);
        o1.z = fmaxf(o1.z, 0.f); o1.w = fmaxf(o1.w, 0.f);
    }
    float* op = outp + (size_t)w * HC + c0;
    *(float4*)op = o0;
    *(float4*)(op + 4) = o1;
}

// ---------------- graph boundaries ----------------
__global__ void bounds_kernel(const int* __restrict__ batch) {
    int g = blockIdx.x * blockDim.x + threadIdx.x;
    if (g > GG) return;
    const int str = g_str;
    int lo = 0, hi = NN;
    while (lo < hi) {
        int mid = (lo + hi) >> 1;
        if (batch[(size_t)mid * str] < g) lo = mid + 1; else hi = mid;
    }
    g_gstart[g] = lo;
}

// ---------------- mean pool ----------------
__global__ void pool_kernel(const float* __restrict__ h) {
    int g = blockIdx.x, c = threadIdx.x;
    int s = g_gstart[g], e = g_gstart[g + 1];
    float acc = 0.f;
    for (int n = s; n < e; n++) acc += h[(size_t)n * HC + c];
    float cnt = (float)max(e - s, 1);
    g_pool[g * HC + c] = acc / cnt;
}

// ---------------- MLP ----------------
__global__ void mlp1_kernel(const float* __restrict__ Wm1, const float* __restrict__ bm1) {
    __shared__ float row[HC];
    int g = blockIdx.x, t = threadIdx.x;
    for (int i = t; i < HC; i += blockDim.x) row[i] = g_pool[g * HC + i];
    __syncthreads();
    #pragma unroll
    for (int j = 0; j < NHID / 256; j++) {
        int o = t + j * 256;
        float acc = bm1[o];
        for (int k = 0; k < HC; k++) acc = fmaf(row[k], Wm1[(size_t)k * NHID + o], acc);
        g_hid[g * NHID + o] = fmaxf(acc, 0.f);
    }
}

__global__ void mlp2_kernel(const float* __restrict__ Wm2, const float* __restrict__ bm2,
                            float* __restrict__ out) {
    __shared__ float row[NHID];
    int g = blockIdx.x, t = threadIdx.x;
    for (int i = t; i < NHID; i += blockDim.x) row[i] = g_hid[g * NHID + i];
    __syncthreads();
    #pragma unroll
    for (int j = 0; j < NOUT / 256; j++) {
        int o = t + j * 256;
        float acc = bm2[o];
        for (int k = 0; k < NHID; k++) acc = fmaf(row[k], Wm2[(size_t)k * NOUT + o], acc);
        out[(size_t)g * NOUT + o] = acc;
    }
}

// ---------------- host orchestration ----------------
static void run_layer(const float* in, const float* W, const float* as_, const float* ad_,
                      const float* b, int relu,
                      float* hw, __nv_bfloat16* hwb, float* hin_next,
                      float* asrc, float* adst) {
    dim3 ggrid((NN + 127) / 128, HC / 128);
    gemm_tc<<<ggrid, 256>>>(in, W, hw, hwb, NN);
    node_prep<<<(NN * HH + 255) / 256, 256>>>(hw, as_, ad_, asrc, adst);
    gat_agg<<<(NN * 32 + 255) / 256, 256>>>(hwb, asrc, adst, b, hin_next, relu);
}

extern "C" void kernel_launch(void* const* d_in, const int* in_sizes, int n_in,
                              void* d_out, int out_size) {
    const float* x   = (const float*)d_in[0];
    const int*   ei  = (const int*)d_in[1];
    const int*   bat = (const int*)d_in[2];
    const float* W1  = (const float*)d_in[3];
    const float* as1 = (const float*)d_in[4];
    const float* ad1 = (const float*)d_in[5];
    const float* b1  = (const float*)d_in[6];
    const float* W2  = (const float*)d_in[7];
    const float* as2 = (const float*)d_in[8];
    const float* ad2 = (const float*)d_in[9];
    const float* b2  = (const float*)d_in[10];
    const float* W3  = (const float*)d_in[11];
    const float* as3 = (const float*)d_in[12];
    const float* ad3 = (const float*)d_in[13];
    const float* b3  = (const float*)d_in[14];
    const float* Wm1 = (const float*)d_in[15];
    const float* bm1 = (const float*)d_in[16];
    const float* Wm2 = (const float*)d_in[17];
    const float* bm2 = (const float*)d_in[18];
    float* out = (float*)d_out;

    float *hw, *hin, *asrc, *adst;
    __nv_bfloat16* hwb;
    int* deg;
    cudaGetSymbolAddress((void**)&hw,   g_hw);
    cudaGetSymbolAddress((void**)&hwb,  g_hwb);
    cudaGetSymbolAddress((void**)&hin,  g_hin);
    cudaGetSymbolAddress((void**)&asrc, g_asrc);
    cudaGetSymbolAddress((void**)&adst, g_adst);
    cudaGetSymbolAddress((void**)&deg,  g_deg);

    detect_kernel<<<1, 32>>>(ei);

    // CSR build (graph identical across layers)
    cudaMemsetAsync(deg, 0, NN * sizeof(int), 0);
    hist_kernel<<<(ET + 255) / 256, 256>>>(ei);
    scan_kernel<<<1, 1024>>>();
    scatter_kernel<<<(ET + 255) / 256, 256>>>(ei);

    run_layer(x,   W1, as1, ad1, b1, 1, hw, hwb, hin, asrc, adst);
    run_layer(hin, W2, as2, ad2, b2, 1, hw, hwb, hin, asrc, adst);
    run_layer(hin, W3, as3, ad3, b3, 0, hw, hwb, hin, asrc, adst);

    bounds_kernel<<<1, 128>>>(bat);
    pool_kernel<<<GG, HC>>>(hin);
    mlp1_kernel<<<GG, 256>>>(Wm1, bm1);
    mlp2_kernel<<<GG, 256>>>(Wm2, bm2, out);
}

// round 8
// speedup vs baseline: 1.4851x; 1.0044x over previous
#include <cuda_runtime.h>
#include <cuda_bf16.h>
#include <math.h>
#include <stdint.h>

// ---------------- problem constants ----------------
#define NN     40000      // nodes
#define EE     640000     // edges (before self loops)
#define ET     (EE + NN)  // edges incl self loops
#define GG     64         // graphs
#define HH     4          // heads
#define CC     64         // channels/head
#define HC     256        // H*C
#define NHID   1024
#define NOUT   768
#define NEG    0.2f

// ---------------- device scratch ----------------
__device__ __align__(16) __nv_bfloat16 g_hwb[NN * HC];     // bf16 features for gather
__device__ __align__(16) float g_hin [NN * HC];            // activated layer output
__device__ __align__(16) float g_asrc[NN * HH];
__device__ __align__(16) float g_adst[NN * HH];
__device__ __align__(16) float g_p   [(size_t)ET * HH];    // edge probs, CSR order
__device__ __align__(16) float g_pool[GG * HC];
__device__ __align__(16) float g_hid [GG * NHID];
__device__ int g_deg [NN];
__device__ int g_off [NN + 1];
__device__ int g_cur [NN];
__device__ int g_csrc[ET];       // src id per CSR slot (grouped by dst)
__device__ int g_cdst[ET];       // dst id per CSR slot
__device__ int g_gstart[GG + 1];
__device__ int g_str;            // 1 = int32 indices, 2 = int64 (low-word stride)

// ---------------- dtype detection ----------------
__global__ void detect_kernel(const int* __restrict__ ei) {
    if (threadIdx.x == 0 && blockIdx.x == 0) {
        int o = 0;
        #pragma unroll
        for (int k = 0; k < 16; k++) o |= ei[2 * k + 1];
        g_str = o ? 1 : 2;
    }
}

// ---------------- CSR build ----------------
__global__ void hist_kernel(const int* __restrict__ ei) {
    int e = blockIdx.x * blockDim.x + threadIdx.x;
    if (e >= ET) return;
    const int str = g_str;
    int d = (e < EE) ? ei[((size_t)EE + e) * str] : e - EE;
    atomicAdd(&g_deg[d], 1);
}

__global__ void scan_kernel() {
    __shared__ int sums[1024];
    const int T = 1024, PER = (NN + T - 1) / T;
    int t = threadIdx.x;
    int base = t * PER;
    int s = 0;
    for (int i = 0; i < PER; i++) {
        int idx = base + i;
        if (idx < NN) s += g_deg[idx];
    }
    sums[t] = s;
    __syncthreads();
    for (int ofs = 1; ofs < T; ofs <<= 1) {
        int v = 0;
        if (t >= ofs) v = sums[t - ofs];
        __syncthreads();
        if (t >= ofs) sums[t] += v;
        __syncthreads();
    }
    int run = (t > 0) ? sums[t - 1] : 0;
    for (int i = 0; i < PER; i++) {
        int idx = base + i;
        if (idx < NN) {
            g_off[idx] = run;
            g_cur[idx] = run;
            run += g_deg[idx];
        }
    }
    if (t == T - 1) g_off[NN] = run;
}

__global__ void scatter_kernel(const int* __restrict__ ei) {
    int e = blockIdx.x * blockDim.x + threadIdx.x;
    if (e >= ET) return;
    const int str = g_str;
    int s, d;
    if (e < EE) { s = ei[(size_t)e * str]; d = ei[((size_t)EE + e) * str]; }
    else        { s = d = e - EE; }
    int pos = atomicAdd(&g_cur[d], 1);
    g_csrc[pos] = s;
    g_cdst[pos] = d;
}

// ---------------- tf32 helpers ----------------
__device__ __forceinline__ float tf32_rna(float x) {
    uint32_t r; asm("cvt.rna.tf32.f32 %0, %1;" : "=r"(r) : "f"(x));
    return __uint_as_float(r);
}
__device__ __forceinline__ void mma_tf32(float* c, const float* a, const float* b) {
    asm volatile(
        "mma.sync.aligned.m16n8k8.row.col.f32.tf32.tf32.f32 "
        "{%0,%1,%2,%3}, {%4,%5,%6,%7}, {%8,%9}, {%0,%1,%2,%3};"
        : "+f"(c[0]), "+f"(c[1]), "+f"(c[2]), "+f"(c[3])
        : "r"(__float_as_uint(a[0])), "r"(__float_as_uint(a[1])),
          "r"(__float_as_uint(a[2])), "r"(__float_as_uint(a[3])),
          "r"(__float_as_uint(b[0])), "r"(__float_as_uint(b[1])));
}

// ---------------- tensor-core GEMM + fused attention-scalar epilogue --------
// HB = bf16(A@W); asrc/adst += per-row dot with a_s/a_d (register-exact).
#define AST 20
#define BST 136
__global__ __launch_bounds__(256) void gemm_tc(const float* __restrict__ A,
                                               const float* __restrict__ B,
                                               __nv_bfloat16* __restrict__ HB,
                                               const float* __restrict__ a_s,
                                               const float* __restrict__ a_d,
                                               float* __restrict__ asrc,
                                               float* __restrict__ adst, int M) {
    __shared__ float As_hi[128][AST], As_lo[128][AST];
    __shared__ float Bs_hi[16][BST],  Bs_lo[16][BST];

    const int tid = threadIdx.x;
    const int wid = tid >> 5, lane = tid & 31;
    const int wm = (wid & 3) * 32;
    const int wn = (wid >> 2) * 64;
    const int row0 = blockIdx.x * 128;
    const int col0 = blockIdx.y * 128;
    const int r = lane >> 2;
    const int c = lane & 3;

    const int arow = tid >> 2;
    const int acol = (tid & 3) * 4;
    const int bk   = tid >> 5;
    const int bn4  = lane * 4;

    float acc[2][8][4];
    #pragma unroll
    for (int mt = 0; mt < 2; mt++)
        #pragma unroll
        for (int nt = 0; nt < 8; nt++)
            #pragma unroll
            for (int i = 0; i < 4; i++) acc[mt][nt][i] = 0.f;

    for (int k0 = 0; k0 < HC; k0 += 16) {
        #pragma unroll
        for (int i = 0; i < 2; i++) {
            int rr = arow + i * 64;
            float4 v = make_float4(0.f, 0.f, 0.f, 0.f);
            if (row0 + rr < M)
                v = *(const float4*)(A + (size_t)(row0 + rr) * HC + k0 + acol);
            float h0 = tf32_rna(v.x), h1 = tf32_rna(v.y);
            float h2 = tf32_rna(v.z), h3 = tf32_rna(v.w);
            As_hi[rr][acol + 0] = h0; As_lo[rr][acol + 0] = v.x - h0;
            As_hi[rr][acol + 1] = h1; As_lo[rr][acol + 1] = v.y - h1;
            As_hi[rr][acol + 2] = h2; As_lo[rr][acol + 2] = v.z - h2;
            As_hi[rr][acol + 3] = h3; As_lo[rr][acol + 3] = v.w - h3;
        }
        #pragma unroll
        for (int i = 0; i < 2; i++) {
            int kk = bk + i * 8;
            float4 v = *(const float4*)(B + (size_t)(k0 + kk) * HC + col0 + bn4);
            float h0 = tf32_rna(v.x), h1 = tf32_rna(v.y);
            float h2 = tf32_rna(v.z), h3 = tf32_rna(v.w);
            Bs_hi[kk][bn4 + 0] = h0; Bs_lo[kk][bn4 + 0] = v.x - h0;
            Bs_hi[kk][bn4 + 1] = h1; Bs_lo[kk][bn4 + 1] = v.y - h1;
            Bs_hi[kk][bn4 + 2] = h2; Bs_lo[kk][bn4 + 2] = v.z - h2;
            Bs_hi[kk][bn4 + 3] = h3; Bs_lo[kk][bn4 + 3] = v.w - h3;
        }
        __syncthreads();

        #pragma unroll
        for (int ks = 0; ks < 16; ks += 8) {
            float ah[2][4], al[2][4];
            #pragma unroll
            for (int mt = 0; mt < 2; mt++) {
                int mb = wm + mt * 16;
                ah[mt][0] = As_hi[mb + r    ][ks + c    ];
                ah[mt][1] = As_hi[mb + r + 8][ks + c    ];
                ah[mt][2] = As_hi[mb + r    ][ks + c + 4];
                ah[mt][3] = As_hi[mb + r + 8][ks + c + 4];
                al[mt][0] = As_lo[mb + r    ][ks + c    ];
                al[mt][1] = As_lo[mb + r + 8][ks + c    ];
                al[mt][2] = As_lo[mb + r    ][ks + c + 4];
                al[mt][3] = As_lo[mb + r + 8][ks + c + 4];
            }
            #pragma unroll
            for (int nt = 0; nt < 8; nt++) {
                int nb = wn + nt * 8 + r;
                float bh[2], bl[2];
                bh[0] = Bs_hi[ks + c    ][nb];
                bh[1] = Bs_hi[ks + c + 4][nb];
                bl[0] = Bs_lo[ks + c    ][nb];
                bl[1] = Bs_lo[ks + c + 4][nb];
                #pragma unroll
                for (int mt = 0; mt < 2; mt++) {
                    mma_tf32(acc[mt][nt], ah[mt], bh);
                    mma_tf32(acc[mt][nt], al[mt], bh);
                    mma_tf32(acc[mt][nt], ah[mt], bl);
                }
            }
        }
        __syncthreads();
    }

    // ---- epilogue: bf16 store + fused attention scalars ----
    // this thread's 16 columns all lie in head hidx = (col0+wn)/64
    const int hidx = (col0 + wn) >> 6;
    float ws[16], wd[16];
    #pragma unroll
    for (int nt = 0; nt < 8; nt++)
        #pragma unroll
        for (int k = 0; k < 2; k++) {
            int ccol = col0 + wn + nt * 8 + 2 * c + k;
            ws[nt * 2 + k] = a_s[ccol];
            wd[nt * 2 + k] = a_d[ccol];
        }

    #pragma unroll
    for (int mt = 0; mt < 2; mt++) {
        float ps0 = 0.f, pd0 = 0.f, ps1 = 0.f, pd1 = 0.f;
        #pragma unroll
        for (int nt = 0; nt < 8; nt++) {
            ps0 += acc[mt][nt][0] * ws[2 * nt] + acc[mt][nt][1] * ws[2 * nt + 1];
            pd0 += acc[mt][nt][0] * wd[2 * nt] + acc[mt][nt][1] * wd[2 * nt + 1];
            ps1 += acc[mt][nt][2] * ws[2 * nt] + acc[mt][nt][3] * ws[2 * nt + 1];
            pd1 += acc[mt][nt][2] * wd[2 * nt] + acc[mt][nt][3] * wd[2 * nt + 1];
        }
        // reduce across the 4 lanes (c = 0..3) sharing each row
        ps0 += __shfl_xor_sync(0xffffffffu, ps0, 1); ps0 += __shfl_xor_sync(0xffffffffu, ps0, 2);
        pd0 += __shfl_xor_sync(0xffffffffu, pd0, 1); pd0 += __shfl_xor_sync(0xffffffffu, pd0, 2);
        ps1 += __shfl_xor_sync(0xffffffffu, ps1, 1); ps1 += __shfl_xor_sync(0xffffffffu, ps1, 2);
        pd1 += __shfl_xor_sync(0xffffffffu, pd1, 1); pd1 += __shfl_xor_sync(0xffffffffu, pd1, 2);
        int rr = row0 + wm + mt * 16 + r;
        if (c == 0) {
            if (rr < M)     { atomicAdd(&asrc[rr * HH + hidx], ps0);
                              atomicAdd(&adst[rr * HH + hidx], pd0); }
            if (rr + 8 < M) { atomicAdd(&asrc[(rr + 8) * HH + hidx], ps1);
                              atomicAdd(&adst[(rr + 8) * HH + hidx], pd1); }
        }
        #pragma unroll
        for (int nt = 0; nt < 8; nt++) {
            int cc = col0 + wn + nt * 8 + 2 * c;
            if (rr < M)
                *(__nv_bfloat162*)(HB + (size_t)rr * HC + cc) =
                    __floats2bfloat162_rn(acc[mt][nt][0], acc[mt][nt][1]);
            if (rr + 8 < M)
                *(__nv_bfloat162*)(HB + (size_t)(rr + 8) * HC + cc) =
                    __floats2bfloat162_rn(acc[mt][nt][2], acc[mt][nt][3]);
        }
    }
}

// ---------------- edge probabilities (CSR order, edge-parallel) -------------
__global__ void edge_p(const float* __restrict__ asrc, const float* __restrict__ adst) {
    size_t t = (size_t)blockIdx.x * blockDim.x + threadIdx.x;
    if (t >= (size_t)ET * HH) return;
    int e = (int)(t >> 2), h = (int)(t & 3);
    int s = g_csrc[e], d = g_cdst[e];
    float v = asrc[s * HH + h] + adst[d * HH + h];
    v = (v > 0.f) ? v : v * NEG;
    g_p[t] = __expf(v);
}

// ---------------- fused GAT aggregation: warp per dst node, bf16 gather -----
// out[d] = (sum_e p_e * hwb[src_e]) / (sum_e p_e) + bias  [, relu]
// lane owns channels [8*lane, 8*lane+8); head = lane>>3.
__global__ __launch_bounds__(256) void gat_agg(const __nv_bfloat16* __restrict__ hwb,
                                               const float* __restrict__ bias,
                                               float* __restrict__ outp, int relu) {
    int w = (blockIdx.x * blockDim.x + threadIdx.x) >> 5;
    int lane = threadIdx.x & 31;
    if (w >= NN) return;
    const int h  = lane >> 3;
    const int c0 = lane * 8;
    const int beg = g_off[w], end = g_off[w + 1];

    float acc[8];
    #pragma unroll
    for (int i = 0; i < 8; i++) acc[i] = 0.f;
    float den = 0.f;

    int j = beg;
    for (; j + 1 < end; j += 2) {
        int s0 = g_csrc[j], s1 = g_csrc[j + 1];
        float p0 = g_p[(size_t)j * HH + h];
        float p1 = g_p[(size_t)(j + 1) * HH + h];
        den += p0 + p1;
        uint4 u0 = *(const uint4*)(hwb + (size_t)s0 * HC + c0);
        uint4 u1 = *(const uint4*)(hwb + (size_t)s1 * HC + c0);
        float2 a0 = __bfloat1622float2(*(__nv_bfloat162*)&u0.x);
        float2 a1 = __bfloat1622float2(*(__nv_bfloat162*)&u0.y);
        float2 a2 = __bfloat1622float2(*(__nv_bfloat162*)&u0.z);
        float2 a3 = __bfloat1622float2(*(__nv_bfloat162*)&u0.w);
        float2 b0 = __bfloat1622float2(*(__nv_bfloat162*)&u1.x);
        float2 b1 = __bfloat1622float2(*(__nv_bfloat162*)&u1.y);
        float2 b2 = __bfloat1622float2(*(__nv_bfloat162*)&u1.z);
        float2 b3 = __bfloat1622float2(*(__nv_bfloat162*)&u1.w);
        acc[0] = fmaf(p0, a0.x, acc[0]); acc[1] = fmaf(p0, a0.y, acc[1]);
        acc[2] = fmaf(p0, a1.x, acc[2]); acc[3] = fmaf(p0, a1.y, acc[3]);
        acc[4] = fmaf(p0, a2.x, acc[4]); acc[5] = fmaf(p0, a2.y, acc[5]);
        acc[6] = fmaf(p0, a3.x, acc[6]); acc[7] = fmaf(p0, a3.y, acc[7]);
        acc[0] = fmaf(p1, b0.x, acc[0]); acc[1] = fmaf(p1, b0.y, acc[1]);
        acc[2] = fmaf(p1, b1.x, acc[2]); acc[3] = fmaf(p1, b1.y, acc[3]);
        acc[4] = fmaf(p1, b2.x, acc[4]); acc[5] = fmaf(p1, b2.y, acc[5]);
        acc[6] = fmaf(p1, b3.x, acc[6]); acc[7] = fmaf(p1, b3.y, acc[7]);
    }
    if (j < end) {
        int s0 = g_csrc[j];
        float p0 = g_p[(size_t)j * HH + h];
        den += p0;
        uint4 u0 = *(const uint4*)(hwb + (size_t)s0 * HC + c0);
        float2 a0 = __bfloat1622float2(*(__nv_bfloat162*)&u0.x);
        float2 a1 = __bfloat1622float2(*(__nv_bfloat162*)&u0.y);
        float2 a2 = __bfloat1622float2(*(__nv_bfloat162*)&u0.z);
        float2 a3 = __bfloat1622float2(*(__nv_bfloat162*)&u0.w);
        acc[0] = fmaf(p0, a0.x, acc[0]); acc[1] = fmaf(p0, a0.y, acc[1]);
        acc[2] = fmaf(p0, a1.x, acc[2]); acc[3] = fmaf(p0, a1.y, acc[3]);
        acc[4] = fmaf(p0, a2.x, acc[4]); acc[5] = fmaf(p0, a2.y, acc[5]);
        acc[6] = fmaf(p0, a3.x, acc[6]); acc[7] = fmaf(p0, a3.y, acc[7]);
    }

    float inv = 1.f / den;
    float4 bb0 = *(const float4*)(bias + c0);
    float4 bb1 = *(const float4*)(bias + c0 + 4);
    float4 o0, o1;
    o0.x = acc[0] * inv + bb0.x; o0.y = acc[1] * inv + bb0.y;
    o0.z = acc[2] * inv + bb0.z; o0.w = acc[3] * inv + bb0.w;
    o1.x = acc[4] * inv + bb1.x; o1.y = acc[5] * inv + bb1.y;
    o1.z = acc[6] * inv + bb1.z; o1.w = acc[7] * inv + bb1.w;
    if (relu) {
        o0.x = fmaxf(o0.x, 0.f); o0.y = fmaxf(o0.y, 0.f);
        o0.z = fmaxf(o0.z, 0.f); o0.w = fmaxf(o0.w, 0.f);
        o1.x = fmaxf(o1.x, 0.f); o1.y = fmaxf(o1.y, 0.f);
        o1.z = fmaxf(o1.z, 0.f); o1.w = fmaxf(o1.w, 0.f);
    }
    float* op = outp + (size_t)w * HC + c0;
    *(float4*)op = o0;
    *(float4*)(op + 4) = o1;
}

// ---------------- graph boundaries ----------------
__global__ void bounds_kernel(const int* __restrict__ batch) {
    int g = blockIdx.x * blockDim.x + threadIdx.x;
    if (g > GG) return;
    const int str = g_str;
    int lo = 0, hi = NN;
    while (lo < hi) {
        int mid = (lo + hi) >> 1;
        if (batch[(size_t)mid * str] < g) lo = mid + 1; else hi = mid;
    }
    g_gstart[g] = lo;
}

// ---------------- mean pool ----------------
__global__ void pool_kernel(const float* __restrict__ h) {
    int g = blockIdx.x, c = threadIdx.x;
    int s = g_gstart[g], e = g_gstart[g + 1];
    float acc = 0.f;
    for (int n = s; n < e; n++) acc += h[(size_t)n * HC + c];
    float cnt = (float)max(e - s, 1);
    g_pool[g * HC + c] = acc / cnt;
}

// ---------------- MLP ----------------
__global__ void mlp1_kernel(const float* __restrict__ Wm1, const float* __restrict__ bm1) {
    __shared__ float row[HC];
    int g = blockIdx.x, t = threadIdx.x;
    for (int i = t; i < HC; i += blockDim.x) row[i] = g_pool[g * HC + i];
    __syncthreads();
    #pragma unroll
    for (int j = 0; j < NHID / 256; j++) {
        int o = t + j * 256;
        float acc = bm1[o];
        for (int k = 0; k < HC; k++) acc = fmaf(row[k], Wm1[(size_t)k * NHID + o], acc);
        g_hid[g * NHID + o] = fmaxf(acc, 0.f);
    }
}

__global__ void mlp2_kernel(const float* __restrict__ Wm2, const float* __restrict__ bm2,
                            float* __restrict__ out) {
    __shared__ float row[NHID];
    int g = blockIdx.x, t = threadIdx.x;
    for (int i = t; i < NHID; i += blockDim.x) row[i] = g_hid[g * NHID + i];
    __syncthreads();
    #pragma unroll
    for (int j = 0; j < NOUT / 256; j++) {
        int o = t + j * 256;
        float acc = bm2[o];
        for (int k = 0; k < NHID; k++) acc = fmaf(row[k], Wm2[(size_t)k * NOUT + o], acc);
        out[(size_t)g * NOUT + o] = acc;
    }
}

// ---------------- host orchestration ----------------
static void run_layer(const float* in, const float* W, const float* as_, const float* ad_,
                      const float* b, int relu,
                      __nv_bfloat16* hwb, float* hin_next, float* asrc, float* adst) {
    cudaMemsetAsync(asrc, 0, (size_t)NN * HH * sizeof(float), 0);
    cudaMemsetAsync(adst, 0, (size_t)NN * HH * sizeof(float), 0);
    dim3 ggrid((NN + 127) / 128, HC / 128);
    gemm_tc<<<ggrid, 256>>>(in, W, hwb, as_, ad_, asrc, adst, NN);
    edge_p<<<((size_t)ET * HH + 255) / 256, 256>>>(asrc, adst);
    gat_agg<<<(NN * 32 + 255) / 256, 256>>>(hwb, b, hin_next, relu);
}

extern "C" void kernel_launch(void* const* d_in, const int* in_sizes, int n_in,
                              void* d_out, int out_size) {
    const float* x   = (const float*)d_in[0];
    const int*   ei  = (const int*)d_in[1];
    const int*   bat = (const int*)d_in[2];
    const float* W1  = (const float*)d_in[3];
    const float* as1 = (const float*)d_in[4];
    const float* ad1 = (const float*)d_in[5];
    const float* b1  = (const float*)d_in[6];
    const float* W2  = (const float*)d_in[7];
    const float* as2 = (const float*)d_in[8];
    const float* ad2 = (const float*)d_in[9];
    const float* b2  = (const float*)d_in[10];
    const float* W3  = (const float*)d_in[11];
    const float* as3 = (const float*)d_in[12];
    const float* ad3 = (const float*)d_in[13];
    const float* b3  = (const float*)d_in[14];
    const float* Wm1 = (const float*)d_in[15];
    const float* bm1 = (const float*)d_in[16];
    const float* Wm2 = (const float*)d_in[17];
    const float* bm2 = (const float*)d_in[18];
    float* out = (float*)d_out;

    float *hin, *asrc, *adst;
    __nv_bfloat16* hwb;
    int* deg;
    cudaGetSymbolAddress((void**)&hwb,  g_hwb);
    cudaGetSymbolAddress((void**)&hin,  g_hin);
    cudaGetSymbolAddress((void**)&asrc, g_asrc);
    cudaGetSymbolAddress((void**)&adst, g_adst);
    cudaGetSymbolAddress((void**)&deg,  g_deg);

    detect_kernel<<<1, 32>>>(ei);

    // CSR build (graph identical across layers)
    cudaMemsetAsync(deg, 0, NN * sizeof(int), 0);
    hist_kernel<<<(ET + 255) / 256, 256>>>(ei);
    scan_kernel<<<1, 1024>>>();
    scatter_kernel<<<(ET + 255) / 256, 256>>>(ei);

    run_layer(x,   W1, as1, ad1, b1, 1, hwb, hin, asrc, adst);
    run_layer(hin, W2, as2, ad2, b2, 1, hwb, hin, asrc, adst);
    run_layer(hin, W3, as3, ad3, b3, 0, hwb, hin, asrc, adst);

    bounds_kernel<<<1, 128>>>(bat);
    pool_kernel<<<GG, HC>>>(hin);
    mlp1_kernel<<<GG, 256>>>(Wm1, bm1);
    mlp2_kernel<<<GG, 256>>>(Wm2, bm2, out);
}

// round 11
// speedup vs baseline: 1.7917x; 1.2064x over previous
#include <cuda_runtime.h>
#include <cuda_bf16.h>
#include <math.h>
#include <stdint.h>

// ---------------- problem constants ----------------
#define NN     40000      // nodes
#define EE     640000     // edges (before self loops)
#define ET     (EE + NN)  // edges incl self loops
#define GG     64         // graphs
#define HH     4          // heads
#define CC     64         // channels/head
#define HC     256        // H*C
#define NHID   1024
#define NOUT   768
#define NEG    0.2f

// ---------------- device scratch ----------------
__device__ __align__(16) __nv_bfloat16 g_ah [NN * HC];   // layer input, bf16 hi
__device__ __align__(16) __nv_bfloat16 g_al [NN * HC];   // layer input, bf16 lo
__device__ __align__(16) __nv_bfloat16 g_wh [HC * HC];   // W^T hi  [n][k]
__device__ __align__(16) __nv_bfloat16 g_wl [HC * HC];   // W^T lo  [n][k]
__device__ __align__(16) __nv_bfloat16 g_hwb[NN * HC];   // bf16 features for gather
__device__ __align__(16) float g_asrc[NN * HH];
__device__ __align__(16) float g_adst[NN * HH];
__device__ __align__(16) float g_p   [(size_t)ET * HH];  // edge probs, CSR order
__device__ __align__(16) float g_pool[GG * HC];
__device__ __align__(16) float g_hid [GG * NHID];
__device__ int g_deg [NN];
__device__ int g_off [NN + 1];
__device__ int g_cur [NN];
__device__ int g_csrc[ET];
__device__ int g_cdst[ET];
__device__ int g_gstart[GG + 1];
__device__ int g_str;            // 1 = int32 indices, 2 = int64 (low-word stride)

// ---------------- dtype detection ----------------
__global__ void detect_kernel(const int* __restrict__ ei) {
    if (threadIdx.x == 0 && blockIdx.x == 0) {
        int o = 0;
        #pragma unroll
        for (int k = 0; k < 16; k++) o |= ei[2 * k + 1];
        g_str = o ? 1 : 2;
    }
}

// ---------------- input split (also zeros g_deg) ----------------
__global__ void conv_x(const float* __restrict__ x) {
    size_t t = (size_t)blockIdx.x * blockDim.x + threadIdx.x;
    if (t < NN) g_deg[t] = 0;
    if (t >= (size_t)NN * HC) return;
    float v = x[t];
    __nv_bfloat16 h = __float2bfloat16(v);
    g_ah[t] = h;
    g_al[t] = __float2bfloat16(v - __bfloat162float(h));
}

// ---------------- weight split + transpose: g_wh/g_wl[n][k] = split(W[k][n])
__global__ void conv_w(const float* __restrict__ W) {
    int t = blockIdx.x * blockDim.x + threadIdx.x;
    if (t >= HC * HC) return;
    int n = t >> 8, k = t & 255;
    float v = W[k * HC + n];
    __nv_bfloat16 h = __float2bfloat16(v);
    g_wh[t] = h;
    g_wl[t] = __float2bfloat16(v - __bfloat162float(h));
}

// ---------------- CSR build ----------------
__global__ void hist_kernel(const int* __restrict__ ei) {
    int e = blockIdx.x * blockDim.x + threadIdx.x;
    if (e >= ET) return;
    const int str = g_str;
    int d = (e < EE) ? ei[((size_t)EE + e) * str] : e - EE;
    atomicAdd(&g_deg[d], 1);
}

__global__ void scan_kernel() {
    __shared__ int sums[1024];
    const int T = 1024, PER = (NN + T - 1) / T;
    int t = threadIdx.x;
    int base = t * PER;
    int s = 0;
    for (int i = 0; i < PER; i++) {
        int idx = base + i;
        if (idx < NN) s += g_deg[idx];
    }
    sums[t] = s;
    __syncthreads();
    for (int ofs = 1; ofs < T; ofs <<= 1) {
        int v = 0;
        if (t >= ofs) v = sums[t - ofs];
        __syncthreads();
        if (t >= ofs) sums[t] += v;
        __syncthreads();
    }
    int run = (t > 0) ? sums[t - 1] : 0;
    for (int i = 0; i < PER; i++) {
        int idx = base + i;
        if (idx < NN) {
            g_off[idx] = run;
            g_cur[idx] = run;
            run += g_deg[idx];
        }
    }
    if (t == T - 1) g_off[NN] = run;
}

__global__ void scatter_kernel(const int* __restrict__ ei) {
    int e = blockIdx.x * blockDim.x + threadIdx.x;
    if (e >= ET) return;
    const int str = g_str;
    int s, d;
    if (e < EE) { s = ei[(size_t)e * str]; d = ei[((size_t)EE + e) * str]; }
    else        { s = d = e - EE; }
    int pos = atomicAdd(&g_cur[d], 1);
    g_csrc[pos] = s;
    g_cdst[pos] = d;
}

// ---------------- bf16 m16n8k16 mma ----------------
__device__ __forceinline__ void mma_bf16(float* c, const uint32_t* a, const uint32_t* b) {
    asm volatile(
        "mma.sync.aligned.m16n8k16.row.col.f32.bf16.bf16.f32 "
        "{%0,%1,%2,%3}, {%4,%5,%6,%7}, {%8,%9}, {%0,%1,%2,%3};"
        : "+f"(c[0]), "+f"(c[1]), "+f"(c[2]), "+f"(c[3])
        : "r"(a[0]), "r"(a[1]), "r"(a[2]), "r"(a[3]), "r"(b[0]), "r"(b[1]));
}

// ---------------- tensor-core GEMM (double-bf16, 3-pass) --------------------
// C[M,256] = A[M,256] @ W[256,256]; A pre-split (Ah,Al), W pre-split+transposed.
// Emits bf16(C) into HB and fused attention scalars (plain stores).
#define SST 24   // smem row stride in bf16 (= 12 words: conflict-free frag loads)
__global__ __launch_bounds__(256) void gemm_tc(const __nv_bfloat16* __restrict__ Ah,
                                               const __nv_bfloat16* __restrict__ Al,
                                               __nv_bfloat16* __restrict__ HB,
                                               const float* __restrict__ a_s,
                                               const float* __restrict__ a_d,
                                               float* __restrict__ asrc,
                                               float* __restrict__ adst, int M) {
    __shared__ __align__(16) __nv_bfloat16 As_hi[128][SST], As_lo[128][SST];
    __shared__ __align__(16) __nv_bfloat16 Bs_hi[128][SST], Bs_lo[128][SST];

    const int tid = threadIdx.x;
    const int wid = tid >> 5, lane = tid & 31;
    const int wm = (wid & 3) * 32;
    const int wn = (wid >> 2) * 64;
    const int row0 = blockIdx.x * 128;
    const int col0 = blockIdx.y * 128;
    const int r = lane >> 2;
    const int c = lane & 3;

    const int srow  = tid >> 1;          // staging row 0..127
    const int shalf = (tid & 1) * 8;     // staging k offset 0 or 8

    float acc[2][8][4];
    #pragma unroll
    for (int mt = 0; mt < 2; mt++)
        #pragma unroll
        for (int nt = 0; nt < 8; nt++)
            #pragma unroll
            for (int i = 0; i < 4; i++) acc[mt][nt][i] = 0.f;

    for (int k0 = 0; k0 < HC; k0 += 16) {
        uint4 va = make_uint4(0u, 0u, 0u, 0u), vla = va;
        if (row0 + srow < M) {
            va  = *(const uint4*)(Ah + (size_t)(row0 + srow) * HC + k0 + shalf);
            vla = *(const uint4*)(Al + (size_t)(row0 + srow) * HC + k0 + shalf);
        }
        *(uint4*)&As_hi[srow][shalf] = va;
        *(uint4*)&As_lo[srow][shalf] = vla;
        *(uint4*)&Bs_hi[srow][shalf] =
            *(const uint4*)(g_wh + (size_t)(col0 + srow) * HC + k0 + shalf);
        *(uint4*)&Bs_lo[srow][shalf] =
            *(const uint4*)(g_wl + (size_t)(col0 + srow) * HC + k0 + shalf);
        __syncthreads();

        uint32_t ah[2][4], alr[2][4];
        #pragma unroll
        for (int mt = 0; mt < 2; mt++) {
            int mb = wm + mt * 16;
            ah[mt][0]  = *(const uint32_t*)&As_hi[mb + r    ][2 * c    ];
            ah[mt][1]  = *(const uint32_t*)&As_hi[mb + r + 8][2 * c    ];
            ah[mt][2]  = *(const uint32_t*)&As_hi[mb + r    ][2 * c + 8];
            ah[mt][3]  = *(const uint32_t*)&As_hi[mb + r + 8][2 * c + 8];
            alr[mt][0] = *(const uint32_t*)&As_lo[mb + r    ][2 * c    ];
            alr[mt][1] = *(const uint32_t*)&As_lo[mb + r + 8][2 * c    ];
            alr[mt][2] = *(const uint32_t*)&As_lo[mb + r    ][2 * c + 8];
            alr[mt][3] = *(const uint32_t*)&As_lo[mb + r + 8][2 * c + 8];
        }
        #pragma unroll
        for (int nt = 0; nt < 8; nt++) {
            int nb = wn + nt * 8 + r;
            uint32_t bh[2], bl[2];
            bh[0] = *(const uint32_t*)&Bs_hi[nb][2 * c    ];
            bh[1] = *(const uint32_t*)&Bs_hi[nb][2 * c + 8];
            bl[0] = *(const uint32_t*)&Bs_lo[nb][2 * c    ];
            bl[1] = *(const uint32_t*)&Bs_lo[nb][2 * c + 8];
            #pragma unroll
            for (int mt = 0; mt < 2; mt++) {
                mma_bf16(acc[mt][nt], ah[mt],  bh);
                mma_bf16(acc[mt][nt], alr[mt], bh);
                mma_bf16(acc[mt][nt], ah[mt],  bl);
            }
        }
        __syncthreads();
    }

    // ---- epilogue: bf16 store + fused attention scalars (plain stores) ----
    const int hidx = (col0 + wn) >> 6;   // this warp's head
    float ws[16], wd[16];
    #pragma unroll
    for (int nt = 0; nt < 8; nt++)
        #pragma unroll
        for (int k = 0; k < 2; k++) {
            int ccol = col0 + wn + nt * 8 + 2 * c + k;
            ws[nt * 2 + k] = a_s[ccol];
            wd[nt * 2 + k] = a_d[ccol];
        }

    #pragma unroll
    for (int mt = 0; mt < 2; mt++) {
        float ps0 = 0.f, pd0 = 0.f, ps1 = 0.f, pd1 = 0.f;
        #pragma unroll
        for (int nt = 0; nt < 8; nt++) {
            ps0 += acc[mt][nt][0] * ws[2 * nt] + acc[mt][nt][1] * ws[2 * nt + 1];
            pd0 += acc[mt][nt][0] * wd[2 * nt] + acc[mt][nt][1] * wd[2 * nt + 1];
            ps1 += acc[mt][nt][2] * ws[2 * nt] + acc[mt][nt][3] * ws[2 * nt + 1];
            pd1 += acc[mt][nt][2] * wd[2 * nt] + acc[mt][nt][3] * wd[2 * nt + 1];
        }
        ps0 += __shfl_xor_sync(0xffffffffu, ps0, 1); ps0 += __shfl_xor_sync(0xffffffffu, ps0, 2);
        pd0 += __shfl_xor_sync(0xffffffffu, pd0, 1); pd0 += __shfl_xor_sync(0xffffffffu, pd0, 2);
        ps1 += __shfl_xor_sync(0xffffffffu, ps1, 1); ps1 += __shfl_xor_sync(0xffffffffu, ps1, 2);
        pd1 += __shfl_xor_sync(0xffffffffu, pd1, 1); pd1 += __shfl_xor_sync(0xffffffffu, pd1, 2);
        int rr = row0 + wm + mt * 16 + r;
        if (c == 0) {
            if (rr < M)     { asrc[rr * HH + hidx] = ps0; adst[rr * HH + hidx] = pd0; }
            if (rr + 8 < M) { asrc[(rr + 8) * HH + hidx] = ps1; adst[(rr + 8) * HH + hidx] = pd1; }
        }
        #pragma unroll
        for (int nt = 0; nt < 8; nt++) {
            int cc = col0 + wn + nt * 8 + 2 * c;
            if (rr < M)
                *(__nv_bfloat162*)(HB + (size_t)rr * HC + cc) =
                    __floats2bfloat162_rn(acc[mt][nt][0], acc[mt][nt][1]);
            if (rr + 8 < M)
                *(__nv_bfloat162*)(HB + (size_t)(rr + 8) * HC + cc) =
                    __floats2bfloat162_rn(acc[mt][nt][2], acc[mt][nt][3]);
        }
    }
}

// ---------------- edge probabilities (CSR order, edge-parallel) -------------
__global__ void edge_p(const float* __restrict__ asrc, const float* __restrict__ adst) {
    size_t t = (size_t)blockIdx.x * blockDim.x + threadIdx.x;
    if (t >= (size_t)ET * HH) return;
    int e = (int)(t >> 2), h = (int)(t & 3);
    int s = g_csrc[e], d = g_cdst[e];
    float v = asrc[s * HH + h] + adst[d * HH + h];
    v = (v > 0.f) ? v : v * NEG;
    g_p[t] = __expf(v);
}

// ---------------- fused GAT aggregation: warp per dst node ------------------
// Writes bf16 hi/lo split of the activated output (next layer's A).
__global__ __launch_bounds__(256) void gat_agg(const __nv_bfloat16* __restrict__ hwb,
                                               const float* __restrict__ bias,
                                               __nv_bfloat16* __restrict__ oh,
                                               __nv_bfloat16* __restrict__ ol,
                                               int relu) {
    int w = (blockIdx.x * blockDim.x + threadIdx.x) >> 5;
    int lane = threadIdx.x & 31;
    if (w >= NN) return;
    const int h  = lane >> 3;
    const int c0 = lane * 8;
    const int beg = g_off[w], end = g_off[w + 1];

    float acc[8];
    #pragma unroll
    for (int i = 0; i < 8; i++) acc[i] = 0.f;
    float den = 0.f;

    int j = beg;
    for (; j + 1 < end; j += 2) {
        int s0 = g_csrc[j], s1 = g_csrc[j + 1];
        float p0 = g_p[(size_t)j * HH + h];
        float p1 = g_p[(size_t)(j + 1) * HH + h];
        den += p0 + p1;
        uint4 u0 = *(const uint4*)(hwb + (size_t)s0 * HC + c0);
        uint4 u1 = *(const uint4*)(hwb + (size_t)s1 * HC + c0);
        float2 a0 = __bfloat1622float2(*(__nv_bfloat162*)&u0.x);
        float2 a1 = __bfloat1622float2(*(__nv_bfloat162*)&u0.y);
        float2 a2 = __bfloat1622float2(*(__nv_bfloat162*)&u0.z);
        float2 a3 = __bfloat1622float2(*(__nv_bfloat162*)&u0.w);
        float2 b0 = __bfloat1622float2(*(__nv_bfloat162*)&u1.x);
        float2 b1 = __bfloat1622float2(*(__nv_bfloat162*)&u1.y);
        float2 b2 = __bfloat1622float2(*(__nv_bfloat162*)&u1.z);
        float2 b3 = __bfloat1622float2(*(__nv_bfloat162*)&u1.w);
        acc[0] = fmaf(p0, a0.x, acc[0]); acc[1] = fmaf(p0, a0.y, acc[1]);
        acc[2] = fmaf(p0, a1.x, acc[2]); acc[3] = fmaf(p0, a1.y, acc[3]);
        acc[4] = fmaf(p0, a2.x, acc[4]); acc[5] = fmaf(p0, a2.y, acc[5]);
        acc[6] = fmaf(p0, a3.x, acc[6]); acc[7] = fmaf(p0, a3.y, acc[7]);
        acc[0] = fmaf(p1, b0.x, acc[0]); acc[1] = fmaf(p1, b0.y, acc[1]);
        acc[2] = fmaf(p1, b1.x, acc[2]); acc[3] = fmaf(p1, b1.y, acc[3]);
        acc[4] = fmaf(p1, b2.x, acc[4]); acc[5] = fmaf(p1, b2.y, acc[5]);
        acc[6] = fmaf(p1, b3.x, acc[6]); acc[7] = fmaf(p1, b3.y, acc[7]);
    }
    if (j < end) {
        int s0 = g_csrc[j];
        float p0 = g_p[(size_t)j * HH + h];
        den += p0;
        uint4 u0 = *(const uint4*)(hwb + (size_t)s0 * HC + c0);
        float2 a0 = __bfloat1622float2(*(__nv_bfloat162*)&u0.x);
        float2 a1 = __bfloat1622float2(*(__nv_bfloat162*)&u0.y);
        float2 a2 = __bfloat1622float2(*(__nv_bfloat162*)&u0.z);
        float2 a3 = __bfloat1622float2(*(__nv_bfloat162*)&u0.w);
        acc[0] = fmaf(p0, a0.x, acc[0]); acc[1] = fmaf(p0, a0.y, acc[1]);
        acc[2] = fmaf(p0, a1.x, acc[2]); acc[3] = fmaf(p0, a1.y, acc[3]);
        acc[4] = fmaf(p0, a2.x, acc[4]); acc[5] = fmaf(p0, a2.y, acc[5]);
        acc[6] = fmaf(p0, a3.x, acc[6]); acc[7] = fmaf(p0, a3.y, acc[7]);
    }

    float inv = 1.f / den;
    float o[8];
    float4 bb0 = *(const float4*)(bias + c0);
    float4 bb1 = *(const float4*)(bias + c0 + 4);
    o[0] = acc[0] * inv + bb0.x; o[1] = acc[1] * inv + bb0.y;
    o[2] = acc[2] * inv + bb0.z; o[3] = acc[3] * inv + bb0.w;
    o[4] = acc[4] * inv + bb1.x; o[5] = acc[5] * inv + bb1.y;
    o[6] = acc[6] * inv + bb1.z; o[7] = acc[7] * inv + bb1.w;
    if (relu) {
        #pragma unroll
        for (int i = 0; i < 8; i++) o[i] = fmaxf(o[i], 0.f);
    }
    __nv_bfloat162 hi[4], lo[4];
    #pragma unroll
    for (int i = 0; i < 4; i++) {
        hi[i] = __floats2bfloat162_rn(o[2 * i], o[2 * i + 1]);
        float2 back = __bfloat1622float2(hi[i]);
        lo[i] = __floats2bfloat162_rn(o[2 * i] - back.x, o[2 * i + 1] - back.y);
    }
    uint4 uh, ul;
    uh.x = *(uint32_t*)&hi[0]; uh.y = *(uint32_t*)&hi[1];
    uh.z = *(uint32_t*)&hi[2]; uh.w = *(uint32_t*)&hi[3];
    ul.x = *(uint32_t*)&lo[0]; ul.y = *(uint32_t*)&lo[1];
    ul.z = *(uint32_t*)&lo[2]; ul.w = *(uint32_t*)&lo[3];
    *(uint4*)(oh + (size_t)w * HC + c0) = uh;
    *(uint4*)(ol + (size_t)w * HC + c0) = ul;
}

// ---------------- graph boundaries ----------------
__global__ void bounds_kernel(const int* __restrict__ batch) {
    int g = blockIdx.x * blockDim.x + threadIdx.x;
    if (g > GG) return;
    const int str = g_str;
    int lo = 0, hi = NN;
    while (lo < hi) {
        int mid = (lo + hi) >> 1;
        if (batch[(size_t)mid * str] < g) lo = mid + 1; else hi = mid;
    }
    g_gstart[g] = lo;
}

// ---------------- mean pool (reads hi+lo split) ----------------
__global__ void pool_kernel() {
    int g = blockIdx.x, c = threadIdx.x;
    int s = g_gstart[g], e = g_gstart[g + 1];
    float acc = 0.f;
    for (int n = s; n < e; n++) {
        size_t idx = (size_t)n * HC + c;
        acc += __bfloat162float(g_ah[idx]) + __bfloat162float(g_al[idx]);
    }
    float cnt = (float)max(e - s, 1);
    g_pool[g * HC + c] = acc / cnt;
}

// ---------------- MLP ----------------
__global__ void mlp1_kernel(const float* __restrict__ Wm1, const float* __restrict__ bm1) {
    __shared__ float row[HC];
    int g = blockIdx.x, t = threadIdx.x;
    for (int i = t; i < HC; i += blockDim.x) row[i] = g_pool[g * HC + i];
    __syncthreads();
    #pragma unroll
    for (int j = 0; j < NHID / 256; j++) {
        int o = t + j * 256;
        float acc = bm1[o];
        for (int k = 0; k < HC; k++) acc = fmaf(row[k], Wm1[(size_t)k * NHID + o], acc);
        g_hid[g * NHID + o] = fmaxf(acc, 0.f);
    }
}

__global__ void mlp2_kernel(const float* __restrict__ Wm2, const float* __restrict__ bm2,
                            float* __restrict__ out) {
    __shared__ float row[NHID];
    int g = blockIdx.x, t = threadIdx.x;
    for (int i = t; i < NHID; i += blockDim.x) row[i] = g_hid[g * NHID + i];
    __syncthreads();
    #pragma unroll
    for (int j = 0; j < NOUT / 256; j++) {
        int o = t + j * 256;
        float acc = bm2[o];
        for (int k = 0; k < NHID; k++) acc = fmaf(row[k], Wm2[(size_t)k * NOUT + o], acc);
        out[(size_t)g * NOUT + o] = acc;
    }
}

// ---------------- host orchestration ----------------
static void run_layer(const float* W, const float* as_, const float* ad_,
                      const float* b, int relu,
                      __nv_bfloat16* ah, __nv_bfloat16* al, __nv_bfloat16* hwb,
                      float* asrc, float* adst) {
    conv_w<<<(HC * HC + 255) / 256, 256>>>(W);
    dim3 ggrid((NN + 127) / 128, HC / 128);
    gemm_tc<<<ggrid, 256>>>(ah, al, hwb, as_, ad_, asrc, adst, NN);
    edge_p<<<((size_t)ET * HH + 255) / 256, 256>>>(asrc, adst);
    gat_agg<<<(NN * 32 + 255) / 256, 256>>>(hwb, b, ah, al, relu);
}

extern "C" void kernel_launch(void* const* d_in, const int* in_sizes, int n_in,
                              void* d_out, int out_size) {
    const float* x   = (const float*)d_in[0];
    const int*   ei  = (const int*)d_in[1];
    const int*   bat = (const int*)d_in[2];
    const float* W1  = (const float*)d_in[3];
    const float* as1 = (const float*)d_in[4];
    const float* ad1 = (const float*)d_in[5];
    const float* b1  = (const float*)d_in[6];
    const float* W2  = (const float*)d_in[7];
    const float* as2 = (const float*)d_in[8];
    const float* ad2 = (const float*)d_in[9];
    const float* b2  = (const float*)d_in[10];
    const float* W3  = (const float*)d_in[11];
    const float* as3 = (const float*)d_in[12];
    const float* ad3 = (const float*)d_in[13];
    const float* b3  = (const float*)d_in[14];
    const float* Wm1 = (const float*)d_in[15];
    const float* bm1 = (const float*)d_in[16];
    const float* Wm2 = (const float*)d_in[17];
    const float* bm2 = (const float*)d_in[18];
    float* out = (float*)d_out;

    float *asrc, *adst;
    __nv_bfloat16 *ah, *al, *hwb;
    cudaGetSymbolAddress((void**)&ah,   g_ah);
    cudaGetSymbolAddress((void**)&al,   g_al);
    cudaGetSymbolAddress((void**)&hwb,  g_hwb);
    cudaGetSymbolAddress((void**)&asrc, g_asrc);
    cudaGetSymbolAddress((void**)&adst, g_adst);

    detect_kernel<<<1, 32>>>(ei);
    conv_x<<<((size_t)NN * HC + 255) / 256, 256>>>(x);   // also zeros g_deg
    hist_kernel<<<(ET + 255) / 256, 256>>>(ei);
    scan_kernel<<<1, 1024>>>();
    scatter_kernel<<<(ET + 255) / 256, 256>>>(ei);

    run_layer(W1, as1, ad1, b1, 1, ah, al, hwb, asrc, adst);
    run_layer(W2, as2, ad2, b2, 1, ah, al, hwb, asrc, adst);
    run_layer(W3, as3, ad3, b3, 0, ah, al, hwb, asrc, adst);

    bounds_kernel<<<1, 128>>>(bat);
    pool_kernel<<<GG, HC>>>();
    mlp1_kernel<<<GG, 256>>>(Wm1, bm1);
    mlp2_kernel<<<GG, 256>>>(Wm2, bm2, out);
}

// round 12
// speedup vs baseline: 1.9371x; 1.0812x over previous
#include <cuda_runtime.h>
#include <cuda_bf16.h>
#include <math.h>
#include <stdint.h>

// ---------------- problem constants ----------------
#define NN     40000      // nodes
#define EE     640000     // edges (before self loops)
#define ET     (EE + NN)  // edges incl self loops
#define GG     64         // graphs
#define HH     4          // heads
#define CC     64         // channels/head
#define HC     256        // H*C
#define NHID   1024
#define NOUT   768
#define NEG    0.2f
#define NB     ((NN + 255) / 256)   // scan blocks = 157

// ---------------- device scratch ----------------
__device__ __align__(16) __nv_bfloat16 g_ah [NN * HC];   // layer input, bf16 hi
__device__ __align__(16) __nv_bfloat16 g_al [NN * HC];   // layer input, bf16 lo
__device__ __align__(16) __nv_bfloat16 g_wh [HC * HC];   // W^T hi  [n][k]
__device__ __align__(16) __nv_bfloat16 g_wl [HC * HC];   // W^T lo  [n][k]
__device__ __align__(16) __nv_bfloat16 g_hwb[NN * HC];   // bf16 features for gather
__device__ __align__(16) float g_asrc[NN * HH];
__device__ __align__(16) float g_adst[NN * HH];
__device__ __align__(16) float g_p   [(size_t)ET * HH];  // edge probs, CSR order
__device__ __align__(16) float g_pool[GG * HC];
__device__ __align__(16) float g_hid [GG * NHID];
__device__ int g_deg [NN];
__device__ int g_off [NN + 1];
__device__ int g_cur [NN];
__device__ int g_bsum[NB];
__device__ int g_bbase[NB];
__device__ int g_csrc[ET];
__device__ int g_cdst[ET];
__device__ int g_gstart[GG + 1];
__device__ int g_str;            // 1 = int32 indices, 2 = int64 (low-word stride)

// ---------------- dtype detection ----------------
__global__ void detect_kernel(const int* __restrict__ ei) {
    if (threadIdx.x == 0 && blockIdx.x == 0) {
        int o = 0;
        #pragma unroll
        for (int k = 0; k < 16; k++) o |= ei[2 * k + 1];
        g_str = o ? 1 : 2;
    }
}

// ---------------- input split (also zeros g_deg) ----------------
__global__ void conv_x(const float* __restrict__ x) {
    size_t t = (size_t)blockIdx.x * blockDim.x + threadIdx.x;
    if (t < NN) g_deg[t] = 0;
    if (t >= (size_t)NN * HC) return;
    float v = x[t];
    __nv_bfloat16 h = __float2bfloat16(v);
    g_ah[t] = h;
    g_al[t] = __float2bfloat16(v - __bfloat162float(h));
}

// ---------------- weight split + transpose: g_wh/g_wl[n][k] = split(W[k][n])
__global__ void conv_w(const float* __restrict__ W) {
    int t = blockIdx.x * blockDim.x + threadIdx.x;
    if (t >= HC * HC) return;
    int n = t >> 8, k = t & 255;
    float v = W[k * HC + n];
    __nv_bfloat16 h = __float2bfloat16(v);
    g_wh[t] = h;
    g_wl[t] = __float2bfloat16(v - __bfloat162float(h));
}

// ---------------- CSR build ----------------
__global__ void hist_kernel(const int* __restrict__ ei) {
    int e = blockIdx.x * blockDim.x + threadIdx.x;
    if (e >= ET) return;
    const int str = g_str;
    int d = (e < EE) ? ei[((size_t)EE + e) * str] : e - EE;
    atomicAdd(&g_deg[d], 1);
}

// phase 1: per-block scan of g_deg; local exclusive prefix -> g_off, block sums
__global__ void scan1_kernel() {
    __shared__ int sh[256];
    int tid = threadIdx.x;
    int i = blockIdx.x * 256 + tid;
    int v = (i < NN) ? g_deg[i] : 0;
    sh[tid] = v;
    __syncthreads();
    #pragma unroll
    for (int ofs = 1; ofs < 256; ofs <<= 1) {
        int t = 0;
        if (tid >= ofs) t = sh[tid - ofs];
        __syncthreads();
        if (tid >= ofs) sh[tid] += t;
        __syncthreads();
    }
    if (i < NN) g_off[i] = sh[tid] - v;      // local exclusive
    if (tid == 255) g_bsum[blockIdx.x] = sh[255];
}

// phase 2: scan block sums (single tiny block)
__global__ void scan2_kernel() {
    __shared__ int sh[256];
    int tid = threadIdx.x;
    int v = (tid < NB) ? g_bsum[tid] : 0;
    sh[tid] = v;
    __syncthreads();
    #pragma unroll
    for (int ofs = 1; ofs < 256; ofs <<= 1) {
        int t = 0;
        if (tid >= ofs) t = sh[tid - ofs];
        __syncthreads();
        if (tid >= ofs) sh[tid] += t;
        __syncthreads();
    }
    if (tid < NB) g_bbase[tid] = sh[tid] - v;   // exclusive
    if (tid == NB - 1) g_off[NN] = sh[tid];     // total = ET
}

// phase 3: add block bases, init cursors
__global__ void scan3_kernel() {
    int i = blockIdx.x * 256 + threadIdx.x;
    if (i >= NN) return;
    int o = g_off[i] + g_bbase[blockIdx.x];
    g_off[i] = o;
    g_cur[i] = o;
}

__global__ void scatter_kernel(const int* __restrict__ ei) {
    int e = blockIdx.x * blockDim.x + threadIdx.x;
    if (e >= ET) return;
    const int str = g_str;
    int s, d;
    if (e < EE) { s = ei[(size_t)e * str]; d = ei[((size_t)EE + e) * str]; }
    else        { s = d = e - EE; }
    int pos = atomicAdd(&g_cur[d], 1);
    g_csrc[pos] = s;
    g_cdst[pos] = d;
}

// ---------------- bf16 m16n8k16 mma ----------------
__device__ __forceinline__ void mma_bf16(float* c, const uint32_t* a, const uint32_t* b) {
    asm volatile(
        "mma.sync.aligned.m16n8k16.row.col.f32.bf16.bf16.f32 "
        "{%0,%1,%2,%3}, {%4,%5,%6,%7}, {%8,%9}, {%0,%1,%2,%3};"
        : "+f"(c[0]), "+f"(c[1]), "+f"(c[2]), "+f"(c[3])
        : "r"(a[0]), "r"(a[1]), "r"(a[2]), "r"(a[3]), "r"(b[0]), "r"(b[1]));
}

// ---------------- tensor-core GEMM (double-bf16, 3-pass, double-buffered) ---
#define SST 24   // smem row stride in bf16
__global__ __launch_bounds__(256) void gemm_tc(const __nv_bfloat16* __restrict__ Ah,
                                               const __nv_bfloat16* __restrict__ Al,
                                               __nv_bfloat16* __restrict__ HB,
                                               const float* __restrict__ a_s,
                                               const float* __restrict__ a_d,
                                               float* __restrict__ asrc,
                                               float* __restrict__ adst, int M) {
    __shared__ __align__(16) __nv_bfloat16 As_hi[2][128][SST], As_lo[2][128][SST];
    __shared__ __align__(16) __nv_bfloat16 Bs_hi[2][128][SST], Bs_lo[2][128][SST];

    const int tid = threadIdx.x;
    const int wid = tid >> 5, lane = tid & 31;
    const int wm = (wid & 3) * 32;
    const int wn = (wid >> 2) * 64;
    const int row0 = blockIdx.x * 128;
    const int col0 = blockIdx.y * 128;
    const int r = lane >> 2;
    const int c = lane & 3;

    const int srow  = tid >> 1;          // staging row 0..127
    const int shalf = (tid & 1) * 8;     // staging k offset 0 or 8
    const bool arow_ok = (row0 + srow < M);

    float acc[2][8][4];
    #pragma unroll
    for (int mt = 0; mt < 2; mt++)
        #pragma unroll
        for (int nt = 0; nt < 8; nt++)
            #pragma unroll
            for (int i = 0; i < 4; i++) acc[mt][nt][i] = 0.f;

    // prologue: stage chunk 0 into buffer 0
    uint4 va = make_uint4(0u, 0u, 0u, 0u), vla = va, vbh, vbl;
    if (arow_ok) {
        va  = *(const uint4*)(Ah + (size_t)(row0 + srow) * HC + shalf);
        vla = *(const uint4*)(Al + (size_t)(row0 + srow) * HC + shalf);
    }
    vbh = *(const uint4*)(g_wh + (size_t)(col0 + srow) * HC + shalf);
    vbl = *(const uint4*)(g_wl + (size_t)(col0 + srow) * HC + shalf);
    *(uint4*)&As_hi[0][srow][shalf] = va;
    *(uint4*)&As_lo[0][srow][shalf] = vla;
    *(uint4*)&Bs_hi[0][srow][shalf] = vbh;
    *(uint4*)&Bs_lo[0][srow][shalf] = vbl;
    __syncthreads();

    int buf = 0;
    for (int k0 = 0; k0 < HC; k0 += 16) {
        const bool more = (k0 + 16 < HC);
        if (more) {
            va = make_uint4(0u, 0u, 0u, 0u); vla = va;
            if (arow_ok) {
                va  = *(const uint4*)(Ah + (size_t)(row0 + srow) * HC + k0 + 16 + shalf);
                vla = *(const uint4*)(Al + (size_t)(row0 + srow) * HC + k0 + 16 + shalf);
            }
            vbh = *(const uint4*)(g_wh + (size_t)(col0 + srow) * HC + k0 + 16 + shalf);
            vbl = *(const uint4*)(g_wl + (size_t)(col0 + srow) * HC + k0 + 16 + shalf);
        }

        uint32_t ah[2][4], alr[2][4];
        #pragma unroll
        for (int mt = 0; mt < 2; mt++) {
            int mb = wm + mt * 16;
            ah[mt][0]  = *(const uint32_t*)&As_hi[buf][mb + r    ][2 * c    ];
            ah[mt][1]  = *(const uint32_t*)&As_hi[buf][mb + r + 8][2 * c    ];
            ah[mt][2]  = *(const uint32_t*)&As_hi[buf][mb + r    ][2 * c + 8];
            ah[mt][3]  = *(const uint32_t*)&As_hi[buf][mb + r + 8][2 * c + 8];
            alr[mt][0] = *(const uint32_t*)&As_lo[buf][mb + r    ][2 * c    ];
            alr[mt][1] = *(const uint32_t*)&As_lo[buf][mb + r + 8][2 * c    ];
            alr[mt][2] = *(const uint32_t*)&As_lo[buf][mb + r    ][2 * c + 8];
            alr[mt][3] = *(const uint32_t*)&As_lo[buf][mb + r + 8][2 * c + 8];
        }
        #pragma unroll
        for (int nt = 0; nt < 8; nt++) {
            int nb = wn + nt * 8 + r;
            uint32_t bh[2], bl[2];
            bh[0] = *(const uint32_t*)&Bs_hi[buf][nb][2 * c    ];
            bh[1] = *(const uint32_t*)&Bs_hi[buf][nb][2 * c + 8];
            bl[0] = *(const uint32_t*)&Bs_lo[buf][nb][2 * c    ];
            bl[1] = *(const uint32_t*)&Bs_lo[buf][nb][2 * c + 8];
            #pragma unroll
            for (int mt = 0; mt < 2; mt++) {
                mma_bf16(acc[mt][nt], ah[mt],  bh);
                mma_bf16(acc[mt][nt], alr[mt], bh);
                mma_bf16(acc[mt][nt], ah[mt],  bl);
            }
        }

        if (more) {
            *(uint4*)&As_hi[buf ^ 1][srow][shalf] = va;
            *(uint4*)&As_lo[buf ^ 1][srow][shalf] = vla;
            *(uint4*)&Bs_hi[buf ^ 1][srow][shalf] = vbh;
            *(uint4*)&Bs_lo[buf ^ 1][srow][shalf] = vbl;
            __syncthreads();
        }
        buf ^= 1;
    }

    // ---- epilogue: bf16 store + fused attention scalars (plain stores) ----
    const int hidx = (col0 + wn) >> 6;   // this warp's head
    float ws[16], wd[16];
    #pragma unroll
    for (int nt = 0; nt < 8; nt++)
        #pragma unroll
        for (int k = 0; k < 2; k++) {
            int ccol = col0 + wn + nt * 8 + 2 * c + k;
            ws[nt * 2 + k] = a_s[ccol];
            wd[nt * 2 + k] = a_d[ccol];
        }

    #pragma unroll
    for (int mt = 0; mt < 2; mt++) {
        float ps0 = 0.f, pd0 = 0.f, ps1 = 0.f, pd1 = 0.f;
        #pragma unroll
        for (int nt = 0; nt < 8; nt++) {
            ps0 += acc[mt][nt][0] * ws[2 * nt] + acc[mt][nt][1] * ws[2 * nt + 1];
            pd0 += acc[mt][nt][0] * wd[2 * nt] + acc[mt][nt][1] * wd[2 * nt + 1];
            ps1 += acc[mt][nt][2] * ws[2 * nt] + acc[mt][nt][3] * ws[2 * nt + 1];
            pd1 += acc[mt][nt][2] * wd[2 * nt] + acc[mt][nt][3] * wd[2 * nt + 1];
        }
        ps0 += __shfl_xor_sync(0xffffffffu, ps0, 1); ps0 += __shfl_xor_sync(0xffffffffu, ps0, 2);
        pd0 += __shfl_xor_sync(0xffffffffu, pd0, 1); pd0 += __shfl_xor_sync(0xffffffffu, pd0, 2);
        ps1 += __shfl_xor_sync(0xffffffffu, ps1, 1); ps1 += __shfl_xor_sync(0xffffffffu, ps1, 2);
        pd1 += __shfl_xor_sync(0xffffffffu, pd1, 1); pd1 += __shfl_xor_sync(0xffffffffu, pd1, 2);
        int rr = row0 + wm + mt * 16 + r;
        if (c == 0) {
            if (rr < M)     { asrc[rr * HH + hidx] = ps0; adst[rr * HH + hidx] = pd0; }
            if (rr + 8 < M) { asrc[(rr + 8) * HH + hidx] = ps1; adst[(rr + 8) * HH + hidx] = pd1; }
        }
        #pragma unroll
        for (int nt = 0; nt < 8; nt++) {
            int cc = col0 + wn + nt * 8 + 2 * c;
            if (rr < M)
                *(__nv_bfloat162*)(HB + (size_t)rr * HC + cc) =
                    __floats2bfloat162_rn(acc[mt][nt][0], acc[mt][nt][1]);
            if (rr + 8 < M)
                *(__nv_bfloat162*)(HB + (size_t)(rr + 8) * HC + cc) =
                    __floats2bfloat162_rn(acc[mt][nt][2], acc[mt][nt][3]);
        }
    }
}

// ---------------- edge probabilities (CSR order, edge-parallel) -------------
__global__ void edge_p(const float* __restrict__ asrc, const float* __restrict__ adst) {
    size_t t = (size_t)blockIdx.x * blockDim.x + threadIdx.x;
    if (t >= (size_t)ET * HH) return;
    int e = (int)(t >> 2), h = (int)(t & 3);
    int s = g_csrc[e], d = g_cdst[e];
    float v = asrc[s * HH + h] + adst[d * HH + h];
    v = (v > 0.f) ? v : v * NEG;
    g_p[t] = __expf(v);
}

// ---------------- fused GAT aggregation: warp per dst node ------------------
__global__ __launch_bounds__(256) void gat_agg(const __nv_bfloat16* __restrict__ hwb,
                                               const float* __restrict__ bias,
                                               __nv_bfloat16* __restrict__ oh,
                                               __nv_bfloat16* __restrict__ ol,
                                               int relu) {
    int w = (blockIdx.x * blockDim.x + threadIdx.x) >> 5;
    int lane = threadIdx.x & 31;
    if (w >= NN) return;
    const int h  = lane >> 3;
    const int c0 = lane * 8;
    const int beg = g_off[w], end = g_off[w + 1];

    float acc[8];
    #pragma unroll
    for (int i = 0; i < 8; i++) acc[i] = 0.f;
    float den = 0.f;

    int j = beg;
    for (; j + 1 < end; j += 2) {
        int s0 = g_csrc[j], s1 = g_csrc[j + 1];
        float p0 = g_p[(size_t)j * HH + h];
        float p1 = g_p[(size_t)(j + 1) * HH + h];
        den += p0 + p1;
        uint4 u0 = *(const uint4*)(hwb + (size_t)s0 * HC + c0);
        uint4 u1 = *(const uint4*)(hwb + (size_t)s1 * HC + c0);
        float2 a0 = __bfloat1622float2(*(__nv_bfloat162*)&u0.x);
        float2 a1 = __bfloat1622float2(*(__nv_bfloat162*)&u0.y);
        float2 a2 = __bfloat1622float2(*(__nv_bfloat162*)&u0.z);
        float2 a3 = __bfloat1622float2(*(__nv_bfloat162*)&u0.w);
        float2 b0 = __bfloat1622float2(*(__nv_bfloat162*)&u1.x);
        float2 b1 = __bfloat1622float2(*(__nv_bfloat162*)&u1.y);
        float2 b2 = __bfloat1622float2(*(__nv_bfloat162*)&u1.z);
        float2 b3 = __bfloat1622float2(*(__nv_bfloat162*)&u1.w);
        acc[0] = fmaf(p0, a0.x, acc[0]); acc[1] = fmaf(p0, a0.y, acc[1]);
        acc[2] = fmaf(p0, a1.x, acc[2]); acc[3] = fmaf(p0, a1.y, acc[3]);
        acc[4] = fmaf(p0, a2.x, acc[4]); acc[5] = fmaf(p0, a2.y, acc[5]);
        acc[6] = fmaf(p0, a3.x, acc[6]); acc[7] = fmaf(p0, a3.y, acc[7]);
        acc[0] = fmaf(p1, b0.x, acc[0]); acc[1] = fmaf(p1, b0.y, acc[1]);
        acc[2] = fmaf(p1, b1.x, acc[2]); acc[3] = fmaf(p1, b1.y, acc[3]);
        acc[4] = fmaf(p1, b2.x, acc[4]); acc[5] = fmaf(p1, b2.y, acc[5]);
        acc[6] = fmaf(p1, b3.x, acc[6]); acc[7] = fmaf(p1, b3.y, acc[7]);
    }
    if (j < end) {
        int s0 = g_csrc[j];
        float p0 = g_p[(size_t)j * HH + h];
        den += p0;
        uint4 u0 = *(const uint4*)(hwb + (size_t)s0 * HC + c0);
        float2 a0 = __bfloat1622float2(*(__nv_bfloat162*)&u0.x);
        float2 a1 = __bfloat1622float2(*(__nv_bfloat162*)&u0.y);
        float2 a2 = __bfloat1622float2(*(__nv_bfloat162*)&u0.z);
        float2 a3 = __bfloat1622float2(*(__nv_bfloat162*)&u0.w);
        acc[0] = fmaf(p0, a0.x, acc[0]); acc[1] = fmaf(p0, a0.y, acc[1]);
        acc[2] = fmaf(p0, a1.x, acc[2]); acc[3] = fmaf(p0, a1.y, acc[3]);
        acc[4] = fmaf(p0, a2.x, acc[4]); acc[5] = fmaf(p0, a2.y, acc[5]);
        acc[6] = fmaf(p0, a3.x, acc[6]); acc[7] = fmaf(p0, a3.y, acc[7]);
    }

    float inv = 1.f / den;
    float o[8];
    float4 bb0 = *(const float4*)(bias + c0);
    float4 bb1 = *(const float4*)(bias + c0 + 4);
    o[0] = acc[0] * inv + bb0.x; o[1] = acc[1] * inv + bb0.y;
    o[2] = acc[2] * inv + bb0.z; o[3] = acc[3] * inv + bb0.w;
    o[4] = acc[4] * inv + bb1.x; o[5] = acc[5] * inv + bb1.y;
    o[6] = acc[6] * inv + bb1.z; o[7] = acc[7] * inv + bb1.w;
    if (relu) {
        #pragma unroll
        for (int i = 0; i < 8; i++) o[i] = fmaxf(o[i], 0.f);
    }
    __nv_bfloat162 hi[4], lo[4];
    #pragma unroll
    for (int i = 0; i < 4; i++) {
        hi[i] = __floats2bfloat162_rn(o[2 * i], o[2 * i + 1]);
        float2 back = __bfloat1622float2(hi[i]);
        lo[i] = __floats2bfloat162_rn(o[2 * i] - back.x, o[2 * i + 1] - back.y);
    }
    uint4 uh, ul;
    uh.x = *(uint32_t*)&hi[0]; uh.y = *(uint32_t*)&hi[1];
    uh.z = *(uint32_t*)&hi[2]; uh.w = *(uint32_t*)&hi[3];
    ul.x = *(uint32_t*)&lo[0]; ul.y = *(uint32_t*)&lo[1];
    ul.z = *(uint32_t*)&lo[2]; ul.w = *(uint32_t*)&lo[3];
    *(uint4*)(oh + (size_t)w * HC + c0) = uh;
    *(uint4*)(ol + (size_t)w * HC + c0) = ul;
}

// ---------------- graph boundaries ----------------
__global__ void bounds_kernel(const int* __restrict__ batch) {
    int g = blockIdx.x * blockDim.x + threadIdx.x;
    if (g > GG) return;
    const int str = g_str;
    int lo = 0, hi = NN;
    while (lo < hi) {
        int mid = (lo + hi) >> 1;
        if (batch[(size_t)mid * str] < g) lo = mid + 1; else hi = mid;
    }
    g_gstart[g] = lo;
}

// ---------------- mean pool (reads hi+lo split) ----------------
__global__ void pool_kernel() {
    int g = blockIdx.x, c = threadIdx.x;
    int s = g_gstart[g], e = g_gstart[g + 1];
    float acc = 0.f;
    for (int n = s; n < e; n++) {
        size_t idx = (size_t)n * HC + c;
        acc += __bfloat162float(g_ah[idx]) + __bfloat162float(g_al[idx]);
    }
    float cnt = (float)max(e - s, 1);
    g_pool[g * HC + c] = acc / cnt;
}

// ---------------- MLP ----------------
__global__ void mlp1_kernel(const float* __restrict__ Wm1, const float* __restrict__ bm1) {
    __shared__ float row[HC];
    int g = blockIdx.x, t = threadIdx.x;
    for (int i = t; i < HC; i += blockDim.x) row[i] = g_pool[g * HC + i];
    __syncthreads();
    #pragma unroll
    for (int j = 0; j < NHID / 256; j++) {
        int o = t + j * 256;
        float acc = bm1[o];
        for (int k = 0; k < HC; k++) acc = fmaf(row[k], Wm1[(size_t)k * NHID + o], acc);
        g_hid[g * NHID + o] = fmaxf(acc, 0.f);
    }
}

__global__ void mlp2_kernel(const float* __restrict__ Wm2, const float* __restrict__ bm2,
                            float* __restrict__ out) {
    __shared__ float row[NHID];
    int g = blockIdx.x, t = threadIdx.x;
    for (int i = t; i < NHID; i += blockDim.x) row[i] = g_hid[g * NHID + i];
    __syncthreads();
    #pragma unroll
    for (int j = 0; j < NOUT / 256; j++) {
        int o = t + j * 256;
        float acc = bm2[o];
        for (int k = 0; k < NHID; k++) acc = fmaf(row[k], Wm2[(size_t)k * NOUT + o], acc);
        out[(size_t)g * NOUT + o] = acc;
    }
}

// ---------------- host orchestration ----------------
static void run_layer(const float* W, const float* as_, const float* ad_,
                      const float* b, int relu,
                      __nv_bfloat16* ah, __nv_bfloat16* al, __nv_bfloat16* hwb,
                      float* asrc, float* adst) {
    conv_w<<<(HC * HC + 255) / 256, 256>>>(W);
    dim3 ggrid((NN + 127) / 128, HC / 128);
    gemm_tc<<<ggrid, 256>>>(ah, al, hwb, as_, ad_, asrc, adst, NN);
    edge_p<<<((size_t)ET * HH + 255) / 256, 256>>>(asrc, adst);
    gat_agg<<<(NN * 32 + 255) / 256, 256>>>(hwb, b, ah, al, relu);
}

extern "C" void kernel_launch(void* const* d_in, const int* in_sizes, int n_in,
                              void* d_out, int out_size) {
    const float* x   = (const float*)d_in[0];
    const int*   ei  = (const int*)d_in[1];
    const int*   bat = (const int*)d_in[2];
    const float* W1  = (const float*)d_in[3];
    const float* as1 = (const float*)d_in[4];
    const float* ad1 = (const float*)d_in[5];
    const float* b1  = (const float*)d_in[6];
    const float* W2  = (const float*)d_in[7];
    const float* as2 = (const float*)d_in[8];
    const float* ad2 = (const float*)d_in[9];
    const float* b2  = (const float*)d_in[10];
    const float* W3  = (const float*)d_in[11];
    const float* as3 = (const float*)d_in[12];
    const float* ad3 = (const float*)d_in[13];
    const float* b3  = (const float*)d_in[14];
    const float* Wm1 = (const float*)d_in[15];
    const float* bm1 = (const float*)d_in[16];
    const float* Wm2 = (const float*)d_in[17];
    const float* bm2 = (const float*)d_in[18];
    float* out = (float*)d_out;

    float *asrc, *adst;
    __nv_bfloat16 *ah, *al, *hwb;
    cudaGetSymbolAddress((void**)&ah,   g_ah);
    cudaGetSymbolAddress((void**)&al,   g_al);
    cudaGetSymbolAddress((void**)&hwb,  g_hwb);
    cudaGetSymbolAddress((void**)&asrc, g_asrc);
    cudaGetSymbolAddress((void**)&adst, g_adst);

    detect_kernel<<<1, 32>>>(ei);
    conv_x<<<((size_t)NN * HC + 255) / 256, 256>>>(x);   // also zeros g_deg
    hist_kernel<<<(ET + 255) / 256, 256>>>(ei);
    scan1_kernel<<<NB, 256>>>();
    scan2_kernel<<<1, 256>>>();
    scan3_kernel<<<NB, 256>>>();
    scatter_kernel<<<(ET + 255) / 256, 256>>>(ei);

    run_layer(W1, as1, ad1, b1, 1, ah, al, hwb, asrc, adst);
    run_layer(W2, as2, ad2, b2, 1, ah, al, hwb, asrc, adst);
    run_layer(W3, as3, ad3, b3, 0, ah, al, hwb, asrc, adst);

    bounds_kernel<<<1, 128>>>(bat);
    pool_kernel<<<GG, HC>>>();
    mlp1_kernel<<<GG, 256>>>(Wm1, bm1);
    mlp2_kernel<<<GG, 256>>>(Wm2, bm2, out);
}

// round 13
// speedup vs baseline: 2.0563x; 1.0615x over previous
#include <cuda_runtime.h>
#include <cuda_bf16.h>
#include <math.h>
#include <stdint.h>

// ---------------- problem constants ----------------
#define NN     40000
#define EE     640000
#define ET     (EE + NN)
#define GG     64
#define HH     4
#define CC     64
#define HC     256
#define NHID   1024
#define NOUT   768
#define NEG    0.2f
#define NB     ((NN + 255) / 256)

// ---------------- device scratch ----------------
__device__ __align__(16) __nv_bfloat16 g_ah [NN * HC];
__device__ __align__(16) __nv_bfloat16 g_al [NN * HC];
__device__ __align__(16) __nv_bfloat16 g_wh [HC * HC];
__device__ __align__(16) __nv_bfloat16 g_wl [HC * HC];
__device__ __align__(16) __nv_bfloat16 g_hwb[NN * HC];
__device__ __align__(16) float g_asrc[NN * HH];
__device__ __align__(16) float g_adst[NN * HH];
__device__ __align__(16) float g_p   [(size_t)ET * HH];
__device__ __align__(16) float g_pool[GG * HC];
__device__ __align__(16) float g_hid [GG * NHID];
__device__ int g_deg [NN];
__device__ int g_off [NN + 1];
__device__ int g_cur [NN];
__device__ int g_bsum[NB];
__device__ int g_bbase[NB];
__device__ int g_csrc[ET];
__device__ int g_cdst[ET];
__device__ int g_gstart[GG + 1];
__device__ int g_str;

// ---------------- dtype detection ----------------
__global__ void detect_kernel(const int* __restrict__ ei) {
    if (threadIdx.x == 0 && blockIdx.x == 0) {
        int o = 0;
        #pragma unroll
        for (int k = 0; k < 16; k++) o |= ei[2 * k + 1];
        g_str = o ? 1 : 2;
    }
}

// ---------------- input split (also zeros g_deg) ----------------
__global__ void conv_x(const float* __restrict__ x) {
    size_t t = (size_t)blockIdx.x * blockDim.x + threadIdx.x;
    if (t < NN) g_deg[t] = 0;
    if (t >= (size_t)NN * HC) return;
    float v = x[t];
    __nv_bfloat16 h = __float2bfloat16(v);
    g_ah[t] = h;
    g_al[t] = __float2bfloat16(v - __bfloat162float(h));
}

// ---------------- weight split + transpose ----------------
__global__ void conv_w(const float* __restrict__ W) {
    int t = blockIdx.x * blockDim.x + threadIdx.x;
    if (t >= HC * HC) return;
    int n = t >> 8, k = t & 255;
    float v = W[k * HC + n];
    __nv_bfloat16 h = __float2bfloat16(v);
    g_wh[t] = h;
    g_wl[t] = __float2bfloat16(v - __bfloat162float(h));
}

// ---------------- CSR build ----------------
__global__ void hist_kernel(const int* __restrict__ ei) {
    int e = blockIdx.x * blockDim.x + threadIdx.x;
    if (e >= ET) return;
    const int str = g_str;
    int d = (e < EE) ? ei[((size_t)EE + e) * str] : e - EE;
    atomicAdd(&g_deg[d], 1);
}

__global__ void scan1_kernel() {
    __shared__ int sh[256];
    int tid = threadIdx.x;
    int i = blockIdx.x * 256 + tid;
    int v = (i < NN) ? g_deg[i] : 0;
    sh[tid] = v;
    __syncthreads();
    #pragma unroll
    for (int ofs = 1; ofs < 256; ofs <<= 1) {
        int t = 0;
        if (tid >= ofs) t = sh[tid - ofs];
        __syncthreads();
        if (tid >= ofs) sh[tid] += t;
        __syncthreads();
    }
    if (i < NN) g_off[i] = sh[tid] - v;
    if (tid == 255) g_bsum[blockIdx.x] = sh[255];
}

__global__ void scan2_kernel() {
    __shared__ int sh[256];
    int tid = threadIdx.x;
    int v = (tid < NB) ? g_bsum[tid] : 0;
    sh[tid] = v;
    __syncthreads();
    #pragma unroll
    for (int ofs = 1; ofs < 256; ofs <<= 1) {
        int t = 0;
        if (tid >= ofs) t = sh[tid - ofs];
        __syncthreads();
        if (tid >= ofs) sh[tid] += t;
        __syncthreads();
    }
    if (tid < NB) g_bbase[tid] = sh[tid] - v;
    if (tid == NB - 1) g_off[NN] = sh[tid];
}

__global__ void scan3_kernel() {
    int i = blockIdx.x * 256 + threadIdx.x;
    if (i >= NN) return;
    int o = g_off[i] + g_bbase[blockIdx.x];
    g_off[i] = o;
    g_cur[i] = o;
}

__global__ void scatter_kernel(const int* __restrict__ ei) {
    int e = blockIdx.x * blockDim.x + threadIdx.x;
    if (e >= ET) return;
    const int str = g_str;
    int s, d;
    if (e < EE) { s = ei[(size_t)e * str]; d = ei[((size_t)EE + e) * str]; }
    else        { s = d = e - EE; }
    int pos = atomicAdd(&g_cur[d], 1);
    g_csrc[pos] = s;
    g_cdst[pos] = d;
}

// ---------------- bf16 m16n8k16 mma ----------------
__device__ __forceinline__ void mma_bf16(float* c, const uint32_t* a, const uint32_t* b) {
    asm volatile(
        "mma.sync.aligned.m16n8k16.row.col.f32.bf16.bf16.f32 "
        "{%0,%1,%2,%3}, {%4,%5,%6,%7}, {%8,%9}, {%0,%1,%2,%3};"
        : "+f"(c[0]), "+f"(c[1]), "+f"(c[2]), "+f"(c[3])
        : "r"(a[0]), "r"(a[1]), "r"(a[2]), "r"(a[3]), "r"(b[0]), "r"(b[1]));
}

// ---------------- tensor-core GEMM (double-bf16, 3-pass, double-buffered) ---
#define SST 24
__global__ __launch_bounds__(256) void gemm_tc(const __nv_bfloat16* __restrict__ Ah,
                                               const __nv_bfloat16* __restrict__ Al,
                                               __nv_bfloat16* __restrict__ HB,
                                               const float* __restrict__ a_s,
                                               const float* __restrict__ a_d,
                                               float* __restrict__ asrc,
                                               float* __restrict__ adst, int M) {
    __shared__ __align__(16) __nv_bfloat16 As_hi[2][128][SST], As_lo[2][128][SST];
    __shared__ __align__(16) __nv_bfloat16 Bs_hi[2][128][SST], Bs_lo[2][128][SST];

    const int tid = threadIdx.x;
    const int wid = tid >> 5, lane = tid & 31;
    const int wm = (wid & 3) * 32;
    const int wn = (wid >> 2) * 64;
    const int row0 = blockIdx.x * 128;
    const int col0 = blockIdx.y * 128;
    const int r = lane >> 2;
    const int c = lane & 3;

    const int srow  = tid >> 1;
    const int shalf = (tid & 1) * 8;
    const bool arow_ok = (row0 + srow < M);

    float acc[2][8][4];
    #pragma unroll
    for (int mt = 0; mt < 2; mt++)
        #pragma unroll
        for (int nt = 0; nt < 8; nt++)
            #pragma unroll
            for (int i = 0; i < 4; i++) acc[mt][nt][i] = 0.f;

    uint4 va = make_uint4(0u, 0u, 0u, 0u), vla = va, vbh, vbl;
    if (arow_ok) {
        va  = *(const uint4*)(Ah + (size_t)(row0 + srow) * HC + shalf);
        vla = *(const uint4*)(Al + (size_t)(row0 + srow) * HC + shalf);
    }
    vbh = *(const uint4*)(g_wh + (size_t)(col0 + srow) * HC + shalf);
    vbl = *(const uint4*)(g_wl + (size_t)(col0 + srow) * HC + shalf);
    *(uint4*)&As_hi[0][srow][shalf] = va;
    *(uint4*)&As_lo[0][srow][shalf] = vla;
    *(uint4*)&Bs_hi[0][srow][shalf] = vbh;
    *(uint4*)&Bs_lo[0][srow][shalf] = vbl;
    __syncthreads();

    int buf = 0;
    for (int k0 = 0; k0 < HC; k0 += 16) {
        const bool more = (k0 + 16 < HC);
        if (more) {
            va = make_uint4(0u, 0u, 0u, 0u); vla = va;
            if (arow_ok) {
                va  = *(const uint4*)(Ah + (size_t)(row0 + srow) * HC + k0 + 16 + shalf);
                vla = *(const uint4*)(Al + (size_t)(row0 + srow) * HC + k0 + 16 + shalf);
            }
            vbh = *(const uint4*)(g_wh + (size_t)(col0 + srow) * HC + k0 + 16 + shalf);
            vbl = *(const uint4*)(g_wl + (size_t)(col0 + srow) * HC + k0 + 16 + shalf);
        }

        uint32_t ah[2][4], alr[2][4];
        #pragma unroll
        for (int mt = 0; mt < 2; mt++) {
            int mb = wm + mt * 16;
            ah[mt][0]  = *(const uint32_t*)&As_hi[buf][mb + r    ][2 * c    ];
            ah[mt][1]  = *(const uint32_t*)&As_hi[buf][mb + r + 8][2 * c    ];
            ah[mt][2]  = *(const uint32_t*)&As_hi[buf][mb + r    ][2 * c + 8];
            ah[mt][3]  = *(const uint32_t*)&As_hi[buf][mb + r + 8][2 * c + 8];
            alr[mt][0] = *(const uint32_t*)&As_lo[buf][mb + r    ][2 * c    ];
            alr[mt][1] = *(const uint32_t*)&As_lo[buf][mb + r + 8][2 * c    ];
            alr[mt][2] = *(const uint32_t*)&As_lo[buf][mb + r    ][2 * c + 8];
            alr[mt][3] = *(const uint32_t*)&As_lo[buf][mb + r + 8][2 * c + 8];
        }
        #pragma unroll
        for (int nt = 0; nt < 8; nt++) {
            int nb = wn + nt * 8 + r;
            uint32_t bh[2], bl[2];
            bh[0] = *(const uint32_t*)&Bs_hi[buf][nb][2 * c    ];
            bh[1] = *(const uint32_t*)&Bs_hi[buf][nb][2 * c + 8];
            bl[0] = *(const uint32_t*)&Bs_lo[buf][nb][2 * c    ];
            bl[1] = *(const uint32_t*)&Bs_lo[buf][nb][2 * c + 8];
            #pragma unroll
            for (int mt = 0; mt < 2; mt++) {
                mma_bf16(acc[mt][nt], ah[mt],  bh);
                mma_bf16(acc[mt][nt], alr[mt], bh);
                mma_bf16(acc[mt][nt], ah[mt],  bl);
            }
        }

        if (more) {
            *(uint4*)&As_hi[buf ^ 1][srow][shalf] = va;
            *(uint4*)&As_lo[buf ^ 1][srow][shalf] = vla;
            *(uint4*)&Bs_hi[buf ^ 1][srow][shalf] = vbh;
            *(uint4*)&Bs_lo[buf ^ 1][srow][shalf] = vbl;
            __syncthreads();
        }
        buf ^= 1;
    }

    // ---- epilogue ----
    const int hidx = (col0 + wn) >> 6;
    float ws[16], wd[16];
    #pragma unroll
    for (int nt = 0; nt < 8; nt++)
        #pragma unroll
        for (int k = 0; k < 2; k++) {
            int ccol = col0 + wn + nt * 8 + 2 * c + k;
            ws[nt * 2 + k] = a_s[ccol];
            wd[nt * 2 + k] = a_d[ccol];
        }

    #pragma unroll
    for (int mt = 0; mt < 2; mt++) {
        float ps0 = 0.f, pd0 = 0.f, ps1 = 0.f, pd1 = 0.f;
        #pragma unroll
        for (int nt = 0; nt < 8; nt++) {
            ps0 += acc[mt][nt][0] * ws[2 * nt] + acc[mt][nt][1] * ws[2 * nt + 1];
            pd0 += acc[mt][nt][0] * wd[2 * nt] + acc[mt][nt][1] * wd[2 * nt + 1];
            ps1 += acc[mt][nt][2] * ws[2 * nt] + acc[mt][nt][3] * ws[2 * nt + 1];
            pd1 += acc[mt][nt][2] * wd[2 * nt] + acc[mt][nt][3] * wd[2 * nt + 1];
        }
        ps0 += __shfl_xor_sync(0xffffffffu, ps0, 1); ps0 += __shfl_xor_sync(0xffffffffu, ps0, 2);
        pd0 += __shfl_xor_sync(0xffffffffu, pd0, 1); pd0 += __shfl_xor_sync(0xffffffffu, pd0, 2);
        ps1 += __shfl_xor_sync(0xffffffffu, ps1, 1); ps1 += __shfl_xor_sync(0xffffffffu, ps1, 2);
        pd1 += __shfl_xor_sync(0xffffffffu, pd1, 1); pd1 += __shfl_xor_sync(0xffffffffu, pd1, 2);
        int rr = row0 + wm + mt * 16 + r;
        if (c == 0) {
            if (rr < M)     { asrc[rr * HH + hidx] = ps0; adst[rr * HH + hidx] = pd0; }
            if (rr + 8 < M) { asrc[(rr + 8) * HH + hidx] = ps1; adst[(rr + 8) * HH + hidx] = pd1; }
        }
        #pragma unroll
        for (int nt = 0; nt < 8; nt++) {
            int cc = col0 + wn + nt * 8 + 2 * c;
            if (rr < M)
                *(__nv_bfloat162*)(HB + (size_t)rr * HC + cc) =
                    __floats2bfloat162_rn(acc[mt][nt][0], acc[mt][nt][1]);
            if (rr + 8 < M)
                *(__nv_bfloat162*)(HB + (size_t)(rr + 8) * HC + cc) =
                    __floats2bfloat162_rn(acc[mt][nt][2], acc[mt][nt][3]);
        }
    }
}

// ---------------- edge probabilities ----------------
__global__ void edge_p(const float* __restrict__ asrc, const float* __restrict__ adst) {
    size_t t = (size_t)blockIdx.x * blockDim.x + threadIdx.x;
    if (t >= (size_t)ET * HH) return;
    int e = (int)(t >> 2), h = (int)(t & 3);
    int s = g_csrc[e], d = g_cdst[e];
    float v = asrc[s * HH + h] + adst[d * HH + h];
    v = (v > 0.f) ? v : v * NEG;
    g_p[t] = __expf(v);
}

// ---------------- fused GAT aggregation (4-edge unroll) ---------------------
__device__ __forceinline__ void agg_one(float* acc, float& den, float p, const uint4& u) {
    den += p;
    float2 a0 = __bfloat1622float2(*(__nv_bfloat162*)&u.x);
    float2 a1 = __bfloat1622float2(*(__nv_bfloat162*)&u.y);
    float2 a2 = __bfloat1622float2(*(__nv_bfloat162*)&u.z);
    float2 a3 = __bfloat1622float2(*(__nv_bfloat162*)&u.w);
    acc[0] = fmaf(p, a0.x, acc[0]); acc[1] = fmaf(p, a0.y, acc[1]);
    acc[2] = fmaf(p, a1.x, acc[2]); acc[3] = fmaf(p, a1.y, acc[3]);
    acc[4] = fmaf(p, a2.x, acc[4]); acc[5] = fmaf(p, a2.y, acc[5]);
    acc[6] = fmaf(p, a3.x, acc[6]); acc[7] = fmaf(p, a3.y, acc[7]);
}

__global__ __launch_bounds__(256) void gat_agg(const __nv_bfloat16* __restrict__ hwb,
                                               const float* __restrict__ bias,
                                               __nv_bfloat16* __restrict__ oh,
                                               __nv_bfloat16* __restrict__ ol,
                                               int relu) {
    int w = (blockIdx.x * blockDim.x + threadIdx.x) >> 5;
    int lane = threadIdx.x & 31;
    if (w >= NN) return;
    const int h  = lane >> 3;
    const int c0 = lane * 8;
    const int beg = g_off[w], end = g_off[w + 1];

    float acc[8];
    #pragma unroll
    for (int i = 0; i < 8; i++) acc[i] = 0.f;
    float den = 0.f;

    int j = beg;
    for (; j + 3 < end; j += 4) {
        int s0 = g_csrc[j], s1 = g_csrc[j + 1], s2 = g_csrc[j + 2], s3 = g_csrc[j + 3];
        float p0 = g_p[(size_t)j * HH + h];
        float p1 = g_p[(size_t)(j + 1) * HH + h];
        float p2 = g_p[(size_t)(j + 2) * HH + h];
        float p3 = g_p[(size_t)(j + 3) * HH + h];
        uint4 u0 = *(const uint4*)(hwb + (size_t)s0 * HC + c0);
        uint4 u1 = *(const uint4*)(hwb + (size_t)s1 * HC + c0);
        uint4 u2 = *(const uint4*)(hwb + (size_t)s2 * HC + c0);
        uint4 u3 = *(const uint4*)(hwb + (size_t)s3 * HC + c0);
        agg_one(acc, den, p0, u0);
        agg_one(acc, den, p1, u1);
        agg_one(acc, den, p2, u2);
        agg_one(acc, den, p3, u3);
    }
    for (; j < end; j++) {
        int s0 = g_csrc[j];
        float p0 = g_p[(size_t)j * HH + h];
        uint4 u0 = *(const uint4*)(hwb + (size_t)s0 * HC + c0);
        agg_one(acc, den, p0, u0);
    }

    float inv = 1.f / den;
    float o[8];
    float4 bb0 = *(const float4*)(bias + c0);
    float4 bb1 = *(const float4*)(bias + c0 + 4);
    o[0] = acc[0] * inv + bb0.x; o[1] = acc[1] * inv + bb0.y;
    o[2] = acc[2] * inv + bb0.z; o[3] = acc[3] * inv + bb0.w;
    o[4] = acc[4] * inv + bb1.x; o[5] = acc[5] * inv + bb1.y;
    o[6] = acc[6] * inv + bb1.z; o[7] = acc[7] * inv + bb1.w;
    if (relu) {
        #pragma unroll
        for (int i = 0; i < 8; i++) o[i] = fmaxf(o[i], 0.f);
    }
    __nv_bfloat162 hi[4], lo[4];
    #pragma unroll
    for (int i = 0; i < 4; i++) {
        hi[i] = __floats2bfloat162_rn(o[2 * i], o[2 * i + 1]);
        float2 back = __bfloat1622float2(hi[i]);
        lo[i] = __floats2bfloat162_rn(o[2 * i] - back.x, o[2 * i + 1] - back.y);
    }
    uint4 uh, ul;
    uh.x = *(uint32_t*)&hi[0]; uh.y = *(uint32_t*)&hi[1];
    uh.z = *(uint32_t*)&hi[2]; uh.w = *(uint32_t*)&hi[3];
    ul.x = *(uint32_t*)&lo[0]; ul.y = *(uint32_t*)&lo[1];
    ul.z = *(uint32_t*)&lo[2]; ul.w = *(uint32_t*)&lo[3];
    *(uint4*)(oh + (size_t)w * HC + c0) = uh;
    *(uint4*)(ol + (size_t)w * HC + c0) = ul;
}

// ---------------- graph boundaries ----------------
__global__ void bounds_kernel(const int* __restrict__ batch) {
    int g = blockIdx.x * blockDim.x + threadIdx.x;
    if (g > GG) return;
    const int str = g_str;
    int lo = 0, hi = NN;
    while (lo < hi) {
        int mid = (lo + hi) >> 1;
        if (batch[(size_t)mid * str] < g) lo = mid + 1; else hi = mid;
    }
    g_gstart[g] = lo;
}

// ---------------- mean pool: (graph, slice) grid, partial atomics -----------
#define PSL 8   // node slices per graph
__global__ void pool_kernel() {
    int g = blockIdx.x, sl = blockIdx.y, c = threadIdx.x;
    int s = g_gstart[g], e = g_gstart[g + 1];
    float acc = 0.f;
    for (int n = s + sl; n < e; n += PSL) {
        size_t idx = (size_t)n * HC + c;
        acc += __bfloat162float(g_ah[idx]) + __bfloat162float(g_al[idx]);
    }
    atomicAdd(&g_pool[g * HC + c], acc);
}

__global__ void pool_div() {
    int t = blockIdx.x * blockDim.x + threadIdx.x;
    if (t >= GG * HC) return;
    int g = t >> 8;
    float cnt = (float)max(g_gstart[g + 1] - g_gstart[g], 1);
    g_pool[t] /= cnt;
}

// ---------------- MLP ----------------
__global__ void mlp1_kernel(const float* __restrict__ Wm1, const float* __restrict__ bm1) {
    __shared__ float row[HC];
    int g = blockIdx.x, t = threadIdx.x;
    for (int i = t; i < HC; i += blockDim.x) row[i] = g_pool[g * HC + i];
    __syncthreads();
    #pragma unroll
    for (int j = 0; j < NHID / 256; j++) {
        int o = t + j * 256;
        float acc = bm1[o];
        for (int k = 0; k < HC; k++) acc = fmaf(row[k], Wm1[(size_t)k * NHID + o], acc);
        g_hid[g * NHID + o] = fmaxf(acc, 0.f);
    }
}

__global__ void mlp2_kernel(const float* __restrict__ Wm2, const float* __restrict__ bm2,
                            float* __restrict__ out) {
    __shared__ float row[NHID];
    int g = blockIdx.x, t = threadIdx.x;
    for (int i = t; i < NHID; i += blockDim.x) row[i] = g_hid[g * NHID + i];
    __syncthreads();
    #pragma unroll
    for (int j = 0; j < NOUT / 256; j++) {
        int o = t + j * 256;
        float acc = bm2[o];
        for (int k = 0; k < NHID; k++) acc = fmaf(row[k], Wm2[(size_t)k * NOUT + o], acc);
        out[(size_t)g * NOUT + o] = acc;
    }
}

// ---------------- host orchestration ----------------
extern "C" void kernel_launch(void* const* d_in, const int* in_sizes, int n_in,
                              void* d_out, int out_size) {
    const float* x   = (const float*)d_in[0];
    const int*   ei  = (const int*)d_in[1];
    const int*   bat = (const int*)d_in[2];
    const float* W1  = (const float*)d_in[3];
    const float* as1 = (const float*)d_in[4];
    const float* ad1 = (const float*)d_in[5];
    const float* b1  = (const float*)d_in[6];
    const float* W2  = (const float*)d_in[7];
    const float* as2 = (const float*)d_in[8];
    const float* ad2 = (const float*)d_in[9];
    const float* b2  = (const float*)d_in[10];
    const float* W3  = (const float*)d_in[11];
    const float* as3 = (const float*)d_in[12];
    const float* ad3 = (const float*)d_in[13];
    const float* b3  = (const float*)d_in[14];
    const float* Wm1 = (const float*)d_in[15];
    const float* bm1 = (const float*)d_in[16];
    const float* Wm2 = (const float*)d_in[17];
    const float* bm2 = (const float*)d_in[18];
    float* out = (float*)d_out;

    float *asrc, *adst, *poolp;
    __nv_bfloat16 *ah, *al, *hwb;
    cudaGetSymbolAddress((void**)&ah,    g_ah);
    cudaGetSymbolAddress((void**)&al,    g_al);
    cudaGetSymbolAddress((void**)&hwb,   g_hwb);
    cudaGetSymbolAddress((void**)&asrc,  g_asrc);
    cudaGetSymbolAddress((void**)&adst,  g_adst);
    cudaGetSymbolAddress((void**)&poolp, g_pool);

    dim3 ggrid((NN + 127) / 128, HC / 128);

    // --- layer-1 GEMM early so ncu's -s 5 window samples gemm_tc ---
    detect_kernel<<<1, 32>>>(ei);                                   // 0
    conv_x<<<((size_t)NN * HC + 255) / 256, 256>>>(x);              // 1 (zeros g_deg)
    conv_w<<<(HC * HC + 255) / 256, 256>>>(W1);                     // 2
    gemm_tc<<<ggrid, 256>>>(ah, al, hwb, as1, ad1, asrc, adst, NN); // 3
    // --- CSR build (independent of GEMM result) ---
    hist_kernel<<<(ET + 255) / 256, 256>>>(ei);                     // 4
    scan1_kernel<<<NB, 256>>>();                                    // 5
    scan2_kernel<<<1, 256>>>();
    scan3_kernel<<<NB, 256>>>();
    scatter_kernel<<<(ET + 255) / 256, 256>>>(ei);
    // --- layer 1 edge phase ---
    edge_p<<<((size_t)ET * HH + 255) / 256, 256>>>(asrc, adst);
    gat_agg<<<(NN * 32 + 255) / 256, 256>>>(hwb, b1, ah, al, 1);
    // --- layer 2 ---
    conv_w<<<(HC * HC + 255) / 256, 256>>>(W2);
    gemm_tc<<<ggrid, 256>>>(ah, al, hwb, as2, ad2, asrc, adst, NN);
    edge_p<<<((size_t)ET * HH + 255) / 256, 256>>>(asrc, adst);
    gat_agg<<<(NN * 32 + 255) / 256, 256>>>(hwb, b2, ah, al, 1);
    // --- layer 3 ---
    conv_w<<<(HC * HC + 255) / 256, 256>>>(W3);
    gemm_tc<<<ggrid, 256>>>(ah, al, hwb, as3, ad3, asrc, adst, NN);
    edge_p<<<((size_t)ET * HH + 255) / 256, 256>>>(asrc, adst);
    gat_agg<<<(NN * 32 + 255) / 256, 256>>>(hwb, b3, ah, al, 0);
    // --- pool + MLP ---
    bounds_kernel<<<1, 128>>>(bat);
    cudaMemsetAsync(poolp, 0, GG * HC * sizeof(float), 0);
    pool_kernel<<<dim3(GG, PSL), HC>>>();
    pool_div<<<(GG * HC + 255) / 256, 256>>>();
    mlp1_kernel<<<GG, 256>>>(Wm1, bm1);
    mlp2_kernel<<<GG, 256>>>(Wm2, bm2, out);
}

// round 15
// speedup vs baseline: 2.0626x; 1.0030x over previous
#include <cuda_runtime.h>
#include <cuda_bf16.h>
#include <math.h>
#include <stdint.h>

// ---------------- problem constants ----------------
#define NN     40000
#define EE     640000
#define ET     (EE + NN)
#define GG     64
#define HH     4
#define CC     64
#define HC     256
#define NHID   1024
#define NOUT   768
#define NEG    0.2f
#define NB     ((NN + 255) / 256)

// ---------------- device scratch ----------------
__device__ __align__(16) __nv_bfloat16 g_ah [NN * HC];
__device__ __align__(16) __nv_bfloat16 g_al [NN * HC];
__device__ __align__(16) __nv_bfloat16 g_wh [HC * HC];
__device__ __align__(16) __nv_bfloat16 g_wl [HC * HC];
__device__ __align__(16) __nv_bfloat16 g_hwb[NN * HC];
__device__ __align__(16) float g_asrc[NN * HH];
__device__ __align__(16) float g_adst[NN * HH];
__device__ __align__(16) float g_p   [(size_t)ET * HH];
__device__ __align__(16) float g_pool[GG * HC];
__device__ __align__(16) float g_hid [GG * NHID];
__device__ int g_deg [NN];
__device__ int g_off [NN + 1];
__device__ int g_cur [NN];
__device__ int g_bsum[NB];
__device__ int g_bbase[NB];
__device__ int g_csrc[ET];
__device__ int g_cdst[ET];
__device__ int g_gstart[GG + 1];
__device__ int g_str;

// ---------------- dtype detection ----------------
__global__ void detect_kernel(const int* __restrict__ ei) {
    if (threadIdx.x == 0 && blockIdx.x == 0) {
        int o = 0;
        #pragma unroll
        for (int k = 0; k < 16; k++) o |= ei[2 * k + 1];
        g_str = o ? 1 : 2;
    }
}

// ---------------- input split (also zeros g_deg) ----------------
__global__ void conv_x(const float* __restrict__ x) {
    size_t t = (size_t)blockIdx.x * blockDim.x + threadIdx.x;
    if (t < NN) g_deg[t] = 0;
    if (t >= (size_t)NN * HC) return;
    float v = x[t];
    __nv_bfloat16 h = __float2bfloat16(v);
    g_ah[t] = h;
    g_al[t] = __float2bfloat16(v - __bfloat162float(h));
}

// ---------------- weight split + transpose ----------------
__global__ void conv_w(const float* __restrict__ W) {
    int t = blockIdx.x * blockDim.x + threadIdx.x;
    if (t >= HC * HC) return;
    int n = t >> 8, k = t & 255;
    float v = W[k * HC + n];
    __nv_bfloat16 h = __float2bfloat16(v);
    g_wh[t] = h;
    g_wl[t] = __float2bfloat16(v - __bfloat162float(h));
}

// ---------------- CSR build ----------------
__global__ void hist_kernel(const int* __restrict__ ei) {
    int e = blockIdx.x * blockDim.x + threadIdx.x;
    if (e >= ET) return;
    const int str = g_str;
    int d = (e < EE) ? ei[((size_t)EE + e) * str] : e - EE;
    atomicAdd(&g_deg[d], 1);
}

__global__ void scan1_kernel() {
    __shared__ int sh[256];
    int tid = threadIdx.x;
    int i = blockIdx.x * 256 + tid;
    int v = (i < NN) ? g_deg[i] : 0;
    sh[tid] = v;
    __syncthreads();
    #pragma unroll
    for (int ofs = 1; ofs < 256; ofs <<= 1) {
        int t = 0;
        if (tid >= ofs) t = sh[tid - ofs];
        __syncthreads();
        if (tid >= ofs) sh[tid] += t;
        __syncthreads();
    }
    if (i < NN) g_off[i] = sh[tid] - v;
    if (tid == 255) g_bsum[blockIdx.x] = sh[255];
}

__global__ void scan2_kernel() {
    __shared__ int sh[256];
    int tid = threadIdx.x;
    int v = (tid < NB) ? g_bsum[tid] : 0;
    sh[tid] = v;
    __syncthreads();
    #pragma unroll
    for (int ofs = 1; ofs < 256; ofs <<= 1) {
        int t = 0;
        if (tid >= ofs) t = sh[tid - ofs];
        __syncthreads();
        if (tid >= ofs) sh[tid] += t;
        __syncthreads();
    }
    if (tid < NB) g_bbase[tid] = sh[tid] - v;
    if (tid == NB - 1) g_off[NN] = sh[tid];
}

__global__ void scan3_kernel() {
    int i = blockIdx.x * 256 + threadIdx.x;
    if (i >= NN) return;
    int o = g_off[i] + g_bbase[blockIdx.x];
    g_off[i] = o;
    g_cur[i] = o;
}

__global__ void scatter_kernel(const int* __restrict__ ei) {
    int e = blockIdx.x * blockDim.x + threadIdx.x;
    if (e >= ET) return;
    const int str = g_str;
    int s, d;
    if (e < EE) { s = ei[(size_t)e * str]; d = ei[((size_t)EE + e) * str]; }
    else        { s = d = e - EE; }
    int pos = atomicAdd(&g_cur[d], 1);
    g_csrc[pos] = s;
    g_cdst[pos] = d;
}

// ---------------- mma / ldmatrix helpers ----------------
__device__ __forceinline__ void mma_bf16(float* c, const uint32_t* a, const uint32_t* b) {
    asm volatile(
        "mma.sync.aligned.m16n8k16.row.col.f32.bf16.bf16.f32 "
        "{%0,%1,%2,%3}, {%4,%5,%6,%7}, {%8,%9}, {%0,%1,%2,%3};"
        : "+f"(c[0]), "+f"(c[1]), "+f"(c[2]), "+f"(c[3])
        : "r"(a[0]), "r"(a[1]), "r"(a[2]), "r"(a[3]), "r"(b[0]), "r"(b[1]));
}
__device__ __forceinline__ void ldsm_x4(uint32_t* r, uint32_t addr) {
    asm volatile("ldmatrix.sync.aligned.m8n8.x4.shared.b16 {%0,%1,%2,%3}, [%4];"
        : "=r"(r[0]), "=r"(r[1]), "=r"(r[2]), "=r"(r[3]) : "r"(addr));
}

// ---------------- tensor-core GEMM (double-bf16, 3-pass, ldmatrix) ----------
#define SST 24
__global__ __launch_bounds__(256) void gemm_tc(const __nv_bfloat16* __restrict__ Ah,
                                               const __nv_bfloat16* __restrict__ Al,
                                               __nv_bfloat16* __restrict__ HB,
                                               const float* __restrict__ a_s,
                                               const float* __restrict__ a_d,
                                               float* __restrict__ asrc,
                                               float* __restrict__ adst, int M) {
    __shared__ __align__(16) __nv_bfloat16 As_hi[2][128][SST], As_lo[2][128][SST];
    __shared__ __align__(16) __nv_bfloat16 Bs_hi[2][128][SST], Bs_lo[2][128][SST];

    const int tid = threadIdx.x;
    const int wid = tid >> 5, lane = tid & 31;
    const int wm = (wid & 3) * 32;
    const int wn = (wid >> 2) * 64;
    const int row0 = blockIdx.x * 128;
    const int col0 = blockIdx.y * 128;
    const int r = lane >> 2;
    const int c = lane & 3;

    const int srow  = tid >> 1;
    const int shalf = (tid & 1) * 8;
    const bool arow_ok = (row0 + srow < M);

    const uint32_t bAhi = (uint32_t)__cvta_generic_to_shared(&As_hi[0][0][0]);
    const uint32_t bAlo = (uint32_t)__cvta_generic_to_shared(&As_lo[0][0][0]);
    const uint32_t bBhi = (uint32_t)__cvta_generic_to_shared(&Bs_hi[0][0][0]);
    const uint32_t bBlo = (uint32_t)__cvta_generic_to_shared(&Bs_lo[0][0][0]);
    const uint32_t BUFB = 128u * SST * 2u;
    const uint32_t aoff = (uint32_t)(((wm + (lane & 15)) * SST + (lane >> 4) * 8) * 2);
    const uint32_t boff = (uint32_t)(((wn + (lane & 7) + ((lane >> 4) & 1) * 8) * SST) * 2
                                     + ((lane >> 3) & 1) * 16);

    float acc[2][8][4];
    #pragma unroll
    for (int mt = 0; mt < 2; mt++)
        #pragma unroll
        for (int nt = 0; nt < 8; nt++)
            #pragma unroll
            for (int i = 0; i < 4; i++) acc[mt][nt][i] = 0.f;

    uint4 va = make_uint4(0u, 0u, 0u, 0u), vla = va, vbh, vbl;
    if (arow_ok) {
        va  = *(const uint4*)(Ah + (size_t)(row0 + srow) * HC + shalf);
        vla = *(const uint4*)(Al + (size_t)(row0 + srow) * HC + shalf);
    }
    vbh = *(const uint4*)(g_wh + (size_t)(col0 + srow) * HC + shalf);
    vbl = *(const uint4*)(g_wl + (size_t)(col0 + srow) * HC + shalf);
    *(uint4*)&As_hi[0][srow][shalf] = va;
    *(uint4*)&As_lo[0][srow][shalf] = vla;
    *(uint4*)&Bs_hi[0][srow][shalf] = vbh;
    *(uint4*)&Bs_lo[0][srow][shalf] = vbl;
    __syncthreads();

    int buf = 0;
    for (int k0 = 0; k0 < HC; k0 += 16) {
        const bool more = (k0 + 16 < HC);
        if (more) {
            va = make_uint4(0u, 0u, 0u, 0u); vla = va;
            if (arow_ok) {
                va  = *(const uint4*)(Ah + (size_t)(row0 + srow) * HC + k0 + 16 + shalf);
                vla = *(const uint4*)(Al + (size_t)(row0 + srow) * HC + k0 + 16 + shalf);
            }
            vbh = *(const uint4*)(g_wh + (size_t)(col0 + srow) * HC + k0 + 16 + shalf);
            vbl = *(const uint4*)(g_wl + (size_t)(col0 + srow) * HC + k0 + 16 + shalf);
        }

        const uint32_t bofs = (uint32_t)buf * BUFB;
        uint32_t ah0[4], ah1[4], al0[4], al1[4];
        ldsm_x4(ah0, bAhi + bofs + aoff);
        ldsm_x4(ah1, bAhi + bofs + aoff + 16u * SST * 2u);
        ldsm_x4(al0, bAlo + bofs + aoff);
        ldsm_x4(al1, bAlo + bofs + aoff + 16u * SST * 2u);

        #pragma unroll
        for (int p = 0; p < 4; p++) {
            uint32_t bh[4], bl[4];
            ldsm_x4(bh, bBhi + bofs + boff + (uint32_t)p * 16u * SST * 2u);
            ldsm_x4(bl, bBlo + bofs + boff + (uint32_t)p * 16u * SST * 2u);
            mma_bf16(acc[0][2 * p],     ah0, bh);
            mma_bf16(acc[0][2 * p],     al0, bh);
            mma_bf16(acc[0][2 * p],     ah0, bl);
            mma_bf16(acc[1][2 * p],     ah1, bh);
            mma_bf16(acc[1][2 * p],     al1, bh);
            mma_bf16(acc[1][2 * p],     ah1, bl);
            mma_bf16(acc[0][2 * p + 1], ah0, bh + 2);
            mma_bf16(acc[0][2 * p + 1], al0, bh + 2);
            mma_bf16(acc[0][2 * p + 1], ah0, bl + 2);
            mma_bf16(acc[1][2 * p + 1], ah1, bh + 2);
            mma_bf16(acc[1][2 * p + 1], al1, bh + 2);
            mma_bf16(acc[1][2 * p + 1], ah1, bl + 2);
        }

        if (more) {
            *(uint4*)&As_hi[buf ^ 1][srow][shalf] = va;
            *(uint4*)&As_lo[buf ^ 1][srow][shalf] = vla;
            *(uint4*)&Bs_hi[buf ^ 1][srow][shalf] = vbh;
            *(uint4*)&Bs_lo[buf ^ 1][srow][shalf] = vbl;
            __syncthreads();
        }
        buf ^= 1;
    }

    // ---- epilogue ----
    const int hidx = (col0 + wn) >> 6;
    float ws[16], wd[16];
    #pragma unroll
    for (int nt = 0; nt < 8; nt++)
        #pragma unroll
        for (int k = 0; k < 2; k++) {
            int ccol = col0 + wn + nt * 8 + 2 * c + k;
            ws[nt * 2 + k] = a_s[ccol];
            wd[nt * 2 + k] = a_d[ccol];
        }

    #pragma unroll
    for (int mt = 0; mt < 2; mt++) {
        float ps0 = 0.f, pd0 = 0.f, ps1 = 0.f, pd1 = 0.f;
        #pragma unroll
        for (int nt = 0; nt < 8; nt++) {
            ps0 += acc[mt][nt][0] * ws[2 * nt] + acc[mt][nt][1] * ws[2 * nt + 1];
            pd0 += acc[mt][nt][0] * wd[2 * nt] + acc[mt][nt][1] * wd[2 * nt + 1];
            ps1 += acc[mt][nt][2] * ws[2 * nt] + acc[mt][nt][3] * ws[2 * nt + 1];
            pd1 += acc[mt][nt][2] * wd[2 * nt] + acc[mt][nt][3] * wd[2 * nt + 1];
        }
        ps0 += __shfl_xor_sync(0xffffffffu, ps0, 1); ps0 += __shfl_xor_sync(0xffffffffu, ps0, 2);
        pd0 += __shfl_xor_sync(0xffffffffu, pd0, 1); pd0 += __shfl_xor_sync(0xffffffffu, pd0, 2);
        ps1 += __shfl_xor_sync(0xffffffffu, ps1, 1); ps1 += __shfl_xor_sync(0xffffffffu, ps1, 2);
        pd1 += __shfl_xor_sync(0xffffffffu, pd1, 1); pd1 += __shfl_xor_sync(0xffffffffu, pd1, 2);
        int rr = row0 + wm + mt * 16 + r;
        if (c == 0) {
            if (rr < M)     { asrc[rr * HH + hidx] = ps0; adst[rr * HH + hidx] = pd0; }
            if (rr + 8 < M) { asrc[(rr + 8) * HH + hidx] = ps1; adst[(rr + 8) * HH + hidx] = pd1; }
        }
        #pragma unroll
        for (int nt = 0; nt < 8; nt++) {
            int cc = col0 + wn + nt * 8 + 2 * c;
            if (rr < M)
                *(__nv_bfloat162*)(HB + (size_t)rr * HC + cc) =
                    __floats2bfloat162_rn(acc[mt][nt][0], acc[mt][nt][1]);
            if (rr + 8 < M)
                *(__nv_bfloat162*)(HB + (size_t)(rr + 8) * HC + cc) =
                    __floats2bfloat162_rn(acc[mt][nt][2], acc[mt][nt][3]);
        }
    }
}

// ---------------- edge probabilities ----------------
__global__ void edge_p(const float* __restrict__ asrc, const float* __restrict__ adst) {
    size_t t = (size_t)blockIdx.x * blockDim.x + threadIdx.x;
    if (t >= (size_t)ET * HH) return;
    int e = (int)(t >> 2), h = (int)(t & 3);
    int s = g_csrc[e], d = g_cdst[e];
    float v = asrc[s * HH + h] + adst[d * HH + h];
    v = (v > 0.f) ? v : v * NEG;
    g_p[t] = __expf(v);
}

// ---------------- fused GAT aggregation (4-edge unroll) ---------------------
__device__ __forceinline__ void agg_one(float* acc, float& den, float p, const uint4& u) {
    den += p;
    float2 a0 = __bfloat1622float2(*(__nv_bfloat162*)&u.x);
    float2 a1 = __bfloat1622float2(*(__nv_bfloat162*)&u.y);
    float2 a2 = __bfloat1622float2(*(__nv_bfloat162*)&u.z);
    float2 a3 = __bfloat1622float2(*(__nv_bfloat162*)&u.w);
    acc[0] = fmaf(p, a0.x, acc[0]); acc[1] = fmaf(p, a0.y, acc[1]);
    acc[2] = fmaf(p, a1.x, acc[2]); acc[3] = fmaf(p, a1.y, acc[3]);
    acc[4] = fmaf(p, a2.x, acc[4]); acc[5] = fmaf(p, a2.y, acc[5]);
    acc[6] = fmaf(p, a3.x, acc[6]); acc[7] = fmaf(p, a3.y, acc[7]);
}

__global__ __launch_bounds__(256) void gat_agg(const __nv_bfloat16* __restrict__ hwb,
                                               const float* __restrict__ bias,
                                               __nv_bfloat16* __restrict__ oh,
                                               __nv_bfloat16* __restrict__ ol,
                                               int relu) {
    int w = (blockIdx.x * blockDim.x + threadIdx.x) >> 5;
    int lane = threadIdx.x & 31;
    if (w >= NN) return;
    const int h  = lane >> 3;
    const int c0 = lane * 8;
    const int beg = g_off[w], end = g_off[w + 1];

    float acc[8];
    #pragma unroll
    for (int i = 0; i < 8; i++) acc[i] = 0.f;
    float den = 0.f;

    int j = beg;
    for (; j + 3 < end; j += 4) {
        int s0 = g_csrc[j], s1 = g_csrc[j + 1], s2 = g_csrc[j + 2], s3 = g_csrc[j + 3];
        float p0 = g_p[(size_t)j * HH + h];
        float p1 = g_p[(size_t)(j + 1) * HH + h];
        float p2 = g_p[(size_t)(j + 2) * HH + h];
        float p3 = g_p[(size_t)(j + 3) * HH + h];
        uint4 u0 = *(const uint4*)(hwb + (size_t)s0 * HC + c0);
        uint4 u1 = *(const uint4*)(hwb + (size_t)s1 * HC + c0);
        uint4 u2 = *(const uint4*)(hwb + (size_t)s2 * HC + c0);
        uint4 u3 = *(const uint4*)(hwb + (size_t)s3 * HC + c0);
        agg_one(acc, den, p0, u0);
        agg_one(acc, den, p1, u1);
        agg_one(acc, den, p2, u2);
        agg_one(acc, den, p3, u3);
    }
    for (; j < end; j++) {
        int s0 = g_csrc[j];
        float p0 = g_p[(size_t)j * HH + h];
        uint4 u0 = *(const uint4*)(hwb + (size_t)s0 * HC + c0);
        agg_one(acc, den, p0, u0);
    }

    float inv = 1.f / den;
    float o[8];
    float4 bb0 = *(const float4*)(bias + c0);
    float4 bb1 = *(const float4*)(bias + c0 + 4);
    o[0] = acc[0] * inv + bb0.x; o[1] = acc[1] * inv + bb0.y;
    o[2] = acc[2] * inv + bb0.z; o[3] = acc[3] * inv + bb0.w;
    o[4] = acc[4] * inv + bb1.x; o[5] = acc[5] * inv + bb1.y;
    o[6] = acc[6] * inv + bb1.z; o[7] = acc[7] * inv + bb1.w;
    if (relu) {
        #pragma unroll
        for (int i = 0; i < 8; i++) o[i] = fmaxf(o[i], 0.f);
    }
    __nv_bfloat162 hi[4], lo[4];
    #pragma unroll
    for (int i = 0; i < 4; i++) {
        hi[i] = __floats2bfloat162_rn(o[2 * i], o[2 * i + 1]);
        float2 back = __bfloat1622float2(hi[i]);
        lo[i] = __floats2bfloat162_rn(o[2 * i] - back.x, o[2 * i + 1] - back.y);
    }
    uint4 uh, ul;
    uh.x = *(uint32_t*)&hi[0]; uh.y = *(uint32_t*)&hi[1];
    uh.z = *(uint32_t*)&hi[2]; uh.w = *(uint32_t*)&hi[3];
    ul.x = *(uint32_t*)&lo[0]; ul.y = *(uint32_t*)&lo[1];
    ul.z = *(uint32_t*)&lo[2]; ul.w = *(uint32_t*)&lo[3];
    *(uint4*)(oh + (size_t)w * HC + c0) = uh;
    *(uint4*)(ol + (size_t)w * HC + c0) = ul;
}

// ---------------- graph boundaries ----------------
__global__ void bounds_kernel(const int* __restrict__ batch) {
    int g = blockIdx.x * blockDim.x + threadIdx.x;
    if (g > GG) return;
    const int str = g_str;
    int lo = 0, hi = NN;
    while (lo < hi) {
        int mid = (lo + hi) >> 1;
        if (batch[(size_t)mid * str] < g) lo = mid + 1; else hi = mid;
    }
    g_gstart[g] = lo;
}

// ---------------- mean pool ----------------
#define PSL 8
__global__ void pool_kernel() {
    int g = blockIdx.x, sl = blockIdx.y, c = threadIdx.x;
    int s = g_gstart[g], e = g_gstart[g + 1];
    float acc = 0.f;
    for (int n = s + sl; n < e; n += PSL) {
        size_t idx = (size_t)n * HC + c;
        acc += __bfloat162float(g_ah[idx]) + __bfloat162float(g_al[idx]);
    }
    atomicAdd(&g_pool[g * HC + c], acc);
}

__global__ void pool_div() {
    int t = blockIdx.x * blockDim.x + threadIdx.x;
    if (t >= GG * HC) return;
    int g = t >> 8;
    float cnt = (float)max(g_gstart[g + 1] - g_gstart[g], 1);
    g_pool[t] /= cnt;
}

// ---------------- MLP ----------------
__global__ void mlp1_kernel(const float* __restrict__ Wm1, const float* __restrict__ bm1) {
    __shared__ float row[HC];
    int g = blockIdx.x, t = threadIdx.x;
    for (int i = t; i < HC; i += blockDim.x) row[i] = g_pool[g * HC + i];
    __syncthreads();
    #pragma unroll
    for (int j = 0; j < NHID / 256; j++) {
        int o = t + j * 256;
        float acc = bm1[o];
        for (int k = 0; k < HC; k++) acc = fmaf(row[k], Wm1[(size_t)k * NHID + o], acc);
        g_hid[g * NHID + o] = fmaxf(acc, 0.f);
    }
}

__global__ void mlp2_kernel(const float* __restrict__ Wm2, const float* __restrict__ bm2,
                            float* __restrict__ out) {
    __shared__ float row[NHID];
    int g = blockIdx.x, t = threadIdx.x;
    for (int i = t; i < NHID; i += blockDim.x) row[i] = g_hid[g * NHID + i];
    __syncthreads();
    #pragma unroll
    for (int j = 0; j < NOUT / 256; j++) {
        int o = t + j * 256;
        float acc = bm2[o];
        for (int k = 0; k < NHID; k++) acc = fmaf(row[k], Wm2[(size_t)k * NOUT + o], acc);
        out[(size_t)g * NOUT + o] = acc;
    }
}

// ---------------- host orchestration ----------------
extern "C" void kernel_launch(void* const* d_in, const int* in_sizes, int n_in,
                              void* d_out, int out_size) {
    const float* x   = (const float*)d_in[0];
    const int*   ei  = (const int*)d_in[1];
    const int*   bat = (const int*)d_in[2];
    const float* W1  = (const float*)d_in[3];
    const float* as1 = (const float*)d_in[4];
    const float* ad1 = (const float*)d_in[5];
    const float* b1  = (const float*)d_in[6];
    const float* W2  = (const float*)d_in[7];
    const float* as2 = (const float*)d_in[8];
    const float* ad2 = (const float*)d_in[9];
    const float* b2  = (const float*)d_in[10];
    const float* W3  = (const float*)d_in[11];
    const float* as3 = (const float*)d_in[12];
    const float* ad3 = (const float*)d_in[13];
    const float* b3  = (const float*)d_in[14];
    const float* Wm1 = (const float*)d_in[15];
    const float* bm1 = (const float*)d_in[16];
    const float* Wm2 = (const float*)d_in[17];
    const float* bm2 = (const float*)d_in[18];
    float* out = (float*)d_out;

    float *asrc, *adst, *poolp;
    __nv_bfloat16 *ah, *al, *hwb;
    cudaGetSymbolAddress((void**)&ah,    g_ah);
    cudaGetSymbolAddress((void**)&al,    g_al);
    cudaGetSymbolAddress((void**)&hwb,   g_hwb);
    cudaGetSymbolAddress((void**)&asrc,  g_asrc);
    cudaGetSymbolAddress((void**)&adst,  g_adst);
    cudaGetSymbolAddress((void**)&poolp, g_pool);

    dim3 ggrid((NN + 127) / 128, HC / 128);

    detect_kernel<<<1, 32>>>(ei);
    conv_x<<<((size_t)NN * HC + 255) / 256, 256>>>(x);
    conv_w<<<(HC * HC + 255) / 256, 256>>>(W1);
    gemm_tc<<<ggrid, 256>>>(ah, al, hwb, as1, ad1, asrc, adst, NN);
    hist_kernel<<<(ET + 255) / 256, 256>>>(ei);
    scan1_kernel<<<NB, 256>>>();
    scan2_kernel<<<1, 256>>>();
    scan3_kernel<<<NB, 256>>>();
    scatter_kernel<<<(ET + 255) / 256, 256>>>(ei);
    edge_p<<<((size_t)ET * HH + 255) / 256, 256>>>(asrc, adst);
    gat_agg<<<(NN * 32 + 255) / 256, 256>>>(hwb, b1, ah, al, 1);
    conv_w<<<(HC * HC + 255) / 256, 256>>>(W2);
    gemm_tc<<<ggrid, 256>>>(ah, al, hwb, as2, ad2, asrc, adst, NN);
    edge_p<<<((size_t)ET * HH + 255) / 256, 256>>>(asrc, adst);
    gat_agg<<<(NN * 32 + 255) / 256, 256>>>(hwb, b2, ah, al, 1);
    conv_w<<<(HC * HC + 255) / 256, 256>>>(W3);
    gemm_tc<<<ggrid, 256>>>(ah, al, hwb, as3, ad3, asrc, adst, NN);
    edge_p<<<((size_t)ET * HH + 255) / 256, 256>>>(asrc, adst);
    gat_agg<<<(NN * 32 + 255) / 256, 256>>>(hwb, b3, ah, al, 0);
    bounds_kernel<<<1, 128>>>(bat);
    cudaMemsetAsync(poolp, 0, GG * HC * sizeof(float), 0);
    pool_kernel<<<dim3(GG, PSL), HC>>>();
    pool_div<<<(GG * HC + 255) / 256, 256>>>();
    mlp1_kernel<<<GG, 256>>>(Wm1, bm1);
    mlp2_kernel<<<GG, 256>>>(Wm2, bm2, out);
}

// round 16
// speedup vs baseline: 2.2606x; 1.0960x over previous
#include <cuda_runtime.h>
#include <cuda_bf16.h>
#include <math.h>
#include <stdint.h>

// ---------------- problem constants ----------------
#define NN     40000
#define EE     640000
#define ET     (EE + NN)
#define GG     64
#define HH     4
#define CC     64
#define HC     256
#define NHID   1024
#define NOUT   768
#define NEG    0.2f
#define NB     ((NN + 255) / 256)

// ---------------- device scratch ----------------
__device__ __align__(16) __nv_bfloat16 g_ah [NN * HC];
__device__ __align__(16) __nv_bfloat16 g_al [NN * HC];
__device__ __align__(16) __nv_bfloat16 g_wh [HC * HC];
__device__ __align__(16) __nv_bfloat16 g_wl [HC * HC];
__device__ __align__(16) __nv_bfloat16 g_hwb[NN * HC];
__device__ __align__(16) float g_asrc[NN * HH];
__device__ __align__(16) float g_adst[NN * HH];
__device__ __align__(16) float g_p   [(size_t)ET * HH];
__device__ __align__(16) float g_pool[GG * HC];
__device__ __align__(16) float g_hid [GG * NHID];
__device__ int g_deg [NN];
__device__ int g_off [NN + 1];
__device__ int g_cur [NN];
__device__ int g_bsum[NB];
__device__ int g_bbase[NB];
__device__ int g_csrc[ET];
__device__ int g_cdst[ET];
__device__ int g_gstart[GG + 1];
__device__ int g_str;

// ---------------- dtype detection ----------------
__global__ void detect_kernel(const int* __restrict__ ei) {
    if (threadIdx.x == 0 && blockIdx.x == 0) {
        int o = 0;
        #pragma unroll
        for (int k = 0; k < 16; k++) o |= ei[2 * k + 1];
        g_str = o ? 1 : 2;
    }
}

// ---------------- input split (also zeros g_deg) ----------------
__global__ void conv_x(const float* __restrict__ x) {
    size_t t = (size_t)blockIdx.x * blockDim.x + threadIdx.x;
    if (t < NN) g_deg[t] = 0;
    if (t >= (size_t)NN * HC) return;
    float v = x[t];
    __nv_bfloat16 h = __float2bfloat16(v);
    g_ah[t] = h;
    g_al[t] = __float2bfloat16(v - __bfloat162float(h));
}

// ---------------- weight split + transpose ----------------
__global__ void conv_w(const float* __restrict__ W) {
    int t = blockIdx.x * blockDim.x + threadIdx.x;
    if (t >= HC * HC) return;
    int n = t >> 8, k = t & 255;
    float v = W[k * HC + n];
    __nv_bfloat16 h = __float2bfloat16(v);
    g_wh[t] = h;
    g_wl[t] = __float2bfloat16(v - __bfloat162float(h));
}

// ---------------- CSR build ----------------
__global__ void hist_kernel(const int* __restrict__ ei) {
    int e = blockIdx.x * blockDim.x + threadIdx.x;
    if (e >= ET) return;
    const int str = g_str;
    int d = (e < EE) ? ei[((size_t)EE + e) * str] : e - EE;
    atomicAdd(&g_deg[d], 1);
}

__global__ void scan1_kernel() {
    __shared__ int sh[256];
    int tid = threadIdx.x;
    int i = blockIdx.x * 256 + tid;
    int v = (i < NN) ? g_deg[i] : 0;
    sh[tid] = v;
    __syncthreads();
    #pragma unroll
    for (int ofs = 1; ofs < 256; ofs <<= 1) {
        int t = 0;
        if (tid >= ofs) t = sh[tid - ofs];
        __syncthreads();
        if (tid >= ofs) sh[tid] += t;
        __syncthreads();
    }
    if (i < NN) g_off[i] = sh[tid] - v;
    if (tid == 255) g_bsum[blockIdx.x] = sh[255];
}

__global__ void scan2_kernel() {
    __shared__ int sh[256];
    int tid = threadIdx.x;
    int v = (tid < NB) ? g_bsum[tid] : 0;
    sh[tid] = v;
    __syncthreads();
    #pragma unroll
    for (int ofs = 1; ofs < 256; ofs <<= 1) {
        int t = 0;
        if (tid >= ofs) t = sh[tid - ofs];
        __syncthreads();
        if (tid >= ofs) sh[tid] += t;
        __syncthreads();
    }
    if (tid < NB) g_bbase[tid] = sh[tid] - v;
    if (tid == NB - 1) g_off[NN] = sh[tid];
}

__global__ void scan3_kernel() {
    int i = blockIdx.x * 256 + threadIdx.x;
    if (i >= NN) return;
    int o = g_off[i] + g_bbase[blockIdx.x];
    g_off[i] = o;
    g_cur[i] = o;
}

__global__ void scatter_kernel(const int* __restrict__ ei) {
    int e = blockIdx.x * blockDim.x + threadIdx.x;
    if (e >= ET) return;
    const int str = g_str;
    int s, d;
    if (e < EE) { s = ei[(size_t)e * str]; d = ei[((size_t)EE + e) * str]; }
    else        { s = d = e - EE; }
    int pos = atomicAdd(&g_cur[d], 1);
    g_csrc[pos] = s;
    g_cdst[pos] = d;
}

// ---------------- mma / ldmatrix / cp.async helpers ----------------
__device__ __forceinline__ void mma_bf16(float* c, const uint32_t* a, const uint32_t* b) {
    asm volatile(
        "mma.sync.aligned.m16n8k16.row.col.f32.bf16.bf16.f32 "
        "{%0,%1,%2,%3}, {%4,%5,%6,%7}, {%8,%9}, {%0,%1,%2,%3};"
        : "+f"(c[0]), "+f"(c[1]), "+f"(c[2]), "+f"(c[3])
        : "r"(a[0]), "r"(a[1]), "r"(a[2]), "r"(a[3]), "r"(b[0]), "r"(b[1]));
}
__device__ __forceinline__ void ldsm_x4(uint32_t* r, uint32_t addr) {
    asm volatile("ldmatrix.sync.aligned.m8n8.x4.shared.b16 {%0,%1,%2,%3}, [%4];"
        : "=r"(r[0]), "=r"(r[1]), "=r"(r[2]), "=r"(r[3]) : "r"(addr));
}
__device__ __forceinline__ void cp16(uint32_t dst, const void* src, int src_bytes) {
    asm volatile("cp.async.cg.shared.global [%0], [%1], 16, %2;"
                 :: "r"(dst), "l"(src), "r"(src_bytes));
}
__device__ __forceinline__ void cp_commit() { asm volatile("cp.async.commit_group;"); }
__device__ __forceinline__ void cp_wait0()  { asm volatile("cp.async.wait_group 0;"); }

// ---------------- tensor-core GEMM (double-bf16, 3-pass, ldmatrix+cp.async) -
#define SST 24
__global__ __launch_bounds__(256, 2) void gemm_tc(const __nv_bfloat16* __restrict__ Ah,
                                                  const __nv_bfloat16* __restrict__ Al,
                                                  __nv_bfloat16* __restrict__ HB,
                                                  const float* __restrict__ a_s,
                                                  const float* __restrict__ a_d,
                                                  float* __restrict__ asrc,
                                                  float* __restrict__ adst, int M) {
    __shared__ __align__(16) __nv_bfloat16 As_hi[2][128][SST], As_lo[2][128][SST];
    __shared__ __align__(16) __nv_bfloat16 Bs_hi[2][128][SST], Bs_lo[2][128][SST];

    const int tid = threadIdx.x;
    const int wid = tid >> 5, lane = tid & 31;
    const int wm = (wid & 3) * 32;
    const int wn = (wid >> 2) * 64;
    const int row0 = blockIdx.x * 128;
    const int col0 = blockIdx.y * 128;
    const int r = lane >> 2;
    const int c = lane & 3;

    const int srow  = tid >> 1;
    const int shalf = (tid & 1) * 8;
    const int asz = (row0 + srow < M) ? 16 : 0;   // OOB A rows -> zero-fill

    const uint32_t bAhi = (uint32_t)__cvta_generic_to_shared(&As_hi[0][0][0]);
    const uint32_t bAlo = (uint32_t)__cvta_generic_to_shared(&As_lo[0][0][0]);
    const uint32_t bBhi = (uint32_t)__cvta_generic_to_shared(&Bs_hi[0][0][0]);
    const uint32_t bBlo = (uint32_t)__cvta_generic_to_shared(&Bs_lo[0][0][0]);
    const uint32_t BUFB = 128u * SST * 2u;
    const uint32_t soff = (uint32_t)((srow * SST + shalf) * 2);   // staging dst offset
    const uint32_t aoff = (uint32_t)(((wm + (lane & 15)) * SST + (lane >> 4) * 8) * 2);
    const uint32_t boff = (uint32_t)(((wn + (lane & 7) + ((lane >> 4) & 1) * 8) * SST) * 2
                                     + ((lane >> 3) & 1) * 16);

    const __nv_bfloat16* pAh = Ah + (size_t)(row0 + srow) * HC + shalf;
    const __nv_bfloat16* pAl = Al + (size_t)(row0 + srow) * HC + shalf;
    const __nv_bfloat16* pBh = g_wh + (size_t)(col0 + srow) * HC + shalf;
    const __nv_bfloat16* pBl = g_wl + (size_t)(col0 + srow) * HC + shalf;

    float acc[2][8][4];
    #pragma unroll
    for (int mt = 0; mt < 2; mt++)
        #pragma unroll
        for (int nt = 0; nt < 8; nt++)
            #pragma unroll
            for (int i = 0; i < 4; i++) acc[mt][nt][i] = 0.f;

    // prologue: async-stage chunk 0 into buffer 0
    cp16(bAhi + soff, pAh, asz);
    cp16(bAlo + soff, pAl, asz);
    cp16(bBhi + soff, pBh, 16);
    cp16(bBlo + soff, pBl, 16);
    cp_commit();

    int buf = 0;
    for (int k0 = 0; k0 < HC; k0 += 16) {
        cp_wait0();
        __syncthreads();          // staged data visible; all warps past previous compute

        const bool more = (k0 + 16 < HC);
        if (more) {
            const uint32_t dofs = (uint32_t)(buf ^ 1) * BUFB + soff;
            cp16(bAhi + dofs, pAh + k0 + 16, asz);
            cp16(bAlo + dofs, pAl + k0 + 16, asz);
            cp16(bBhi + dofs, pBh + k0 + 16, 16);
            cp16(bBlo + dofs, pBl + k0 + 16, 16);
            cp_commit();
        }

        const uint32_t bofs = (uint32_t)buf * BUFB;
        uint32_t ah0[4], ah1[4], al0[4], al1[4];
        ldsm_x4(ah0, bAhi + bofs + aoff);
        ldsm_x4(ah1, bAhi + bofs + aoff + 16u * SST * 2u);
        ldsm_x4(al0, bAlo + bofs + aoff);
        ldsm_x4(al1, bAlo + bofs + aoff + 16u * SST * 2u);

        #pragma unroll
        for (int p = 0; p < 4; p++) {
            uint32_t bh[4], bl[4];
            ldsm_x4(bh, bBhi + bofs + boff + (uint32_t)p * 16u * SST * 2u);
            ldsm_x4(bl, bBlo + bofs + boff + (uint32_t)p * 16u * SST * 2u);
            mma_bf16(acc[0][2 * p],     ah0, bh);
            mma_bf16(acc[0][2 * p],     al0, bh);
            mma_bf16(acc[0][2 * p],     ah0, bl);
            mma_bf16(acc[1][2 * p],     ah1, bh);
            mma_bf16(acc[1][2 * p],     al1, bh);
            mma_bf16(acc[1][2 * p],     ah1, bl);
            mma_bf16(acc[0][2 * p + 1], ah0, bh + 2);
            mma_bf16(acc[0][2 * p + 1], al0, bh + 2);
            mma_bf16(acc[0][2 * p + 1], ah0, bl + 2);
            mma_bf16(acc[1][2 * p + 1], ah1, bh + 2);
            mma_bf16(acc[1][2 * p + 1], al1, bh + 2);
            mma_bf16(acc[1][2 * p + 1], ah1, bl + 2);
        }
        buf ^= 1;
    }

    // ---- epilogue ----
    const int hidx = (col0 + wn) >> 6;
    float ws[16], wd[16];
    #pragma unroll
    for (int nt = 0; nt < 8; nt++)
        #pragma unroll
        for (int k = 0; k < 2; k++) {
            int ccol = col0 + wn + nt * 8 + 2 * c + k;
            ws[nt * 2 + k] = a_s[ccol];
            wd[nt * 2 + k] = a_d[ccol];
        }

    #pragma unroll
    for (int mt = 0; mt < 2; mt++) {
        float ps0 = 0.f, pd0 = 0.f, ps1 = 0.f, pd1 = 0.f;
        #pragma unroll
        for (int nt = 0; nt < 8; nt++) {
            ps0 += acc[mt][nt][0] * ws[2 * nt] + acc[mt][nt][1] * ws[2 * nt + 1];
            pd0 += acc[mt][nt][0] * wd[2 * nt] + acc[mt][nt][1] * wd[2 * nt + 1];
            ps1 += acc[mt][nt][2] * ws[2 * nt] + acc[mt][nt][3] * ws[2 * nt + 1];
            pd1 += acc[mt][nt][2] * wd[2 * nt] + acc[mt][nt][3] * wd[2 * nt + 1];
        }
        ps0 += __shfl_xor_sync(0xffffffffu, ps0, 1); ps0 += __shfl_xor_sync(0xffffffffu, ps0, 2);
        pd0 += __shfl_xor_sync(0xffffffffu, pd0, 1); pd0 += __shfl_xor_sync(0xffffffffu, pd0, 2);
        ps1 += __shfl_xor_sync(0xffffffffu, ps1, 1); ps1 += __shfl_xor_sync(0xffffffffu, ps1, 2);
        pd1 += __shfl_xor_sync(0xffffffffu, pd1, 1); pd1 += __shfl_xor_sync(0xffffffffu, pd1, 2);
        int rr = row0 + wm + mt * 16 + r;
        if (c == 0) {
            if (rr < M)     { asrc[rr * HH + hidx] = ps0; adst[rr * HH + hidx] = pd0; }
            if (rr + 8 < M) { asrc[(rr + 8) * HH + hidx] = ps1; adst[(rr + 8) * HH + hidx] = pd1; }
        }
        #pragma unroll
        for (int nt = 0; nt < 8; nt++) {
            int cc = col0 + wn + nt * 8 + 2 * c;
            if (rr < M)
                *(__nv_bfloat162*)(HB + (size_t)rr * HC + cc) =
                    __floats2bfloat162_rn(acc[mt][nt][0], acc[mt][nt][1]);
            if (rr + 8 < M)
                *(__nv_bfloat162*)(HB + (size_t)(rr + 8) * HC + cc) =
                    __floats2bfloat162_rn(acc[mt][nt][2], acc[mt][nt][3]);
        }
    }
}

// ---------------- edge probabilities ----------------
__global__ void edge_p(const float* __restrict__ asrc, const float* __restrict__ adst) {
    size_t t = (size_t)blockIdx.x * blockDim.x + threadIdx.x;
    if (t >= (size_t)ET * HH) return;
    int e = (int)(t >> 2), h = (int)(t & 3);
    int s = g_csrc[e], d = g_cdst[e];
    float v = asrc[s * HH + h] + adst[d * HH + h];
    v = (v > 0.f) ? v : v * NEG;
    g_p[t] = __expf(v);
}

// ---------------- fused GAT aggregation (4-edge unroll) ---------------------
__device__ __forceinline__ void agg_one(float* acc, float& den, float p, const uint4& u) {
    den += p;
    float2 a0 = __bfloat1622float2(*(__nv_bfloat162*)&u.x);
    float2 a1 = __bfloat1622float2(*(__nv_bfloat162*)&u.y);
    float2 a2 = __bfloat1622float2(*(__nv_bfloat162*)&u.z);
    float2 a3 = __bfloat1622float2(*(__nv_bfloat162*)&u.w);
    acc[0] = fmaf(p, a0.x, acc[0]); acc[1] = fmaf(p, a0.y, acc[1]);
    acc[2] = fmaf(p, a1.x, acc[2]); acc[3] = fmaf(p, a1.y, acc[3]);
    acc[4] = fmaf(p, a2.x, acc[4]); acc[5] = fmaf(p, a2.y, acc[5]);
    acc[6] = fmaf(p, a3.x, acc[6]); acc[7] = fmaf(p, a3.y, acc[7]);
}

__global__ __launch_bounds__(256) void gat_agg(const __nv_bfloat16* __restrict__ hwb,
                                               const float* __restrict__ bias,
                                               __nv_bfloat16* __restrict__ oh,
                                               __nv_bfloat16* __restrict__ ol,
                                               int relu) {
    int w = (blockIdx.x * blockDim.x + threadIdx.x) >> 5;
    int lane = threadIdx.x & 31;
    if (w >= NN) return;
    const int h  = lane >> 3;
    const int c0 = lane * 8;
    const int beg = g_off[w], end = g_off[w + 1];

    float acc[8];
    #pragma unroll
    for (int i = 0; i < 8; i++) acc[i] = 0.f;
    float den = 0.f;

    int j = beg;
    for (; j + 3 < end; j += 4) {
        int s0 = g_csrc[j], s1 = g_csrc[j + 1], s2 = g_csrc[j + 2], s3 = g_csrc[j + 3];
        float p0 = g_p[(size_t)j * HH + h];
        float p1 = g_p[(size_t)(j + 1) * HH + h];
        float p2 = g_p[(size_t)(j + 2) * HH + h];
        float p3 = g_p[(size_t)(j + 3) * HH + h];
        uint4 u0 = *(const uint4*)(hwb + (size_t)s0 * HC + c0);
        uint4 u1 = *(const uint4*)(hwb + (size_t)s1 * HC + c0);
        uint4 u2 = *(const uint4*)(hwb + (size_t)s2 * HC + c0);
        uint4 u3 = *(const uint4*)(hwb + (size_t)s3 * HC + c0);
        agg_one(acc, den, p0, u0);
        agg_one(acc, den, p1, u1);
        agg_one(acc, den, p2, u2);
        agg_one(acc, den, p3, u3);
    }
    for (; j < end; j++) {
        int s0 = g_csrc[j];
        float p0 = g_p[(size_t)j * HH + h];
        uint4 u0 = *(const uint4*)(hwb + (size_t)s0 * HC + c0);
        agg_one(acc, den, p0, u0);
    }

    float inv = 1.f / den;
    float o[8];
    float4 bb0 = *(const float4*)(bias + c0);
    float4 bb1 = *(const float4*)(bias + c0 + 4);
    o[0] = acc[0] * inv + bb0.x; o[1] = acc[1] * inv + bb0.y;
    o[2] = acc[2] * inv + bb0.z; o[3] = acc[3] * inv + bb0.w;
    o[4] = acc[4] * inv + bb1.x; o[5] = acc[5] * inv + bb1.y;
    o[6] = acc[6] * inv + bb1.z; o[7] = acc[7] * inv + bb1.w;
    if (relu) {
        #pragma unroll
        for (int i = 0; i < 8; i++) o[i] = fmaxf(o[i], 0.f);
    }
    __nv_bfloat162 hi[4], lo[4];
    #pragma unroll
    for (int i = 0; i < 4; i++) {
        hi[i] = __floats2bfloat162_rn(o[2 * i], o[2 * i + 1]);
        float2 back = __bfloat1622float2(hi[i]);
        lo[i] = __floats2bfloat162_rn(o[2 * i] - back.x, o[2 * i + 1] - back.y);
    }
    uint4 uh, ul;
    uh.x = *(uint32_t*)&hi[0]; uh.y = *(uint32_t*)&hi[1];
    uh.z = *(uint32_t*)&hi[2]; uh.w = *(uint32_t*)&hi[3];
    ul.x = *(uint32_t*)&lo[0]; ul.y = *(uint32_t*)&lo[1];
    ul.z = *(uint32_t*)&lo[2]; ul.w = *(uint32_t*)&lo[3];
    *(uint4*)(oh + (size_t)w * HC + c0) = uh;
    *(uint4*)(ol + (size_t)w * HC + c0) = ul;
}

// ---------------- graph boundaries ----------------
__global__ void bounds_kernel(const int* __restrict__ batch) {
    int g = blockIdx.x * blockDim.x + threadIdx.x;
    if (g > GG) return;
    const int str = g_str;
    int lo = 0, hi = NN;
    while (lo < hi) {
        int mid = (lo + hi) >> 1;
        if (batch[(size_t)mid * str] < g) lo = mid + 1; else hi = mid;
    }
    g_gstart[g] = lo;
}

// ---------------- mean pool ----------------
#define PSL 8
__global__ void pool_kernel() {
    int g = blockIdx.x, sl = blockIdx.y, c = threadIdx.x;
    int s = g_gstart[g], e = g_gstart[g + 1];
    float acc = 0.f;
    for (int n = s + sl; n < e; n += PSL) {
        size_t idx = (size_t)n * HC + c;
        acc += __bfloat162float(g_ah[idx]) + __bfloat162float(g_al[idx]);
    }
    atomicAdd(&g_pool[g * HC + c], acc);
}

__global__ void pool_div() {
    int t = blockIdx.x * blockDim.x + threadIdx.x;
    if (t >= GG * HC) return;
    int g = t >> 8;
    float cnt = (float)max(g_gstart[g + 1] - g_gstart[g], 1);
    g_pool[t] /= cnt;
}

// ---------------- MLP ----------------
__global__ void mlp1_kernel(const float* __restrict__ Wm1, const float* __restrict__ bm1) {
    __shared__ float row[HC];
    int g = blockIdx.x, t = threadIdx.x;
    for (int i = t; i < HC; i += blockDim.x) row[i] = g_pool[g * HC + i];
    __syncthreads();
    #pragma unroll
    for (int j = 0; j < NHID / 256; j++) {
        int o = t + j * 256;
        float acc = bm1[o];
        for (int k = 0; k < HC; k++) acc = fmaf(row[k], Wm1[(size_t)k * NHID + o], acc);
        g_hid[g * NHID + o] = fmaxf(acc, 0.f);
    }
}

__global__ void mlp2_kernel(const float* __restrict__ Wm2, const float* __restrict__ bm2,
                            float* __restrict__ out) {
    __shared__ float row[NHID];
    int g = blockIdx.x, t = threadIdx.x;
    for (int i = t; i < NHID; i += blockDim.x) row[i] = g_hid[g * NHID + i];
    __syncthreads();
    #pragma unroll
    for (int j = 0; j < NOUT / 256; j++) {
        int o = t + j * 256;
        float acc = bm2[o];
        for (int k = 0; k < NHID; k++) acc = fmaf(row[k], Wm2[(size_t)k * NOUT + o], acc);
        out[(size_t)g * NOUT + o] = acc;
    }
}

// ---------------- host orchestration ----------------
extern "C" void kernel_launch(void* const* d_in, const int* in_sizes, int n_in,
                              void* d_out, int out_size) {
    const float* x   = (const float*)d_in[0];
    const int*   ei  = (const int*)d_in[1];
    const int*   bat = (const int*)d_in[2];
    const float* W1  = (const float*)d_in[3];
    const float* as1 = (const float*)d_in[4];
    const float* ad1 = (const float*)d_in[5];
    const float* b1  = (const float*)d_in[6];
    const float* W2  = (const float*)d_in[7];
    const float* as2 = (const float*)d_in[8];
    const float* ad2 = (const float*)d_in[9];
    const float* b2  = (const float*)d_in[10];
    const float* W3  = (const float*)d_in[11];
    const float* as3 = (const float*)d_in[12];
    const float* ad3 = (const float*)d_in[13];
    const float* b3  = (const float*)d_in[14];
    const float* Wm1 = (const float*)d_in[15];
    const float* bm1 = (const float*)d_in[16];
    const float* Wm2 = (const float*)d_in[17];
    const float* bm2 = (const float*)d_in[18];
    float* out = (float*)d_out;

    float *asrc, *adst, *poolp;
    __nv_bfloat16 *ah, *al, *hwb;
    cudaGetSymbolAddress((void**)&ah,    g_ah);
    cudaGetSymbolAddress((void**)&al,    g_al);
    cudaGetSymbolAddress((void**)&hwb,   g_hwb);
    cudaGetSymbolAddress((void**)&asrc,  g_asrc);
    cudaGetSymbolAddress((void**)&adst,  g_adst);
    cudaGetSymbolAddress((void**)&poolp, g_pool);

    dim3 ggrid((NN + 127) / 128, HC / 128);

    detect_kernel<<<1, 32>>>(ei);
    conv_x<<<((size_t)NN * HC + 255) / 256, 256>>>(x);
    conv_w<<<(HC * HC + 255) / 256, 256>>>(W1);
    gemm_tc<<<ggrid, 256>>>(ah, al, hwb, as1, ad1, asrc, adst, NN);
    hist_kernel<<<(ET + 255) / 256, 256>>>(ei);
    scan1_kernel<<<NB, 256>>>();
    scan2_kernel<<<1, 256>>>();
    scan3_kernel<<<NB, 256>>>();
    scatter_kernel<<<(ET + 255) / 256, 256>>>(ei);
    edge_p<<<((size_t)ET * HH + 255) / 256, 256>>>(asrc, adst);
    gat_agg<<<(NN * 32 + 255) / 256, 256>>>(hwb, b1, ah, al, 1);
    conv_w<<<(HC * HC + 255) / 256, 256>>>(W2);
    gemm_tc<<<ggrid, 256>>>(ah, al, hwb, as2, ad2, asrc, adst, NN);
    edge_p<<<((size_t)ET * HH + 255) / 256, 256>>>(asrc, adst);
    gat_agg<<<(NN * 32 + 255) / 256, 256>>>(hwb, b2, ah, al, 1);
    conv_w<<<(HC * HC + 255) / 256, 256>>>(W3);
    gemm_tc<<<ggrid, 256>>>(ah, al, hwb, as3, ad3, asrc, adst, NN);
    edge_p<<<((size_t)ET * HH + 255) / 256, 256>>>(asrc, adst);
    gat_agg<<<(NN * 32 + 255) / 256, 256>>>(hwb, b3, ah, al, 0);
    bounds_kernel<<<1, 128>>>(bat);
    cudaMemsetAsync(poolp, 0, GG * HC * sizeof(float), 0);
    pool_kernel<<<dim3(GG, PSL), HC>>>();
    pool_div<<<(GG * HC + 255) / 256, 256>>>();
    mlp1_kernel<<<GG, 256>>>(Wm1, bm1);
    mlp2_kernel<<<GG, 256>>>(Wm2, bm2, out);
}